// round 2
// baseline (speedup 1.0000x reference)
#include <cuda_runtime.h>
#include <cuda_bf16.h>
#include <math.h>

#define BT 32768
#define NSTREAM 4
#define D 192
#define ND 768
#define MLP 768
#define T_SEQ 1024
#define NB 32
#define NH 3
#define HD 64

// ---------------- scratch (device globals; no allocation allowed) ----------------
__device__ float g_xin[BT * D];
__device__ float g_h[BT * D];
__device__ float g_q[BT * D];
__device__ float g_k[BT * D];
__device__ float g_v[BT * D];
__device__ float g_o[BT * D];
__device__ float g_x2[BT * D];
__device__ float g_g[BT * MLP];
__device__ float g_hpost[BT * NSTREAM];

// =================================================================================
// Kernel 1: gate kernel. One block (768 threads) per token.
// rmsnorm -> 24 projections -> sinkhorn(4x4, 20 iters) -> x_res (to out), x_in, h_post
// =================================================================================
__global__ __launch_bounds__(768) void gate_kernel(
    const float* __restrict__ x, const float* __restrict__ norm_w,
    const float* __restrict__ phi_pre, const float* __restrict__ phi_post,
    const float* __restrict__ phi_res,
    const float* __restrict__ b_pre, const float* __restrict__ b_post,
    const float* __restrict__ b_res,
    const float* __restrict__ a_pre, const float* __restrict__ a_post,
    const float* __restrict__ a_res,
    float* __restrict__ out, float* __restrict__ xin, float* __restrict__ hpost)
{
    int tok = blockIdx.x;
    int tid = threadIdx.x;
    int lane = tid & 31, wid = tid >> 5;

    __shared__ __align__(16) float xs[ND];
    __shared__ __align__(16) float ss[ND];
    __shared__ float red[24];
    __shared__ float tilde[24];
    __shared__ float hres[16];
    __shared__ float hpre[4];
    __shared__ float s_inv;

    float xv = x[(size_t)tok * ND + tid];
    xs[tid] = xv;

    float sq = xv * xv;
    #pragma unroll
    for (int o = 16; o; o >>= 1) sq += __shfl_xor_sync(~0u, sq, o);
    if (lane == 0) red[wid] = sq;
    __syncthreads();
    if (tid == 0) {
        float s = 0.f;
        #pragma unroll
        for (int i = 0; i < 24; i++) s += red[i];
        s_inv = rsqrtf(s / (float)ND + 1e-8f);
    }
    __syncthreads();
    float sv = xv * s_inv * norm_w[tid];
    ss[tid] = sv;
    __syncthreads();

    // 24 projections: one warp each
    {
        const float* phi; int stride, col;
        if (wid < 4)       { phi = phi_pre;  stride = 4;  col = wid; }
        else if (wid < 8)  { phi = phi_post; stride = 4;  col = wid - 4; }
        else               { phi = phi_res;  stride = 16; col = wid - 8; }
        float acc = 0.f;
        for (int j = lane; j < ND; j += 32) acc += ss[j] * phi[j * stride + col];
        #pragma unroll
        for (int o = 16; o; o >>= 1) acc += __shfl_xor_sync(~0u, acc, o);
        if (lane == 0) {
            float t;
            if (wid < 4)      t = a_pre[0]  * acc + b_pre[col];
            else if (wid < 8) t = a_post[0] * acc + b_post[col];
            else              t = a_res[0]  * acc + b_res[col];
            tilde[wid] = t;
        }
    }
    __syncthreads();

    // Sinkhorn on warp 0, lanes 0..15 hold the 4x4 (lane = i*4+j)
    if (wid == 0) {
        float v = (lane < 16) ? tilde[8 + lane] : -1e30f;
        float m = v;
        #pragma unroll
        for (int o = 8; o; o >>= 1) m = fmaxf(m, __shfl_xor_sync(~0u, m, o));
        v = expf(v - m);
        #pragma unroll 1
        for (int it = 0; it < 20; it++) {
            float rs = v;
            rs += __shfl_xor_sync(~0u, rs, 1);
            rs += __shfl_xor_sync(~0u, rs, 2);
            v = v / (rs + 1e-8f);
            float cs = v;
            cs += __shfl_xor_sync(~0u, cs, 4);
            cs += __shfl_xor_sync(~0u, cs, 8);
            v = v / (cs + 1e-8f);
        }
        if (lane < 16) hres[lane] = v;
        if (lane < 4) {
            hpre[lane] = 1.f / (1.f + expf(-tilde[lane]));
            hpost[(size_t)tok * 4 + lane] = 2.f / (1.f + expf(-tilde[4 + lane]));
        }
    }
    __syncthreads();

    // x_res -> out ; x_in
    int i = tid / D, dd = tid % D;
    float r = hres[i * 4 + 0] * xs[0 * D + dd] + hres[i * 4 + 1] * xs[1 * D + dd]
            + hres[i * 4 + 2] * xs[2 * D + dd] + hres[i * 4 + 3] * xs[3 * D + dd];
    out[(size_t)tok * ND + tid] = r;
    if (tid < D) {
        float xi = hpre[0] * xs[dd] + hpre[1] * xs[D + dd]
                 + hpre[2] * xs[2 * D + dd] + hpre[3] * xs[3 * D + dd];
        xin[(size_t)tok * D + dd] = xi;
    }
}

// =================================================================================
// Kernel 2: LayerNorm over D=192. One block (192 threads) per token.
// =================================================================================
__global__ __launch_bounds__(192) void ln_kernel(
    const float* __restrict__ in, const float* __restrict__ w,
    const float* __restrict__ b, float* __restrict__ outp)
{
    int tok = blockIdx.x, tid = threadIdx.x;
    int lane = tid & 31, wid = tid >> 5;
    __shared__ float red[6];
    __shared__ float s_mean, s_invstd;

    float v = in[(size_t)tok * D + tid];
    float sm = v;
    #pragma unroll
    for (int o = 16; o; o >>= 1) sm += __shfl_xor_sync(~0u, sm, o);
    if (lane == 0) red[wid] = sm;
    __syncthreads();
    if (tid == 0) {
        float s = 0.f;
        #pragma unroll
        for (int i = 0; i < 6; i++) s += red[i];
        s_mean = s / (float)D;
    }
    __syncthreads();
    float dv = v - s_mean;
    float sq = dv * dv;
    #pragma unroll
    for (int o = 16; o; o >>= 1) sq += __shfl_xor_sync(~0u, sq, o);
    __syncthreads();               // red reads done (tid0 read between barriers)
    if (lane == 0) red[wid] = sq;
    __syncthreads();
    if (tid == 0) {
        float s = 0.f;
        #pragma unroll
        for (int i = 0; i < 6; i++) s += red[i];
        s_invstd = rsqrtf(s / (float)D + 1e-5f);
    }
    __syncthreads();
    outp[(size_t)tok * D + tid] = dv * s_invstd * w[tid] + b[tid];
}

// =================================================================================
// Kernel 3: smem-tiled fp32 GEMM. C[M,N] = A[M,K] @ B[K,N] (+epilogue)
// BM=64 BN=64 BK=16, 256 threads, 4x4 per thread.
// EPI: 0 plain, 1 +Res, 2 gelu, 3 fused final scatter: out += (acc+Res)*h_post
// =================================================================================
__device__ __forceinline__ float gelu_f(float x) {
    float x3 = x * x * x;
    float t = tanhf(0.7978845608028654f * (x + 0.044715f * x3));
    return 0.5f * x * (1.f + t);
}

template <int EPI>
__global__ __launch_bounds__(256) void gemm_kernel(
    const float* __restrict__ A, const float* __restrict__ B,
    const float* __restrict__ Res, const float* __restrict__ hpost,
    float* __restrict__ C, int N, int K)
{
    const int BM = 64, BN = 64, BK = 16;
    __shared__ __align__(16) float As[BK][68];
    __shared__ __align__(16) float Bs[BK][BN];

    int bm = blockIdx.y, bn = blockIdx.x;
    int tid = threadIdx.x;
    int ty = tid >> 4, tx = tid & 15;

    float acc[4][4] = {};
    const float* Ag = A + (size_t)(bm * BM) * K;
    const float* Bg = B + bn * BN;
    int ar = tid >> 2, ac = (tid & 3) * 4;
    int br = tid >> 4, bc = (tid & 15) * 4;

    for (int kb = 0; kb < K; kb += BK) {
        float4 av = *(const float4*)(Ag + (size_t)ar * K + kb + ac);
        As[ac + 0][ar] = av.x; As[ac + 1][ar] = av.y;
        As[ac + 2][ar] = av.z; As[ac + 3][ar] = av.w;
        *(float4*)(&Bs[br][bc]) = *(const float4*)(Bg + (size_t)(kb + br) * N + bc);
        __syncthreads();
        #pragma unroll
        for (int kk = 0; kk < BK; kk++) {
            float4 a = *(const float4*)(&As[kk][ty * 4]);
            float4 b = *(const float4*)(&Bs[kk][tx * 4]);
            acc[0][0] += a.x * b.x; acc[0][1] += a.x * b.y; acc[0][2] += a.x * b.z; acc[0][3] += a.x * b.w;
            acc[1][0] += a.y * b.x; acc[1][1] += a.y * b.y; acc[1][2] += a.y * b.z; acc[1][3] += a.y * b.w;
            acc[2][0] += a.z * b.x; acc[2][1] += a.z * b.y; acc[2][2] += a.z * b.z; acc[2][3] += a.z * b.w;
            acc[3][0] += a.w * b.x; acc[3][1] += a.w * b.y; acc[3][2] += a.w * b.z; acc[3][3] += a.w * b.w;
        }
        __syncthreads();
    }

    int row0 = bm * BM + ty * 4, col0 = bn * BN + tx * 4;
    #pragma unroll
    for (int i = 0; i < 4; i++) {
        int row = row0 + i;
        if (EPI == 0) {
            float4 v = make_float4(acc[i][0], acc[i][1], acc[i][2], acc[i][3]);
            *(float4*)(C + (size_t)row * N + col0) = v;
        } else if (EPI == 1) {
            float4 r = *(const float4*)(Res + (size_t)row * N + col0);
            float4 v = make_float4(acc[i][0] + r.x, acc[i][1] + r.y, acc[i][2] + r.z, acc[i][3] + r.w);
            *(float4*)(C + (size_t)row * N + col0) = v;
        } else if (EPI == 2) {
            float4 v = make_float4(gelu_f(acc[i][0]), gelu_f(acc[i][1]), gelu_f(acc[i][2]), gelu_f(acc[i][3]));
            *(float4*)(C + (size_t)row * N + col0) = v;
        } else {
            float4 r = *(const float4*)(Res + (size_t)row * N + col0);
            float vx = acc[i][0] + r.x, vy = acc[i][1] + r.y, vz = acc[i][2] + r.z, vw = acc[i][3] + r.w;
            #pragma unroll
            for (int s = 0; s < 4; s++) {
                float hp = hpost[(size_t)row * 4 + s];
                float* op = C + (size_t)row * ND + s * D + col0;
                float4 o = *(const float4*)op;
                o.x += vx * hp; o.y += vy * hp; o.z += vz * hp; o.w += vw * hp;
                *(float4*)op = o;
            }
        }
    }
}

// =================================================================================
// Kernel 4: fp32 flash attention. BQ=64 queries/block, BKEY=32 key tile, HD=64.
// grid (T/64, NH, NB), 256 threads (16x16, 4x4 O / 4x2 S per thread).
// =================================================================================
__global__ __launch_bounds__(256) void flash_kernel(
    const float* __restrict__ Q, const float* __restrict__ K,
    const float* __restrict__ V, float* __restrict__ O)
{
    const int BQ = 64, BKY = 32;
    __shared__ __align__(16) float Qt[HD][BQ];   // [d][q]
    __shared__ __align__(16) float Kt[HD][BKY];  // [d][k]
    __shared__ __align__(16) float Vs[BKY][HD];  // [k][d]
    __shared__ __align__(16) float Pt[BKY][BQ];  // [k][q]

    int qt = blockIdx.x, h = blockIdx.y, b = blockIdx.z;
    int tid = threadIdx.x;
    int ty = tid >> 4, tx = tid & 15;
    size_t base = ((size_t)b * T_SEQ) * D + h * HD;

    // load Q tile transposed
    {
        int r = tid >> 2;
        int c0 = (tid & 3) * 16;
        const float* qp = Q + base + (size_t)(qt * BQ + r) * D + c0;
        #pragma unroll
        for (int u = 0; u < 4; u++) {
            float4 v = *(const float4*)(qp + u * 4);
            Qt[c0 + u * 4 + 0][r] = v.x; Qt[c0 + u * 4 + 1][r] = v.y;
            Qt[c0 + u * 4 + 2][r] = v.z; Qt[c0 + u * 4 + 3][r] = v.w;
        }
    }
    float m_prev[4], l_run[4], o_acc[4][4];
    #pragma unroll
    for (int i = 0; i < 4; i++) {
        m_prev[i] = -1e30f; l_run[i] = 0.f;
        #pragma unroll
        for (int j = 0; j < 4; j++) o_acc[i][j] = 0.f;
    }
    __syncthreads();

    for (int kt = 0; kt < T_SEQ; kt += BKY) {
        // load K (transposed) and V tiles
        {
            int r = tid >> 3;
            int c0 = (tid & 7) * 8;
            const float* kp = K + base + (size_t)(kt + r) * D + c0;
            const float* vp = V + base + (size_t)(kt + r) * D + c0;
            #pragma unroll
            for (int u = 0; u < 2; u++) {
                float4 kv = *(const float4*)(kp + u * 4);
                Kt[c0 + u * 4 + 0][r] = kv.x; Kt[c0 + u * 4 + 1][r] = kv.y;
                Kt[c0 + u * 4 + 2][r] = kv.z; Kt[c0 + u * 4 + 3][r] = kv.w;
                *(float4*)(&Vs[r][c0 + u * 4]) = *(const float4*)(vp + u * 4);
            }
        }
        __syncthreads();

        // S = (Q K^T) * scale : 4 rows x 2 cols per thread
        float s[4][2] = {};
        #pragma unroll
        for (int kk = 0; kk < HD; kk++) {
            float4 a = *(const float4*)(&Qt[kk][ty * 4]);
            float2 kb2 = *(const float2*)(&Kt[kk][tx * 2]);
            s[0][0] += a.x * kb2.x; s[0][1] += a.x * kb2.y;
            s[1][0] += a.y * kb2.x; s[1][1] += a.y * kb2.y;
            s[2][0] += a.z * kb2.x; s[2][1] += a.z * kb2.y;
            s[3][0] += a.w * kb2.x; s[3][1] += a.w * kb2.y;
        }
        const float scale = 0.125f;
        float p[4][2];
        #pragma unroll
        for (int i = 0; i < 4; i++) {
            s[i][0] *= scale; s[i][1] *= scale;
            float mx = fmaxf(s[i][0], s[i][1]);
            #pragma unroll
            for (int o = 8; o; o >>= 1) mx = fmaxf(mx, __shfl_xor_sync(~0u, mx, o));
            float m_new = fmaxf(m_prev[i], mx);
            p[i][0] = expf(s[i][0] - m_new);
            p[i][1] = expf(s[i][1] - m_new);
            float rs = p[i][0] + p[i][1];
            #pragma unroll
            for (int o = 8; o; o >>= 1) rs += __shfl_xor_sync(~0u, rs, o);
            float scl = expf(m_prev[i] - m_new);
            l_run[i] = l_run[i] * scl + rs;
            m_prev[i] = m_new;
            o_acc[i][0] *= scl; o_acc[i][1] *= scl; o_acc[i][2] *= scl; o_acc[i][3] *= scl;
        }
        // stage P transposed
        #pragma unroll
        for (int i = 0; i < 4; i++) {
            Pt[tx * 2 + 0][ty * 4 + i] = p[i][0];
            Pt[tx * 2 + 1][ty * 4 + i] = p[i][1];
        }
        __syncthreads();
        // O += P V
        #pragma unroll
        for (int kk = 0; kk < BKY; kk++) {
            float4 a  = *(const float4*)(&Pt[kk][ty * 4]);
            float4 bv = *(const float4*)(&Vs[kk][tx * 4]);
            o_acc[0][0] += a.x * bv.x; o_acc[0][1] += a.x * bv.y; o_acc[0][2] += a.x * bv.z; o_acc[0][3] += a.x * bv.w;
            o_acc[1][0] += a.y * bv.x; o_acc[1][1] += a.y * bv.y; o_acc[1][2] += a.y * bv.z; o_acc[1][3] += a.y * bv.w;
            o_acc[2][0] += a.z * bv.x; o_acc[2][1] += a.z * bv.y; o_acc[2][2] += a.z * bv.z; o_acc[2][3] += a.z * bv.w;
            o_acc[3][0] += a.w * bv.x; o_acc[3][1] += a.w * bv.y; o_acc[3][2] += a.w * bv.z; o_acc[3][3] += a.w * bv.w;
        }
        __syncthreads();
    }

    #pragma unroll
    for (int i = 0; i < 4; i++) {
        float inv = 1.f / l_run[i];
        float4 v = make_float4(o_acc[i][0] * inv, o_acc[i][1] * inv,
                               o_acc[i][2] * inv, o_acc[i][3] * inv);
        *(float4*)(O + base + (size_t)(qt * BQ + ty * 4 + i) * D + tx * 4) = v;
    }
}

// =================================================================================
extern "C" void kernel_launch(void* const* d_in, const int* in_sizes, int n_in,
                              void* d_out, int out_size)
{
    const float* x        = (const float*)d_in[0];
    const float* norm_w   = (const float*)d_in[1];
    const float* phi_pre  = (const float*)d_in[2];
    const float* phi_post = (const float*)d_in[3];
    const float* phi_res  = (const float*)d_in[4];
    const float* b_pre    = (const float*)d_in[5];
    const float* b_post   = (const float*)d_in[6];
    const float* b_res    = (const float*)d_in[7];
    const float* a_pre    = (const float*)d_in[8];
    const float* a_post   = (const float*)d_in[9];
    const float* a_res    = (const float*)d_in[10];
    const float* ln1_w    = (const float*)d_in[11];
    const float* ln1_b    = (const float*)d_in[12];
    const float* Wq       = (const float*)d_in[13];
    const float* Wk       = (const float*)d_in[14];
    const float* Wv       = (const float*)d_in[15];
    const float* Wo       = (const float*)d_in[16];
    const float* ln2_w    = (const float*)d_in[17];
    const float* ln2_b    = (const float*)d_in[18];
    const float* W1       = (const float*)d_in[19];
    const float* W2       = (const float*)d_in[20];
    float* out = (float*)d_out;

    void *p_xin, *p_h, *p_q, *p_k, *p_v, *p_o, *p_x2, *p_g, *p_hpost;
    cudaGetSymbolAddress(&p_xin,  g_xin);
    cudaGetSymbolAddress(&p_h,    g_h);
    cudaGetSymbolAddress(&p_q,    g_q);
    cudaGetSymbolAddress(&p_k,    g_k);
    cudaGetSymbolAddress(&p_v,    g_v);
    cudaGetSymbolAddress(&p_o,    g_o);
    cudaGetSymbolAddress(&p_x2,   g_x2);
    cudaGetSymbolAddress(&p_g,    g_g);
    cudaGetSymbolAddress(&p_hpost, g_hpost);
    float* xin  = (float*)p_xin;  float* h   = (float*)p_h;
    float* q    = (float*)p_q;    float* k   = (float*)p_k;
    float* v    = (float*)p_v;    float* o   = (float*)p_o;
    float* x2   = (float*)p_x2;   float* g   = (float*)p_g;
    float* hpost = (float*)p_hpost;

    // 1) gating / sinkhorn / x_res / x_in
    gate_kernel<<<BT, 768>>>(x, norm_w, phi_pre, phi_post, phi_res,
                             b_pre, b_post, b_res, a_pre, a_post, a_res,
                             out, xin, hpost);
    // 2) LN1
    ln_kernel<<<BT, 192>>>(xin, ln1_w, ln1_b, h);
    // 3) QKV
    dim3 g192(D / 64, BT / 64), g768(MLP / 64, BT / 64);
    gemm_kernel<0><<<g192, 256>>>(h, Wq, nullptr, nullptr, q, D, D);
    gemm_kernel<0><<<g192, 256>>>(h, Wk, nullptr, nullptr, k, D, D);
    gemm_kernel<0><<<g192, 256>>>(h, Wv, nullptr, nullptr, v, D, D);
    // 4) attention
    flash_kernel<<<dim3(T_SEQ / 64, NH, NB), 256>>>(q, k, v, o);
    // 5) Wo + residual
    gemm_kernel<1><<<g192, 256>>>(o, Wo, xin, nullptr, x2, D, D);
    // 6) LN2
    ln_kernel<<<BT, 192>>>(x2, ln2_w, ln2_b, h);
    // 7) MLP up + GELU
    gemm_kernel<2><<<g768, 256>>>(h, W1, nullptr, nullptr, g, MLP, D);
    // 8) MLP down + residual + fused gated scatter into out
    gemm_kernel<3><<<g192, 256>>>(g, W2, x2, hpost, out, D, MLP);
}

// round 3
// speedup vs baseline: 1.4268x; 1.4268x over previous
#include <cuda_runtime.h>
#include <cuda_bf16.h>
#include <math.h>

#define BT 32768
#define NSTREAM 4
#define D 192
#define ND 768
#define MLP 768
#define T_SEQ 1024
#define NB 32
#define NH 3
#define HD 64

// ---------------- scratch (device globals; no allocation allowed) ----------------
__device__ float g_xin[BT * D];
__device__ float g_h[BT * D];
__device__ float g_q[BT * D];
__device__ float g_k[BT * D];
__device__ float g_v[BT * D];
__device__ float g_o[BT * D];
__device__ float g_x2[BT * D];
__device__ float g_g[BT * MLP];
__device__ float g_hpost[BT * NSTREAM];

// ---------------- tf32 mma helpers ----------------
__device__ __forceinline__ unsigned f2tf32(float f) {
    unsigned r;
    asm("cvt.rna.tf32.f32 %0, %1;" : "=r"(r) : "f"(f));
    return r;
}

__device__ __forceinline__ void mma_tf32(float c[4],
    unsigned a0, unsigned a1, unsigned a2, unsigned a3,
    unsigned b0, unsigned b1)
{
    asm volatile(
        "mma.sync.aligned.m16n8k8.row.col.f32.tf32.tf32.f32 "
        "{%0,%1,%2,%3}, {%4,%5,%6,%7}, {%8,%9}, {%0,%1,%2,%3};\n"
        : "+f"(c[0]), "+f"(c[1]), "+f"(c[2]), "+f"(c[3])
        : "r"(a0), "r"(a1), "r"(a2), "r"(a3), "r"(b0), "r"(b1));
}

// =================================================================================
// Kernel 1: gate kernel. One block (768 threads) per token.
// =================================================================================
__global__ __launch_bounds__(768) void gate_kernel(
    const float* __restrict__ x, const float* __restrict__ norm_w,
    const float* __restrict__ phi_pre, const float* __restrict__ phi_post,
    const float* __restrict__ phi_res,
    const float* __restrict__ b_pre, const float* __restrict__ b_post,
    const float* __restrict__ b_res,
    const float* __restrict__ a_pre, const float* __restrict__ a_post,
    const float* __restrict__ a_res,
    float* __restrict__ out, float* __restrict__ xin, float* __restrict__ hpost)
{
    int tok = blockIdx.x;
    int tid = threadIdx.x;
    int lane = tid & 31, wid = tid >> 5;

    __shared__ __align__(16) float xs[ND];
    __shared__ __align__(16) float ss[ND];
    __shared__ float red[24];
    __shared__ float tilde[24];
    __shared__ float hres[16];
    __shared__ float hpre[4];
    __shared__ float s_inv;

    float xv = x[(size_t)tok * ND + tid];
    xs[tid] = xv;

    float sq = xv * xv;
    #pragma unroll
    for (int o = 16; o; o >>= 1) sq += __shfl_xor_sync(~0u, sq, o);
    if (lane == 0) red[wid] = sq;
    __syncthreads();
    if (tid == 0) {
        float s = 0.f;
        #pragma unroll
        for (int i = 0; i < 24; i++) s += red[i];
        s_inv = rsqrtf(s / (float)ND + 1e-8f);
    }
    __syncthreads();
    float sv = xv * s_inv * norm_w[tid];
    ss[tid] = sv;
    __syncthreads();

    {
        const float* phi; int stride, col;
        if (wid < 4)       { phi = phi_pre;  stride = 4;  col = wid; }
        else if (wid < 8)  { phi = phi_post; stride = 4;  col = wid - 4; }
        else               { phi = phi_res;  stride = 16; col = wid - 8; }
        float acc = 0.f;
        for (int j = lane; j < ND; j += 32) acc += ss[j] * phi[j * stride + col];
        #pragma unroll
        for (int o = 16; o; o >>= 1) acc += __shfl_xor_sync(~0u, acc, o);
        if (lane == 0) {
            float t;
            if (wid < 4)      t = a_pre[0]  * acc + b_pre[col];
            else if (wid < 8) t = a_post[0] * acc + b_post[col];
            else              t = a_res[0]  * acc + b_res[col];
            tilde[wid] = t;
        }
    }
    __syncthreads();

    if (wid == 0) {
        float v = (lane < 16) ? tilde[8 + lane] : -1e30f;
        float m = v;
        #pragma unroll
        for (int o = 8; o; o >>= 1) m = fmaxf(m, __shfl_xor_sync(~0u, m, o));
        v = expf(v - m);
        #pragma unroll 1
        for (int it = 0; it < 20; it++) {
            float rs = v;
            rs += __shfl_xor_sync(~0u, rs, 1);
            rs += __shfl_xor_sync(~0u, rs, 2);
            v = v / (rs + 1e-8f);
            float cs = v;
            cs += __shfl_xor_sync(~0u, cs, 4);
            cs += __shfl_xor_sync(~0u, cs, 8);
            v = v / (cs + 1e-8f);
        }
        if (lane < 16) hres[lane] = v;
        if (lane < 4) {
            hpre[lane] = 1.f / (1.f + expf(-tilde[lane]));
            hpost[(size_t)tok * 4 + lane] = 2.f / (1.f + expf(-tilde[4 + lane]));
        }
    }
    __syncthreads();

    int i = tid / D, dd = tid % D;
    float r = hres[i * 4 + 0] * xs[0 * D + dd] + hres[i * 4 + 1] * xs[1 * D + dd]
            + hres[i * 4 + 2] * xs[2 * D + dd] + hres[i * 4 + 3] * xs[3 * D + dd];
    out[(size_t)tok * ND + tid] = r;
    if (tid < D) {
        float xi = hpre[0] * xs[dd] + hpre[1] * xs[D + dd]
                 + hpre[2] * xs[2 * D + dd] + hpre[3] * xs[3 * D + dd];
        xin[(size_t)tok * D + dd] = xi;
    }
}

// =================================================================================
// Kernel 2: LayerNorm over D=192.
// =================================================================================
__global__ __launch_bounds__(192) void ln_kernel(
    const float* __restrict__ in, const float* __restrict__ w,
    const float* __restrict__ b, float* __restrict__ outp)
{
    int tok = blockIdx.x, tid = threadIdx.x;
    int lane = tid & 31, wid = tid >> 5;
    __shared__ float red[6];
    __shared__ float s_mean, s_invstd;

    float v = in[(size_t)tok * D + tid];
    float sm = v;
    #pragma unroll
    for (int o = 16; o; o >>= 1) sm += __shfl_xor_sync(~0u, sm, o);
    if (lane == 0) red[wid] = sm;
    __syncthreads();
    if (tid == 0) {
        float s = 0.f;
        #pragma unroll
        for (int i = 0; i < 6; i++) s += red[i];
        s_mean = s / (float)D;
    }
    __syncthreads();
    float dv = v - s_mean;
    float sq = dv * dv;
    #pragma unroll
    for (int o = 16; o; o >>= 1) sq += __shfl_xor_sync(~0u, sq, o);
    __syncthreads();
    if (lane == 0) red[wid] = sq;
    __syncthreads();
    if (tid == 0) {
        float s = 0.f;
        #pragma unroll
        for (int i = 0; i < 6; i++) s += red[i];
        s_invstd = rsqrtf(s / (float)D + 1e-5f);
    }
    __syncthreads();
    outp[(size_t)tok * D + tid] = dv * s_invstd * w[tid] + b[tid];
}

// =================================================================================
// Kernel 3: tf32 tensor-core GEMM. C[M,N] = A[M,K] @ B[K,N] (+epilogue)
// BM=128 BN=64 BK=32, 256 threads (8 warps), warp tile 32x32 (2x4 m16n8k8 mmas).
// EPI: 0 plain, 1 +Res, 2 gelu, 3 fused final scatter: out += (acc+Res)*h_post
// =================================================================================
__device__ __forceinline__ float gelu_f(float x) {
    float x3 = x * x * x;
    float t = tanhf(0.7978845608028654f * (x + 0.044715f * x3));
    return 0.5f * x * (1.f + t);
}

template <int EPI>
__global__ __launch_bounds__(256) void gemm_tc(
    const float* __restrict__ A, const float* __restrict__ B,
    const float* __restrict__ Res, const float* __restrict__ hpost,
    float* __restrict__ C, int N, int K)
{
    __shared__ __align__(16) unsigned As[128][36];  // [m][k], stride%32==4 -> CF frags
    __shared__ __align__(16) unsigned Bs[32][72];   // [k][n], stride%32==8 -> CF frags

    int tid = threadIdx.x;
    int wid = tid >> 5, lane = tid & 31;
    int g = lane >> 2, tig = lane & 3;
    int wm = wid & 3, wn = wid >> 2;     // 4 x 2 warp grid
    int bm = blockIdx.y, bn = blockIdx.x;

    float acc[2][4][4] = {};

    const float* Ag = A + (size_t)(bm * 128) * K;
    const float* Bg = B + bn * 64;
    int ar = tid >> 1, ac = (tid & 1) * 16;
    int br = tid >> 3, bc = (tid & 7) * 8;

    for (int kb = 0; kb < K; kb += 32) {
        const float* ap = Ag + (size_t)ar * K + kb + ac;
        #pragma unroll
        for (int u = 0; u < 4; u++) {
            float4 v = *(const float4*)(ap + u * 4);
            uint4 t = make_uint4(f2tf32(v.x), f2tf32(v.y), f2tf32(v.z), f2tf32(v.w));
            *(uint4*)&As[ar][ac + u * 4] = t;
        }
        const float* bp = Bg + (size_t)(kb + br) * N + bc;
        #pragma unroll
        for (int u = 0; u < 2; u++) {
            float4 v = *(const float4*)(bp + u * 4);
            uint4 t = make_uint4(f2tf32(v.x), f2tf32(v.y), f2tf32(v.z), f2tf32(v.w));
            *(uint4*)&Bs[br][bc + u * 4] = t;
        }
        __syncthreads();

        #pragma unroll
        for (int ks = 0; ks < 4; ks++) {
            int k0 = ks * 8;
            unsigned a[2][4], b[4][2];
            #pragma unroll
            for (int mt = 0; mt < 2; mt++) {
                int m0 = wm * 32 + mt * 16;
                a[mt][0] = As[m0 + g][k0 + tig];
                a[mt][1] = As[m0 + g + 8][k0 + tig];
                a[mt][2] = As[m0 + g][k0 + tig + 4];
                a[mt][3] = As[m0 + g + 8][k0 + tig + 4];
            }
            #pragma unroll
            for (int nt = 0; nt < 4; nt++) {
                int n0 = wn * 32 + nt * 8;
                b[nt][0] = Bs[k0 + tig][n0 + g];
                b[nt][1] = Bs[k0 + tig + 4][n0 + g];
            }
            #pragma unroll
            for (int mt = 0; mt < 2; mt++)
                #pragma unroll
                for (int nt = 0; nt < 4; nt++)
                    mma_tf32(acc[mt][nt], a[mt][0], a[mt][1], a[mt][2], a[mt][3],
                             b[nt][0], b[nt][1]);
        }
        __syncthreads();
    }

    #pragma unroll
    for (int mt = 0; mt < 2; mt++) {
        #pragma unroll
        for (int half = 0; half < 2; half++) {
            int row = bm * 128 + wm * 32 + mt * 16 + g + half * 8;
            #pragma unroll
            for (int nt = 0; nt < 4; nt++) {
                int col = bn * 64 + wn * 32 + nt * 8 + tig * 2;
                float v0 = acc[mt][nt][half * 2 + 0];
                float v1 = acc[mt][nt][half * 2 + 1];
                if (EPI == 0) {
                    *(float2*)(C + (size_t)row * N + col) = make_float2(v0, v1);
                } else if (EPI == 1) {
                    float2 r = *(const float2*)(Res + (size_t)row * N + col);
                    *(float2*)(C + (size_t)row * N + col) = make_float2(v0 + r.x, v1 + r.y);
                } else if (EPI == 2) {
                    *(float2*)(C + (size_t)row * N + col) = make_float2(gelu_f(v0), gelu_f(v1));
                } else {
                    float2 r = *(const float2*)(Res + (size_t)row * N + col);
                    float vx = v0 + r.x, vy = v1 + r.y;
                    #pragma unroll
                    for (int s = 0; s < 4; s++) {
                        float hp = hpost[(size_t)row * 4 + s];
                        float* op = C + (size_t)row * ND + s * D + col;
                        float2 o = *(const float2*)op;
                        o.x += vx * hp; o.y += vy * hp;
                        *(float2*)op = o;
                    }
                }
            }
        }
    }
}

// =================================================================================
// Kernel 4: tf32 tensor-core flash attention. BQ=64, BKEY=32, HD=64.
// 128 threads (4 warps), warp owns 16 q-rows. grid (T/64, NH, NB).
// =================================================================================
__global__ __launch_bounds__(128) void flash_tc(
    const float* __restrict__ Q, const float* __restrict__ K,
    const float* __restrict__ V, float* __restrict__ O)
{
    __shared__ __align__(16) unsigned Qs[64][68];  // [q][d]  stride%32==4
    __shared__ __align__(16) unsigned Ks[32][68];  // [key][d] stride%32==4
    __shared__ __align__(16) unsigned Vs[32][72];  // [key][d] stride%32==8 (B-frag)
    __shared__ __align__(16) unsigned Ps[64][36];  // [q][key] stride%32==4 (A-frag)

    int tid = threadIdx.x, wid = tid >> 5, lane = tid & 31;
    int g = lane >> 2, tig = lane & 3;
    int qt = blockIdx.x, h = blockIdx.y, b = blockIdx.z;
    size_t base = ((size_t)b * T_SEQ) * D + h * HD;
    int m0 = wid * 16;

    // load Q tile (64x64)
    {
        int r = tid >> 1, c0 = (tid & 1) * 32;
        const float* qp = Q + base + (size_t)(qt * 64 + r) * D + c0;
        #pragma unroll
        for (int u = 0; u < 8; u++) {
            float4 v = *(const float4*)(qp + u * 4);
            uint4 t = make_uint4(f2tf32(v.x), f2tf32(v.y), f2tf32(v.z), f2tf32(v.w));
            *(uint4*)&Qs[r][c0 + u * 4] = t;
        }
    }
    float m_prev[2] = {-1e30f, -1e30f};
    float l_run[2] = {0.f, 0.f};
    float o_acc[8][4] = {};
    __syncthreads();

    for (int kt = 0; kt < T_SEQ; kt += 32) {
        // load K,V tiles (32x64 each)
        {
            int r = tid >> 2, c0 = (tid & 3) * 16;
            const float* kp = K + base + (size_t)(kt + r) * D + c0;
            const float* vp = V + base + (size_t)(kt + r) * D + c0;
            #pragma unroll
            for (int u = 0; u < 4; u++) {
                float4 kv = *(const float4*)(kp + u * 4);
                uint4 t = make_uint4(f2tf32(kv.x), f2tf32(kv.y), f2tf32(kv.z), f2tf32(kv.w));
                *(uint4*)&Ks[r][c0 + u * 4] = t;
                float4 vv = *(const float4*)(vp + u * 4);
                uint4 t2 = make_uint4(f2tf32(vv.x), f2tf32(vv.y), f2tf32(vv.z), f2tf32(vv.w));
                *(uint4*)&Vs[r][c0 + u * 4] = t2;
            }
        }
        __syncthreads();

        // S = Q K^T (warp: 16 q-rows x 32 keys)
        float s[4][4] = {};
        #pragma unroll
        for (int ks = 0; ks < 8; ks++) {
            int k0 = ks * 8;
            unsigned a0 = Qs[m0 + g][k0 + tig];
            unsigned a1 = Qs[m0 + g + 8][k0 + tig];
            unsigned a2 = Qs[m0 + g][k0 + tig + 4];
            unsigned a3 = Qs[m0 + g + 8][k0 + tig + 4];
            #pragma unroll
            for (int nt = 0; nt < 4; nt++) {
                unsigned b0 = Ks[nt * 8 + g][k0 + tig];
                unsigned b1 = Ks[nt * 8 + g][k0 + tig + 4];
                mma_tf32(s[nt], a0, a1, a2, a3, b0, b1);
            }
        }

        // online softmax (row groups = quads; shfl_xor 1,2 reduce within row)
        const float sc = 0.125f;
        float mx0 = -1e30f, mx1 = -1e30f;
        #pragma unroll
        for (int nt = 0; nt < 4; nt++) {
            s[nt][0] *= sc; s[nt][1] *= sc; s[nt][2] *= sc; s[nt][3] *= sc;
            mx0 = fmaxf(mx0, fmaxf(s[nt][0], s[nt][1]));
            mx1 = fmaxf(mx1, fmaxf(s[nt][2], s[nt][3]));
        }
        mx0 = fmaxf(mx0, __shfl_xor_sync(~0u, mx0, 1));
        mx0 = fmaxf(mx0, __shfl_xor_sync(~0u, mx0, 2));
        mx1 = fmaxf(mx1, __shfl_xor_sync(~0u, mx1, 1));
        mx1 = fmaxf(mx1, __shfl_xor_sync(~0u, mx1, 2));
        float mn0 = fmaxf(m_prev[0], mx0);
        float mn1 = fmaxf(m_prev[1], mx1);
        float rs0 = 0.f, rs1 = 0.f;
        #pragma unroll
        for (int nt = 0; nt < 4; nt++) {
            s[nt][0] = __expf(s[nt][0] - mn0);
            s[nt][1] = __expf(s[nt][1] - mn0);
            s[nt][2] = __expf(s[nt][2] - mn1);
            s[nt][3] = __expf(s[nt][3] - mn1);
            rs0 += s[nt][0] + s[nt][1];
            rs1 += s[nt][2] + s[nt][3];
        }
        rs0 += __shfl_xor_sync(~0u, rs0, 1);
        rs0 += __shfl_xor_sync(~0u, rs0, 2);
        rs1 += __shfl_xor_sync(~0u, rs1, 1);
        rs1 += __shfl_xor_sync(~0u, rs1, 2);
        float scl0 = __expf(m_prev[0] - mn0);
        float scl1 = __expf(m_prev[1] - mn1);
        l_run[0] = l_run[0] * scl0 + rs0;
        l_run[1] = l_run[1] * scl1 + rs1;
        m_prev[0] = mn0; m_prev[1] = mn1;
        #pragma unroll
        for (int nt = 0; nt < 8; nt++) {
            o_acc[nt][0] *= scl0; o_acc[nt][1] *= scl0;
            o_acc[nt][2] *= scl1; o_acc[nt][3] *= scl1;
        }
        // stage P (C-layout -> [q][key])
        #pragma unroll
        for (int nt = 0; nt < 4; nt++) {
            int c0 = nt * 8 + tig * 2;
            Ps[m0 + g][c0]         = f2tf32(s[nt][0]);
            Ps[m0 + g][c0 + 1]     = f2tf32(s[nt][1]);
            Ps[m0 + g + 8][c0]     = f2tf32(s[nt][2]);
            Ps[m0 + g + 8][c0 + 1] = f2tf32(s[nt][3]);
        }
        __syncthreads();

        // O += P V  (16 x 64 += 16x32 @ 32x64)
        #pragma unroll
        for (int ks = 0; ks < 4; ks++) {
            int k0 = ks * 8;
            unsigned a0 = Ps[m0 + g][k0 + tig];
            unsigned a1 = Ps[m0 + g + 8][k0 + tig];
            unsigned a2 = Ps[m0 + g][k0 + tig + 4];
            unsigned a3 = Ps[m0 + g + 8][k0 + tig + 4];
            #pragma unroll
            for (int nt = 0; nt < 8; nt++) {
                unsigned b0 = Vs[k0 + tig][nt * 8 + g];
                unsigned b1 = Vs[k0 + tig + 4][nt * 8 + g];
                mma_tf32(o_acc[nt], a0, a1, a2, a3, b0, b1);
            }
        }
        __syncthreads();
    }

    float inv0 = 1.f / l_run[0];
    float inv1 = 1.f / l_run[1];
    int q0 = qt * 64 + m0 + g;
    #pragma unroll
    for (int nt = 0; nt < 8; nt++) {
        int col = nt * 8 + tig * 2;
        *(float2*)(O + base + (size_t)q0 * D + col) =
            make_float2(o_acc[nt][0] * inv0, o_acc[nt][1] * inv0);
        *(float2*)(O + base + (size_t)(q0 + 8) * D + col) =
            make_float2(o_acc[nt][2] * inv1, o_acc[nt][3] * inv1);
    }
}

// =================================================================================
extern "C" void kernel_launch(void* const* d_in, const int* in_sizes, int n_in,
                              void* d_out, int out_size)
{
    const float* x        = (const float*)d_in[0];
    const float* norm_w   = (const float*)d_in[1];
    const float* phi_pre  = (const float*)d_in[2];
    const float* phi_post = (const float*)d_in[3];
    const float* phi_res  = (const float*)d_in[4];
    const float* b_pre    = (const float*)d_in[5];
    const float* b_post   = (const float*)d_in[6];
    const float* b_res    = (const float*)d_in[7];
    const float* a_pre    = (const float*)d_in[8];
    const float* a_post   = (const float*)d_in[9];
    const float* a_res    = (const float*)d_in[10];
    const float* ln1_w    = (const float*)d_in[11];
    const float* ln1_b    = (const float*)d_in[12];
    const float* Wq       = (const float*)d_in[13];
    const float* Wk       = (const float*)d_in[14];
    const float* Wv       = (const float*)d_in[15];
    const float* Wo       = (const float*)d_in[16];
    const float* ln2_w    = (const float*)d_in[17];
    const float* ln2_b    = (const float*)d_in[18];
    const float* W1       = (const float*)d_in[19];
    const float* W2       = (const float*)d_in[20];
    float* out = (float*)d_out;

    void *p_xin, *p_h, *p_q, *p_k, *p_v, *p_o, *p_x2, *p_g, *p_hpost;
    cudaGetSymbolAddress(&p_xin,  g_xin);
    cudaGetSymbolAddress(&p_h,    g_h);
    cudaGetSymbolAddress(&p_q,    g_q);
    cudaGetSymbolAddress(&p_k,    g_k);
    cudaGetSymbolAddress(&p_v,    g_v);
    cudaGetSymbolAddress(&p_o,    g_o);
    cudaGetSymbolAddress(&p_x2,   g_x2);
    cudaGetSymbolAddress(&p_g,    g_g);
    cudaGetSymbolAddress(&p_hpost, g_hpost);
    float* xin  = (float*)p_xin;  float* h   = (float*)p_h;
    float* q    = (float*)p_q;    float* k   = (float*)p_k;
    float* v    = (float*)p_v;    float* o   = (float*)p_o;
    float* x2   = (float*)p_x2;   float* g   = (float*)p_g;
    float* hpost = (float*)p_hpost;

    // 1) gating / sinkhorn / x_res / x_in
    gate_kernel<<<BT, 768>>>(x, norm_w, phi_pre, phi_post, phi_res,
                             b_pre, b_post, b_res, a_pre, a_post, a_res,
                             out, xin, hpost);
    // 2) LN1
    ln_kernel<<<BT, 192>>>(xin, ln1_w, ln1_b, h);
    // 3) QKV (tf32 tensor cores)
    dim3 g192(D / 64, BT / 128), g768(MLP / 64, BT / 128);
    gemm_tc<0><<<g192, 256>>>(h, Wq, nullptr, nullptr, q, D, D);
    gemm_tc<0><<<g192, 256>>>(h, Wk, nullptr, nullptr, k, D, D);
    gemm_tc<0><<<g192, 256>>>(h, Wv, nullptr, nullptr, v, D, D);
    // 4) attention (tf32 tensor cores)
    flash_tc<<<dim3(T_SEQ / 64, NH, NB), 128>>>(q, k, v, o);
    // 5) Wo + residual
    gemm_tc<1><<<g192, 256>>>(o, Wo, xin, nullptr, x2, D, D);
    // 6) LN2
    ln_kernel<<<BT, 192>>>(x2, ln2_w, ln2_b, h);
    // 7) MLP up + GELU
    gemm_tc<2><<<g768, 256>>>(h, W1, nullptr, nullptr, g, MLP, D);
    // 8) MLP down + residual + fused gated scatter into out
    gemm_tc<3><<<g192, 256>>>(g, W2, x2, hpost, out, D, MLP);
}

// round 6
// speedup vs baseline: 4.8159x; 3.3753x over previous
#include <cuda_runtime.h>
#include <cuda_bf16.h>
#include <math.h>

#define BT 32768
#define NSTREAM 4
#define D 192
#define ND 768
#define MLP 768
#define T_SEQ 1024
#define NB 32
#define NH 3
#define HD 64

typedef __nv_bfloat16 bf16;

// ---------------- scratch (device globals; no allocation allowed) ----------------
__device__ float g_xin[BT * D];
__device__ float g_x2[BT * D];
__device__ float g_hpost[BT * NSTREAM];
__device__ float g_tilde[BT * 24];
__device__ float g_bias24[24];
__device__ bf16  g_streams[BT * ND];
__device__ bf16  g_h[BT * D];
__device__ bf16  g_q[BT * D];
__device__ bf16  g_k[BT * D];
__device__ bf16  g_v[BT * D];
__device__ bf16  g_o[BT * D];
__device__ bf16  g_g[BT * MLP];
__device__ bf16  g_wq[D * D];
__device__ bf16  g_wk[D * D];
__device__ bf16  g_wv[D * D];
__device__ bf16  g_wo[D * D];
__device__ bf16  g_w1[D * MLP];
__device__ bf16  g_w2[MLP * D];
__device__ bf16  g_phiC[ND * 64];   // cols 0-3 pre*alpha, 4-7 post*alpha, 8-23 res*alpha, 24-63 zero

// ---------------- helpers ----------------
__device__ __forceinline__ unsigned pack_bf16(float lo, float hi) {
    unsigned r;
    asm("cvt.rn.bf16x2.f32 %0, %1, %2;" : "=r"(r) : "f"(hi), "f"(lo));
    return r;
}

__device__ __forceinline__ void mma_bf16(float c[4],
    unsigned a0, unsigned a1, unsigned a2, unsigned a3,
    unsigned b0, unsigned b1)
{
    asm volatile(
        "mma.sync.aligned.m16n8k16.row.col.f32.bf16.bf16.f32 "
        "{%0,%1,%2,%3}, {%4,%5,%6,%7}, {%8,%9}, {%0,%1,%2,%3};\n"
        : "+f"(c[0]), "+f"(c[1]), "+f"(c[2]), "+f"(c[3])
        : "r"(a0), "r"(a1), "r"(a2), "r"(a3), "r"(b0), "r"(b1));
}

__device__ __forceinline__ float gelu_f(float x) {
    float x3 = x * x * x;
    float t = tanhf(0.7978845608028654f * (x + 0.044715f * x3));
    return 0.5f * x * (1.f + t);
}

// =================================================================================
// Kernel 0: weight conversion fp32 -> bf16 (+ phi combine with alpha, bias24)
// =================================================================================
__global__ void convert_kernel(
    const float* __restrict__ Wq, const float* __restrict__ Wk,
    const float* __restrict__ Wv, const float* __restrict__ Wo,
    const float* __restrict__ W1, const float* __restrict__ W2,
    const float* __restrict__ phi_pre, const float* __restrict__ phi_post,
    const float* __restrict__ phi_res,
    const float* __restrict__ b_pre, const float* __restrict__ b_post,
    const float* __restrict__ b_res,
    const float* __restrict__ a_pre, const float* __restrict__ a_post,
    const float* __restrict__ a_res)
{
    int idx = blockIdx.x * blockDim.x + threadIdx.x;
    if (idx < D * D) {
        g_wq[idx] = __float2bfloat16(Wq[idx]);
        g_wk[idx] = __float2bfloat16(Wk[idx]);
        g_wv[idx] = __float2bfloat16(Wv[idx]);
        g_wo[idx] = __float2bfloat16(Wo[idx]);
    }
    if (idx < D * MLP) {
        g_w1[idx] = __float2bfloat16(W1[idx]);
        g_w2[idx] = __float2bfloat16(W2[idx]);
    }
    if (idx < ND * 64) {
        int d = idx >> 6, c = idx & 63;
        float v = 0.f;
        if (c < 4)       v = a_pre[0]  * phi_pre[d * 4 + c];
        else if (c < 8)  v = a_post[0] * phi_post[d * 4 + (c - 4)];
        else if (c < 24) v = a_res[0]  * phi_res[d * 16 + (c - 8)];
        g_phiC[idx] = __float2bfloat16(v);
    }
    if (idx < 24) {
        float v;
        if (idx < 4)      v = b_pre[idx];
        else if (idx < 8) v = b_post[idx - 4];
        else              v = b_res[idx - 8];
        g_bias24[idx] = v;
    }
}

// =================================================================================
// Kernel 1: rmsnorm -> streams (bf16). One block (192 threads, float4 each) / token.
// =================================================================================
__global__ __launch_bounds__(192) void rms_kernel(
    const float* __restrict__ x, const float* __restrict__ norm_w)
{
    int tok = blockIdx.x, tid = threadIdx.x;
    int lane = tid & 31, wid = tid >> 5;
    __shared__ float red[6];
    __shared__ float s_inv;

    float4 xv = *(const float4*)(x + (size_t)tok * ND + tid * 4);
    float sq = xv.x * xv.x + xv.y * xv.y + xv.z * xv.z + xv.w * xv.w;
    #pragma unroll
    for (int o = 16; o; o >>= 1) sq += __shfl_xor_sync(~0u, sq, o);
    if (lane == 0) red[wid] = sq;
    __syncthreads();
    if (tid == 0) {
        float s = red[0] + red[1] + red[2] + red[3] + red[4] + red[5];
        s_inv = rsqrtf(s / (float)ND + 1e-8f);
    }
    __syncthreads();
    float inv = s_inv;
    float4 wv = *(const float4*)(norm_w + tid * 4);
    unsigned p0 = pack_bf16(xv.x * inv * wv.x, xv.y * inv * wv.y);
    unsigned p1 = pack_bf16(xv.z * inv * wv.z, xv.w * inv * wv.w);
    *(uint2*)((unsigned*)g_streams + (size_t)tok * (ND / 2) + tid * 2) = make_uint2(p0, p1);
}

// =================================================================================
// Kernel 2: bf16 tensor-core GEMM. BM=128 BN=64 BK=32, 256 threads, 8 warps.
// EPI: 0 plain->bf16, 1 +Res->f32, 2 gelu->bf16, 3 scatter out+=(acc+Res)*hpost,
//      4 tilde (f32, cols<24, +bias24)
// =================================================================================
template <int EPI>
__global__ __launch_bounds__(256) void gemm_bf(
    const bf16* __restrict__ A, const bf16* __restrict__ B,
    const float* __restrict__ Res, const float* __restrict__ hpost,
    void* __restrict__ Cv, int N, int K)
{
    __shared__ __align__(16) unsigned Asp[128][20];  // [m][kpair], (20g+tig) CF
    __shared__ __align__(16) unsigned Bsp[16][72];   // [kpair][n], (8tig+g) CF

    int tid = threadIdx.x;
    int wid = tid >> 5, lane = tid & 31;
    int g = lane >> 2, tig = lane & 3;
    int wm = wid & 3, wn = wid >> 2;     // 4 x 2 warp grid
    int bm = blockIdx.y, bn = blockIdx.x;

    float acc[2][4][4] = {};

    int ar = tid >> 1, acp = (tid & 1) * 8;           // A: row, pair-col base
    int bkp = tid >> 4, bc = (tid & 15) * 4;          // B: pair-row, col base

    for (int kb = 0; kb < K; kb += 32) {
        // A fill: direct pair copy (bf16 row-major => pairs contiguous)
        {
            const uint4* ap = (const uint4*)(A + (size_t)(bm * 128 + ar) * K + kb + acp * 2);
            *(uint4*)&Asp[ar][acp]     = ap[0];
            *(uint4*)&Asp[ar][acp + 4] = ap[1];
        }
        // B fill: interleave two k-rows into pairs
        {
            const bf16* b0p = B + (size_t)(kb + 2 * bkp) * N + bn * 64 + bc;
            uint2 r0 = *(const uint2*)b0p;
            uint2 r1 = *(const uint2*)(b0p + N);
            uint4 o;
            o.x = __byte_perm(r0.x, r1.x, 0x5410);
            o.y = __byte_perm(r0.x, r1.x, 0x7632);
            o.z = __byte_perm(r0.y, r1.y, 0x5410);
            o.w = __byte_perm(r0.y, r1.y, 0x7632);
            *(uint4*)&Bsp[bkp][bc] = o;
        }
        __syncthreads();

        #pragma unroll
        for (int ks = 0; ks < 2; ks++) {
            int kp0 = ks * 8;
            unsigned a[2][4], b[4][2];
            #pragma unroll
            for (int mt = 0; mt < 2; mt++) {
                int m0 = wm * 32 + mt * 16;
                a[mt][0] = Asp[m0 + g][kp0 + tig];
                a[mt][1] = Asp[m0 + g + 8][kp0 + tig];
                a[mt][2] = Asp[m0 + g][kp0 + tig + 4];
                a[mt][3] = Asp[m0 + g + 8][kp0 + tig + 4];
            }
            #pragma unroll
            for (int nt = 0; nt < 4; nt++) {
                int n0 = wn * 32 + nt * 8;
                b[nt][0] = Bsp[kp0 + tig][n0 + g];
                b[nt][1] = Bsp[kp0 + tig + 4][n0 + g];
            }
            #pragma unroll
            for (int mt = 0; mt < 2; mt++)
                #pragma unroll
                for (int nt = 0; nt < 4; nt++)
                    mma_bf16(acc[mt][nt], a[mt][0], a[mt][1], a[mt][2], a[mt][3],
                             b[nt][0], b[nt][1]);
        }
        __syncthreads();
    }

    #pragma unroll
    for (int mt = 0; mt < 2; mt++) {
        #pragma unroll
        for (int half = 0; half < 2; half++) {
            int row = bm * 128 + wm * 32 + mt * 16 + g + half * 8;
            #pragma unroll
            for (int nt = 0; nt < 4; nt++) {
                int col = bn * 64 + wn * 32 + nt * 8 + tig * 2;
                float v0 = acc[mt][nt][half * 2 + 0];
                float v1 = acc[mt][nt][half * 2 + 1];
                if (EPI == 0) {
                    bf16* C = (bf16*)Cv;
                    *(unsigned*)(C + (size_t)row * N + col) = pack_bf16(v0, v1);
                } else if (EPI == 1) {
                    float* C = (float*)Cv;
                    float2 r = *(const float2*)(Res + (size_t)row * N + col);
                    *(float2*)(C + (size_t)row * N + col) = make_float2(v0 + r.x, v1 + r.y);
                } else if (EPI == 2) {
                    bf16* C = (bf16*)Cv;
                    *(unsigned*)(C + (size_t)row * N + col) = pack_bf16(gelu_f(v0), gelu_f(v1));
                } else if (EPI == 3) {
                    float* C = (float*)Cv;
                    float2 r = *(const float2*)(Res + (size_t)row * N + col);
                    float vx = v0 + r.x, vy = v1 + r.y;
                    #pragma unroll
                    for (int s = 0; s < 4; s++) {
                        float hp = hpost[(size_t)row * 4 + s];
                        float* op = C + (size_t)row * ND + s * D + col;
                        float2 o = *(const float2*)op;
                        o.x += vx * hp; o.y += vy * hp;
                        *(float2*)op = o;
                    }
                } else { // EPI == 4: tilde (width 24), add bias24
                    if (wn == 0 && nt < 3) {
                        float* C = (float*)Cv;
                        float2 bv = *(const float2*)(g_bias24 + col);
                        *(float2*)(C + (size_t)row * 24 + col) = make_float2(v0 + bv.x, v1 + bv.y);
                    }
                }
            }
        }
    }
}

// =================================================================================
// Kernel 3: sinkhorn + stream mixing + fused LN1. 1 warp/token, 8 tokens/block.
// Reads tilde (bias included), x. Writes out(x_res), hpost, xin (f32), h (bf16, LN1'd)
// =================================================================================
__global__ __launch_bounds__(256) void sinkmix_kernel(
    const float* __restrict__ x,
    const float* __restrict__ ln1_w, const float* __restrict__ ln1_b,
    float* __restrict__ out, float* __restrict__ xin, float* __restrict__ hpost)
{
    __shared__ float sm_hres[8][16];
    __shared__ float sm_hpre[8][4];

    int wid = threadIdx.x >> 5, lane = threadIdx.x & 31;
    int tok = blockIdx.x * 8 + wid;

    float tl = (lane < 24) ? g_tilde[(size_t)tok * 24 + lane] : 0.f;

    if (lane >= 4 && lane < 8)
        hpost[(size_t)tok * 4 + (lane - 4)] = 2.f / (1.f + expf(-tl));
    if (lane < 4)
        sm_hpre[wid][lane] = 1.f / (1.f + expf(-tl));

    // sinkhorn on lanes 0..15 using tilde[8..23]
    {
        float v = __shfl_sync(~0u, tl, (lane & 15) + 8);
        if (lane >= 16) v = -1e30f;
        float m = v;
        #pragma unroll
        for (int o = 8; o; o >>= 1) m = fmaxf(m, __shfl_xor_sync(~0u, m, o));
        v = expf(v - m);
        #pragma unroll 1
        for (int it = 0; it < 20; it++) {
            float rs = v;
            rs += __shfl_xor_sync(~0u, rs, 1);
            rs += __shfl_xor_sync(~0u, rs, 2);
            v = v / (rs + 1e-8f);
            float cs = v;
            cs += __shfl_xor_sync(~0u, cs, 4);
            cs += __shfl_xor_sync(~0u, cs, 8);
            v = v / (cs + 1e-8f);
        }
        if (lane < 16) sm_hres[wid][lane] = v;
    }
    __syncwarp();

    float hr[16], hp[4];
    #pragma unroll
    for (int i = 0; i < 16; i++) hr[i] = sm_hres[wid][i];
    #pragma unroll
    for (int i = 0; i < 4; i++) hp[i] = sm_hpre[wid][i];

    const float* xrow = x + (size_t)tok * ND;
    float xi_c[6];
    float sum = 0.f, sumsq = 0.f;
    #pragma unroll
    for (int c = 0; c < 6; c++) {
        int dd = c * 32 + lane;
        float x0 = xrow[dd], x1 = xrow[D + dd], x2v = xrow[2 * D + dd], x3 = xrow[3 * D + dd];
        #pragma unroll
        for (int i = 0; i < 4; i++) {
            float r = hr[i * 4 + 0] * x0 + hr[i * 4 + 1] * x1
                    + hr[i * 4 + 2] * x2v + hr[i * 4 + 3] * x3;
            out[(size_t)tok * ND + i * D + dd] = r;
        }
        float xi = hp[0] * x0 + hp[1] * x1 + hp[2] * x2v + hp[3] * x3;
        xin[(size_t)tok * D + dd] = xi;
        xi_c[c] = xi;
        sum += xi; sumsq += xi * xi;
    }
    #pragma unroll
    for (int o = 16; o; o >>= 1) {
        sum += __shfl_xor_sync(~0u, sum, o);
        sumsq += __shfl_xor_sync(~0u, sumsq, o);
    }
    float mean = sum / (float)D;
    float var = sumsq / (float)D - mean * mean;
    float invstd = rsqrtf(var + 1e-5f);
    #pragma unroll
    for (int c = 0; c < 6; c++) {
        int dd = c * 32 + lane;
        float hv = (xi_c[c] - mean) * invstd * ln1_w[dd] + ln1_b[dd];
        g_h[(size_t)tok * D + dd] = __float2bfloat16(hv);
    }
}

// =================================================================================
// Kernel 4: LayerNorm (x2 f32 -> h bf16). One block (192 threads) per token.
// =================================================================================
__global__ __launch_bounds__(192) void ln2_kernel(
    const float* __restrict__ in, const float* __restrict__ w,
    const float* __restrict__ b)
{
    int tok = blockIdx.x, tid = threadIdx.x;
    int lane = tid & 31, wid = tid >> 5;
    __shared__ float red[6];
    __shared__ float s_mean, s_invstd;

    float v = in[(size_t)tok * D + tid];
    float sm = v;
    #pragma unroll
    for (int o = 16; o; o >>= 1) sm += __shfl_xor_sync(~0u, sm, o);
    if (lane == 0) red[wid] = sm;
    __syncthreads();
    if (tid == 0) {
        float s = red[0] + red[1] + red[2] + red[3] + red[4] + red[5];
        s_mean = s / (float)D;
    }
    __syncthreads();
    float dv = v - s_mean;
    float sq = dv * dv;
    #pragma unroll
    for (int o = 16; o; o >>= 1) sq += __shfl_xor_sync(~0u, sq, o);
    __syncthreads();
    if (lane == 0) red[wid] = sq;
    __syncthreads();
    if (tid == 0) {
        float s = red[0] + red[1] + red[2] + red[3] + red[4] + red[5];
        s_invstd = rsqrtf(s / (float)D + 1e-5f);
    }
    __syncthreads();
    g_h[(size_t)tok * D + tid] = __float2bfloat16(dv * s_invstd * w[tid] + b[tid]);
}

// =================================================================================
// Kernel 5: bf16 tensor-core flash attention. BQ=64, BKEY=32, HD=64, 4 warps.
// =================================================================================
__global__ __launch_bounds__(128) void flash_bf(
    const bf16* __restrict__ Q, const bf16* __restrict__ K,
    const bf16* __restrict__ V, bf16* __restrict__ O)
{
    __shared__ __align__(16) unsigned Qsp[64][36];  // [q][dpair]   (4g+tig) CF
    __shared__ __align__(16) unsigned Ksp[32][36];  // [key][dpair] (4g+tig) CF
    __shared__ __align__(16) unsigned Vp[16][72];   // [keypair][d] (8tig+g) CF
    __shared__ __align__(16) unsigned Pp[64][20];   // [q][keypair] (20g+tig) CF

    int tid = threadIdx.x, wid = tid >> 5, lane = tid & 31;
    int g = lane >> 2, tig = lane & 3;
    int qt = blockIdx.x, h = blockIdx.y, b = blockIdx.z;
    size_t base = ((size_t)b * T_SEQ) * D + h * HD;
    int m0 = wid * 16;

    // load Q tile (64 rows x 32 pairs)
    {
        int r = tid >> 1, cp0 = (tid & 1) * 16;
        const uint4* qp = (const uint4*)(Q + base + (size_t)(qt * 64 + r) * D + cp0 * 2);
        #pragma unroll
        for (int u = 0; u < 4; u++)
            *(uint4*)&Qsp[r][cp0 + u * 4] = qp[u];
    }
    float m_prev[2] = {-1e30f, -1e30f};
    float l_run[2] = {0.f, 0.f};
    float o_acc[8][4] = {};
    __syncthreads();

    for (int kt = 0; kt < T_SEQ; kt += 32) {
        // K tile: direct pair copy (pairs along d)
        {
            int r = tid >> 2, cp0 = (tid & 3) * 8;
            const uint4* kp = (const uint4*)(K + base + (size_t)(kt + r) * D + cp0 * 2);
            *(uint4*)&Ksp[r][cp0]     = kp[0];
            *(uint4*)&Ksp[r][cp0 + 4] = kp[1];
        }
        // V tile: interleave two key-rows into pairs along key
        {
            int kpi = tid >> 3, c0 = (tid & 7) * 8;
            const uint4* v0p = (const uint4*)(V + base + (size_t)(kt + 2 * kpi) * D + c0);
            uint4 r0 = v0p[0];
            uint4 r1 = *(const uint4*)(V + base + (size_t)(kt + 2 * kpi + 1) * D + c0);
            uint4 oA, oB;
            oA.x = __byte_perm(r0.x, r1.x, 0x5410); oA.y = __byte_perm(r0.x, r1.x, 0x7632);
            oA.z = __byte_perm(r0.y, r1.y, 0x5410); oA.w = __byte_perm(r0.y, r1.y, 0x7632);
            oB.x = __byte_perm(r0.z, r1.z, 0x5410); oB.y = __byte_perm(r0.z, r1.z, 0x7632);
            oB.z = __byte_perm(r0.w, r1.w, 0x5410); oB.w = __byte_perm(r0.w, r1.w, 0x7632);
            *(uint4*)&Vp[kpi][c0]     = oA;
            *(uint4*)&Vp[kpi][c0 + 4] = oB;
        }
        __syncthreads();

        // S = Q K^T (warp: 16 q-rows x 32 keys), k = 64 -> 4 ksteps of 16
        float s[4][4] = {};
        #pragma unroll
        for (int ks = 0; ks < 4; ks++) {
            int kp0 = ks * 8;
            unsigned a0 = Qsp[m0 + g][kp0 + tig];
            unsigned a1 = Qsp[m0 + g + 8][kp0 + tig];
            unsigned a2 = Qsp[m0 + g][kp0 + tig + 4];
            unsigned a3 = Qsp[m0 + g + 8][kp0 + tig + 4];
            #pragma unroll
            for (int nt = 0; nt < 4; nt++) {
                unsigned b0 = Ksp[nt * 8 + g][kp0 + tig];
                unsigned b1 = Ksp[nt * 8 + g][kp0 + tig + 4];
                mma_bf16(s[nt], a0, a1, a2, a3, b0, b1);
            }
        }

        // online softmax (quad rows; shfl_xor 1,2 reduce within row)
        const float sc = 0.125f;
        float mx0 = -1e30f, mx1 = -1e30f;
        #pragma unroll
        for (int nt = 0; nt < 4; nt++) {
            s[nt][0] *= sc; s[nt][1] *= sc; s[nt][2] *= sc; s[nt][3] *= sc;
            mx0 = fmaxf(mx0, fmaxf(s[nt][0], s[nt][1]));
            mx1 = fmaxf(mx1, fmaxf(s[nt][2], s[nt][3]));
        }
        mx0 = fmaxf(mx0, __shfl_xor_sync(~0u, mx0, 1));
        mx0 = fmaxf(mx0, __shfl_xor_sync(~0u, mx0, 2));
        mx1 = fmaxf(mx1, __shfl_xor_sync(~0u, mx1, 1));
        mx1 = fmaxf(mx1, __shfl_xor_sync(~0u, mx1, 2));
        float mn0 = fmaxf(m_prev[0], mx0);
        float mn1 = fmaxf(m_prev[1], mx1);
        float rs0 = 0.f, rs1 = 0.f;
        #pragma unroll
        for (int nt = 0; nt < 4; nt++) {
            s[nt][0] = __expf(s[nt][0] - mn0);
            s[nt][1] = __expf(s[nt][1] - mn0);
            s[nt][2] = __expf(s[nt][2] - mn1);
            s[nt][3] = __expf(s[nt][3] - mn1);
            rs0 += s[nt][0] + s[nt][1];
            rs1 += s[nt][2] + s[nt][3];
        }
        rs0 += __shfl_xor_sync(~0u, rs0, 1);
        rs0 += __shfl_xor_sync(~0u, rs0, 2);
        rs1 += __shfl_xor_sync(~0u, rs1, 1);
        rs1 += __shfl_xor_sync(~0u, rs1, 2);
        float scl0 = __expf(m_prev[0] - mn0);
        float scl1 = __expf(m_prev[1] - mn1);
        l_run[0] = l_run[0] * scl0 + rs0;
        l_run[1] = l_run[1] * scl1 + rs1;
        m_prev[0] = mn0; m_prev[1] = mn1;
        #pragma unroll
        for (int nt = 0; nt < 8; nt++) {
            o_acc[nt][0] *= scl0; o_acc[nt][1] *= scl0;
            o_acc[nt][2] *= scl1; o_acc[nt][3] *= scl1;
        }
        // stage P as bf16 pairs along key (thread owns adjacent cols 2tig,2tig+1)
        #pragma unroll
        for (int nt = 0; nt < 4; nt++) {
            Pp[m0 + g][nt * 4 + tig]     = pack_bf16(s[nt][0], s[nt][1]);
            Pp[m0 + g + 8][nt * 4 + tig] = pack_bf16(s[nt][2], s[nt][3]);
        }
        __syncthreads();

        // O += P V : key=32 -> 2 ksteps of 16
        #pragma unroll
        for (int ks = 0; ks < 2; ks++) {
            int kp0 = ks * 8;
            unsigned a0 = Pp[m0 + g][kp0 + tig];
            unsigned a1 = Pp[m0 + g + 8][kp0 + tig];
            unsigned a2 = Pp[m0 + g][kp0 + tig + 4];
            unsigned a3 = Pp[m0 + g + 8][kp0 + tig + 4];
            #pragma unroll
            for (int nt = 0; nt < 8; nt++) {
                unsigned b0 = Vp[kp0 + tig][nt * 8 + g];
                unsigned b1 = Vp[kp0 + tig + 4][nt * 8 + g];
                mma_bf16(o_acc[nt], a0, a1, a2, a3, b0, b1);
            }
        }
        __syncthreads();
    }

    float inv0 = 1.f / l_run[0];
    float inv1 = 1.f / l_run[1];
    int q0 = qt * 64 + m0 + g;
    #pragma unroll
    for (int nt = 0; nt < 8; nt++) {
        int col = nt * 8 + tig * 2;
        *(unsigned*)(O + base + (size_t)q0 * D + col) =
            pack_bf16(o_acc[nt][0] * inv0, o_acc[nt][1] * inv0);
        *(unsigned*)(O + base + (size_t)(q0 + 8) * D + col) =
            pack_bf16(o_acc[nt][2] * inv1, o_acc[nt][3] * inv1);
    }
}

// =================================================================================
extern "C" void kernel_launch(void* const* d_in, const int* in_sizes, int n_in,
                              void* d_out, int out_size)
{
    const float* x        = (const float*)d_in[0];
    const float* norm_w   = (const float*)d_in[1];
    const float* phi_pre  = (const float*)d_in[2];
    const float* phi_post = (const float*)d_in[3];
    const float* phi_res  = (const float*)d_in[4];
    const float* b_pre    = (const float*)d_in[5];
    const float* b_post   = (const float*)d_in[6];
    const float* b_res    = (const float*)d_in[7];
    const float* a_pre    = (const float*)d_in[8];
    const float* a_post   = (const float*)d_in[9];
    const float* a_res    = (const float*)d_in[10];
    const float* ln1_w    = (const float*)d_in[11];
    const float* ln1_b    = (const float*)d_in[12];
    const float* Wq       = (const float*)d_in[13];
    const float* Wk       = (const float*)d_in[14];
    const float* Wv       = (const float*)d_in[15];
    const float* Wo       = (const float*)d_in[16];
    const float* ln2_w    = (const float*)d_in[17];
    const float* ln2_b    = (const float*)d_in[18];
    const float* W1       = (const float*)d_in[19];
    const float* W2       = (const float*)d_in[20];
    float* out = (float*)d_out;

    void *p; 
    cudaGetSymbolAddress(&p, g_xin);     float* xin    = (float*)p;
    cudaGetSymbolAddress(&p, g_x2);      float* x2     = (float*)p;
    cudaGetSymbolAddress(&p, g_hpost);   float* hpost  = (float*)p;
    cudaGetSymbolAddress(&p, g_tilde);   float* tilde  = (float*)p;
    cudaGetSymbolAddress(&p, g_streams); bf16* streams = (bf16*)p;
    cudaGetSymbolAddress(&p, g_h);       bf16* h       = (bf16*)p;
    cudaGetSymbolAddress(&p, g_q);       bf16* q       = (bf16*)p;
    cudaGetSymbolAddress(&p, g_k);       bf16* k       = (bf16*)p;
    cudaGetSymbolAddress(&p, g_v);       bf16* v       = (bf16*)p;
    cudaGetSymbolAddress(&p, g_o);       bf16* o       = (bf16*)p;
    cudaGetSymbolAddress(&p, g_g);       bf16* gbuf    = (bf16*)p;
    cudaGetSymbolAddress(&p, g_wq);      bf16* wq      = (bf16*)p;
    cudaGetSymbolAddress(&p, g_wk);      bf16* wk      = (bf16*)p;
    cudaGetSymbolAddress(&p, g_wv);      bf16* wv      = (bf16*)p;
    cudaGetSymbolAddress(&p, g_wo);      bf16* wo      = (bf16*)p;
    cudaGetSymbolAddress(&p, g_w1);      bf16* w1      = (bf16*)p;
    cudaGetSymbolAddress(&p, g_w2);      bf16* w2      = (bf16*)p;
    cudaGetSymbolAddress(&p, g_phiC);    bf16* phiC    = (bf16*)p;

    // 0) weight conversion
    convert_kernel<<<576, 256>>>(Wq, Wk, Wv, Wo, W1, W2, phi_pre, phi_post, phi_res,
                                 b_pre, b_post, b_res, a_pre, a_post, a_res);
    // 1) rmsnorm -> streams bf16
    rms_kernel<<<BT, 192>>>(x, norm_w);
    // 2) projections -> tilde (+bias)
    gemm_bf<4><<<dim3(1, BT / 128), 256>>>(streams, phiC, nullptr, nullptr, tilde, 64, ND);
    // 3) sinkhorn + mix + LN1 -> out(x_res), xin, h, hpost
    sinkmix_kernel<<<BT / 8, 256>>>(x, ln1_w, ln1_b, out, xin, hpost);
    // 4) QKV
    dim3 g192(D / 64, BT / 128), g768(MLP / 64, BT / 128);
    gemm_bf<0><<<g192, 256>>>(h, wq, nullptr, nullptr, q, D, D);
    gemm_bf<0><<<g192, 256>>>(h, wk, nullptr, nullptr, k, D, D);
    gemm_bf<0><<<g192, 256>>>(h, wv, nullptr, nullptr, v, D, D);
    // 5) attention
    flash_bf<<<dim3(T_SEQ / 64, NH, NB), 128>>>(q, k, v, o);
    // 6) Wo + residual -> x2 (f32)
    gemm_bf<1><<<g192, 256>>>(o, wo, xin, nullptr, x2, D, D);
    // 7) LN2 -> h bf16
    ln2_kernel<<<BT, 192>>>(x2, ln2_w, ln2_b);
    // 8) MLP up + GELU -> g bf16
    gemm_bf<2><<<g768, 256>>>(h, w1, nullptr, nullptr, gbuf, MLP, D);
    // 9) MLP down + residual + fused gated scatter into out
    gemm_bf<3><<<g192, 256>>>(gbuf, w2, x2, hpost, out, D, MLP);
}

// round 8
// speedup vs baseline: 4.8379x; 1.0046x over previous
#include <cuda_runtime.h>
#include <cuda_bf16.h>
#include <math.h>

#define BT 32768
#define NSTREAM 4
#define D 192
#define ND 768
#define MLP 768
#define T_SEQ 1024
#define NB 32
#define NH 3
#define HD 64
#define QKVN 576

typedef __nv_bfloat16 bf16;

// ---------------- scratch (device globals; no allocation allowed) ----------------
__device__ float g_xin[BT * D];
__device__ float g_x2[BT * D];
__device__ float g_hpost[BT * NSTREAM];
__device__ float g_tilde[BT * 24];
__device__ float g_gates[BT * 20];       // 16 hres + 4 hpre per token
__device__ float g_bias24[24];
__device__ bf16  g_streams[BT * ND];
__device__ bf16  g_h[BT * D];
__device__ bf16  g_qkv[BT * QKVN];
__device__ bf16  g_o[BT * D];
__device__ bf16  g_g[BT * MLP];
__device__ bf16  g_wqkv[D * QKVN];
__device__ bf16  g_wo[D * D];
__device__ bf16  g_w1[D * MLP];
__device__ bf16  g_w2[MLP * D];
__device__ bf16  g_phiC[ND * 64];   // cols 0-3 pre*alpha, 4-7 post*alpha, 8-23 res*alpha, 24-63 zero

// ---------------- helpers ----------------
__device__ __forceinline__ unsigned pack_bf16(float lo, float hi) {
    unsigned r;
    asm("cvt.rn.bf16x2.f32 %0, %1, %2;" : "=r"(r) : "f"(hi), "f"(lo));
    return r;
}

__device__ __forceinline__ void mma_bf16(float c[4],
    unsigned a0, unsigned a1, unsigned a2, unsigned a3,
    unsigned b0, unsigned b1)
{
    asm volatile(
        "mma.sync.aligned.m16n8k16.row.col.f32.bf16.bf16.f32 "
        "{%0,%1,%2,%3}, {%4,%5,%6,%7}, {%8,%9}, {%0,%1,%2,%3};\n"
        : "+f"(c[0]), "+f"(c[1]), "+f"(c[2]), "+f"(c[3])
        : "r"(a0), "r"(a1), "r"(a2), "r"(a3), "r"(b0), "r"(b1));
}

__device__ __forceinline__ float gelu_f(float x) {
    float x3 = x * x * x;
    float t = tanhf(0.7978845608028654f * (x + 0.044715f * x3));
    return 0.5f * x * (1.f + t);
}

// =================================================================================
// Kernel 0: weight conversion fp32 -> bf16 (+ QKV concat, phi combine, bias24)
// =================================================================================
__global__ void convert_kernel(
    const float* __restrict__ Wq, const float* __restrict__ Wk,
    const float* __restrict__ Wv, const float* __restrict__ Wo,
    const float* __restrict__ W1, const float* __restrict__ W2,
    const float* __restrict__ phi_pre, const float* __restrict__ phi_post,
    const float* __restrict__ phi_res,
    const float* __restrict__ b_pre, const float* __restrict__ b_post,
    const float* __restrict__ b_res,
    const float* __restrict__ a_pre, const float* __restrict__ a_post,
    const float* __restrict__ a_res)
{
    int idx = blockIdx.x * blockDim.x + threadIdx.x;
    if (idx < D * QKVN) {
        int d = idx / QKVN, c = idx % QKVN;
        float v;
        if (c < D)           v = Wq[d * D + c];
        else if (c < 2 * D)  v = Wk[d * D + (c - D)];
        else                 v = Wv[d * D + (c - 2 * D)];
        g_wqkv[idx] = __float2bfloat16(v);
    }
    if (idx < D * D)
        g_wo[idx] = __float2bfloat16(Wo[idx]);
    if (idx < D * MLP) {
        g_w1[idx] = __float2bfloat16(W1[idx]);
        g_w2[idx] = __float2bfloat16(W2[idx]);
    }
    if (idx < ND * 64) {
        int d = idx >> 6, c = idx & 63;
        float v = 0.f;
        if (c < 4)       v = a_pre[0]  * phi_pre[d * 4 + c];
        else if (c < 8)  v = a_post[0] * phi_post[d * 4 + (c - 4)];
        else if (c < 24) v = a_res[0]  * phi_res[d * 16 + (c - 8)];
        g_phiC[idx] = __float2bfloat16(v);
    }
    if (idx < 24) {
        float v;
        if (idx < 4)      v = b_pre[idx];
        else if (idx < 8) v = b_post[idx - 4];
        else              v = b_res[idx - 8];
        g_bias24[idx] = v;
    }
}

// =================================================================================
// Kernel 1: rmsnorm -> streams (bf16). One block (192 threads, float4 each) / token.
// =================================================================================
__global__ __launch_bounds__(192) void rms_kernel(
    const float* __restrict__ x, const float* __restrict__ norm_w)
{
    int tok = blockIdx.x, tid = threadIdx.x;
    int lane = tid & 31, wid = tid >> 5;
    __shared__ float red[6];
    __shared__ float s_inv;

    float4 xv = *(const float4*)(x + (size_t)tok * ND + tid * 4);
    float sq = xv.x * xv.x + xv.y * xv.y + xv.z * xv.z + xv.w * xv.w;
    #pragma unroll
    for (int o = 16; o; o >>= 1) sq += __shfl_xor_sync(~0u, sq, o);
    if (lane == 0) red[wid] = sq;
    __syncthreads();
    if (tid == 0) {
        float s = red[0] + red[1] + red[2] + red[3] + red[4] + red[5];
        s_inv = rsqrtf(s / (float)ND + 1e-8f);
    }
    __syncthreads();
    float inv = s_inv;
    float4 wv = *(const float4*)(norm_w + tid * 4);
    unsigned p0 = pack_bf16(xv.x * inv * wv.x, xv.y * inv * wv.y);
    unsigned p1 = pack_bf16(xv.z * inv * wv.z, xv.w * inv * wv.w);
    *(uint2*)((unsigned*)g_streams + (size_t)tok * (ND / 2) + tid * 2) = make_uint2(p0, p1);
}

// =================================================================================
// Kernel 2: bf16 tensor-core GEMM. BM=128 BN=64 BK=32, 256 threads, 8 warps.
// EPI: 0 plain->bf16, 1 +Res->f32, 2 gelu->bf16, 3 scatter out+=(acc+Res)*hpost,
//      4 tilde (f32, cols<24, +bias24)
// =================================================================================
template <int EPI>
__global__ __launch_bounds__(256) void gemm_bf(
    const bf16* __restrict__ A, const bf16* __restrict__ B,
    const float* __restrict__ Res, const float* __restrict__ hpost,
    void* __restrict__ Cv, int N, int K)
{
    __shared__ __align__(16) unsigned Asp[128][20];  // [m][kpair], (20g+tig) CF
    __shared__ __align__(16) unsigned Bsp[16][72];   // [kpair][n], (8tig+g) CF

    int tid = threadIdx.x;
    int wid = tid >> 5, lane = tid & 31;
    int g = lane >> 2, tig = lane & 3;
    int wm = wid & 3, wn = wid >> 2;     // 4 x 2 warp grid
    int bm = blockIdx.y, bn = blockIdx.x;

    float acc[2][4][4] = {};

    int ar = tid >> 1, acp = (tid & 1) * 8;           // A: row, pair-col base
    int bkp = tid >> 4, bc = (tid & 15) * 4;          // B: pair-row, col base

    for (int kb = 0; kb < K; kb += 32) {
        {
            const uint4* ap = (const uint4*)(A + (size_t)(bm * 128 + ar) * K + kb + acp * 2);
            *(uint4*)&Asp[ar][acp]     = ap[0];
            *(uint4*)&Asp[ar][acp + 4] = ap[1];
        }
        {
            const bf16* b0p = B + (size_t)(kb + 2 * bkp) * N + bn * 64 + bc;
            uint2 r0 = *(const uint2*)b0p;
            uint2 r1 = *(const uint2*)(b0p + N);
            uint4 o;
            o.x = __byte_perm(r0.x, r1.x, 0x5410);
            o.y = __byte_perm(r0.x, r1.x, 0x7632);
            o.z = __byte_perm(r0.y, r1.y, 0x5410);
            o.w = __byte_perm(r0.y, r1.y, 0x7632);
            *(uint4*)&Bsp[bkp][bc] = o;
        }
        __syncthreads();

        #pragma unroll
        for (int ks = 0; ks < 2; ks++) {
            int kp0 = ks * 8;
            unsigned a[2][4], b[4][2];
            #pragma unroll
            for (int mt = 0; mt < 2; mt++) {
                int m0 = wm * 32 + mt * 16;
                a[mt][0] = Asp[m0 + g][kp0 + tig];
                a[mt][1] = Asp[m0 + g + 8][kp0 + tig];
                a[mt][2] = Asp[m0 + g][kp0 + tig + 4];
                a[mt][3] = Asp[m0 + g + 8][kp0 + tig + 4];
            }
            #pragma unroll
            for (int nt = 0; nt < 4; nt++) {
                int n0 = wn * 32 + nt * 8;
                b[nt][0] = Bsp[kp0 + tig][n0 + g];
                b[nt][1] = Bsp[kp0 + tig + 4][n0 + g];
            }
            #pragma unroll
            for (int mt = 0; mt < 2; mt++)
                #pragma unroll
                for (int nt = 0; nt < 4; nt++)
                    mma_bf16(acc[mt][nt], a[mt][0], a[mt][1], a[mt][2], a[mt][3],
                             b[nt][0], b[nt][1]);
        }
        __syncthreads();
    }

    #pragma unroll
    for (int mt = 0; mt < 2; mt++) {
        #pragma unroll
        for (int half = 0; half < 2; half++) {
            int row = bm * 128 + wm * 32 + mt * 16 + g + half * 8;
            #pragma unroll
            for (int nt = 0; nt < 4; nt++) {
                int col = bn * 64 + wn * 32 + nt * 8 + tig * 2;
                float v0 = acc[mt][nt][half * 2 + 0];
                float v1 = acc[mt][nt][half * 2 + 1];
                if (EPI == 0) {
                    bf16* C = (bf16*)Cv;
                    *(unsigned*)(C + (size_t)row * N + col) = pack_bf16(v0, v1);
                } else if (EPI == 1) {
                    float* C = (float*)Cv;
                    float2 r = *(const float2*)(Res + (size_t)row * N + col);
                    *(float2*)(C + (size_t)row * N + col) = make_float2(v0 + r.x, v1 + r.y);
                } else if (EPI == 2) {
                    bf16* C = (bf16*)Cv;
                    *(unsigned*)(C + (size_t)row * N + col) = pack_bf16(gelu_f(v0), gelu_f(v1));
                } else if (EPI == 3) {
                    float* C = (float*)Cv;
                    float2 r = *(const float2*)(Res + (size_t)row * N + col);
                    float vx = v0 + r.x, vy = v1 + r.y;
                    #pragma unroll
                    for (int s = 0; s < 4; s++) {
                        float hp = hpost[(size_t)row * 4 + s];
                        float* op = C + (size_t)row * ND + s * D + col;
                        float2 o = *(const float2*)op;
                        o.x += vx * hp; o.y += vy * hp;
                        *(float2*)op = o;
                    }
                } else { // EPI == 4: tilde (width 24), add bias24
                    if (wn == 0 && nt < 3) {
                        float* C = (float*)Cv;
                        float2 bv = *(const float2*)(g_bias24 + col);
                        *(float2*)(C + (size_t)row * 24 + col) = make_float2(v0 + bv.x, v1 + bv.y);
                    }
                }
            }
        }
    }
}

// =================================================================================
// Kernel 3a: gates kernel. 1 warp/token: sigmoid gates + sinkhorn. Tiny, latency-only.
// =================================================================================
__global__ __launch_bounds__(256) void gates_kernel(float* __restrict__ hpost)
{
    int wid = threadIdx.x >> 5, lane = threadIdx.x & 31;
    int tok = blockIdx.x * 8 + wid;

    float tl = (lane < 24) ? g_tilde[(size_t)tok * 24 + lane] : 0.f;

    if (lane >= 4 && lane < 8)
        hpost[(size_t)tok * 4 + (lane - 4)] = 2.f / (1.f + expf(-tl));
    float hpre_v = 1.f / (1.f + expf(-tl));

    float v = __shfl_sync(~0u, tl, (lane & 15) + 8);
    if (lane >= 16) v = -1e30f;
    float m = v;
    #pragma unroll
    for (int o = 8; o; o >>= 1) m = fmaxf(m, __shfl_xor_sync(~0u, m, o));
    v = expf(v - m);
    #pragma unroll 1
    for (int it = 0; it < 20; it++) {
        float rs = v;
        rs += __shfl_xor_sync(~0u, rs, 1);
        rs += __shfl_xor_sync(~0u, rs, 2);
        v = v / (rs + 1e-8f);
        float cs = v;
        cs += __shfl_xor_sync(~0u, cs, 4);
        cs += __shfl_xor_sync(~0u, cs, 8);
        v = v / (cs + 1e-8f);
    }
    if (lane < 16) g_gates[(size_t)tok * 20 + lane] = v;
    if (lane < 4)  g_gates[(size_t)tok * 20 + 16 + lane] = hpre_v;
}

// =================================================================================
// Kernel 3b: stream mixing + fused LN1 (pure streaming). 1 warp/token, 8 tok/block.
// =================================================================================
__global__ __launch_bounds__(256) void sinkmix_kernel(
    const float* __restrict__ x,
    const float* __restrict__ ln1_w, const float* __restrict__ ln1_b,
    float* __restrict__ out, float* __restrict__ xin)
{
    int wid = threadIdx.x >> 5, lane = threadIdx.x & 31;
    int tok = blockIdx.x * 8 + wid;

    float gv = (lane < 20) ? g_gates[(size_t)tok * 20 + lane] : 0.f;
    float hr[16], hp[4];
    #pragma unroll
    for (int i = 0; i < 16; i++) hr[i] = __shfl_sync(~0u, gv, i);
    #pragma unroll
    for (int i = 0; i < 4; i++) hp[i] = __shfl_sync(~0u, gv, 16 + i);

    const float* xrow = x + (size_t)tok * ND;
    float xi_c[6];
    float sum = 0.f, sumsq = 0.f;
    #pragma unroll
    for (int c = 0; c < 6; c++) {
        int dd = c * 32 + lane;
        float x0 = xrow[dd], x1 = xrow[D + dd], x2v = xrow[2 * D + dd], x3 = xrow[3 * D + dd];
        #pragma unroll
        for (int i = 0; i < 4; i++) {
            float r = hr[i * 4 + 0] * x0 + hr[i * 4 + 1] * x1
                    + hr[i * 4 + 2] * x2v + hr[i * 4 + 3] * x3;
            out[(size_t)tok * ND + i * D + dd] = r;
        }
        float xi = hp[0] * x0 + hp[1] * x1 + hp[2] * x2v + hp[3] * x3;
        xin[(size_t)tok * D + dd] = xi;
        xi_c[c] = xi;
        sum += xi; sumsq += xi * xi;
    }
    #pragma unroll
    for (int o = 16; o; o >>= 1) {
        sum += __shfl_xor_sync(~0u, sum, o);
        sumsq += __shfl_xor_sync(~0u, sumsq, o);
    }
    float mean = sum / (float)D;
    float var = sumsq / (float)D - mean * mean;
    float invstd = rsqrtf(var + 1e-5f);
    #pragma unroll
    for (int c = 0; c < 6; c++) {
        int dd = c * 32 + lane;
        float hv = (xi_c[c] - mean) * invstd * ln1_w[dd] + ln1_b[dd];
        g_h[(size_t)tok * D + dd] = __float2bfloat16(hv);
    }
}

// =================================================================================
// Kernel 4: LayerNorm (x2 f32 -> h bf16). One block (192 threads) per token.
// =================================================================================
__global__ __launch_bounds__(192) void ln2_kernel(
    const float* __restrict__ in, const float* __restrict__ w,
    const float* __restrict__ b)
{
    int tok = blockIdx.x, tid = threadIdx.x;
    int lane = tid & 31, wid = tid >> 5;
    __shared__ float red[6];
    __shared__ float s_mean, s_invstd;

    float v = in[(size_t)tok * D + tid];
    float sm = v;
    #pragma unroll
    for (int o = 16; o; o >>= 1) sm += __shfl_xor_sync(~0u, sm, o);
    if (lane == 0) red[wid] = sm;
    __syncthreads();
    if (tid == 0) {
        float s = red[0] + red[1] + red[2] + red[3] + red[4] + red[5];
        s_mean = s / (float)D;
    }
    __syncthreads();
    float dv = v - s_mean;
    float sq = dv * dv;
    #pragma unroll
    for (int o = 16; o; o >>= 1) sq += __shfl_xor_sync(~0u, sq, o);
    __syncthreads();
    if (lane == 0) red[wid] = sq;
    __syncthreads();
    if (tid == 0) {
        float s = red[0] + red[1] + red[2] + red[3] + red[4] + red[5];
        s_invstd = rsqrtf(s / (float)D + 1e-5f);
    }
    __syncthreads();
    g_h[(size_t)tok * D + tid] = __float2bfloat16(dv * s_invstd * w[tid] + b[tid]);
}

// =================================================================================
// Kernel 5: bf16 flash attention. BQ=128, BKEY=32, HD=64, 256 threads (8 warps).
// Reads fused QKV buffer [tok][576]: q at h*64, k at 192+h*64, v at 384+h*64.
// =================================================================================
__global__ __launch_bounds__(256, 2) void flash_bf(
    const bf16* __restrict__ QKV, bf16* __restrict__ O)
{
    __shared__ __align__(16) unsigned Qsp[128][36];  // [q][dpair]   (4g+tig) CF
    __shared__ __align__(16) unsigned Ksp[32][36];   // [key][dpair] (4g+tig) CF
    __shared__ __align__(16) unsigned Vp[16][72];    // [keypair][d] (8tig+g) CF
    __shared__ __align__(16) unsigned Pp[128][20];   // [q][keypair] (20g+tig) CF

    int tid = threadIdx.x, wid = tid >> 5, lane = tid & 31;
    int g = lane >> 2, tig = lane & 3;
    int qt = blockIdx.x, h = blockIdx.y, b = blockIdx.z;
    size_t tokbase = (size_t)b * T_SEQ;
    int qoff = h * HD, koff = D + h * HD, voff = 2 * D + h * HD;
    int m0 = wid * 16;

    // load Q tile (128 rows x 32 pairs)
    {
        int r = tid >> 1, cp0 = (tid & 1) * 16;
        const uint4* qp = (const uint4*)(QKV + (tokbase + qt * 128 + r) * QKVN + qoff + cp0 * 2);
        #pragma unroll
        for (int u = 0; u < 4; u++)
            *(uint4*)&Qsp[r][cp0 + u * 4] = qp[u];
    }
    float m_prev[2] = {-1e30f, -1e30f};
    float l_run[2] = {0.f, 0.f};
    float o_acc[8][4] = {};
    __syncthreads();

    for (int kt = 0; kt < T_SEQ; kt += 32) {
        // K tile: direct pair copy (pairs along d). 32 rows x 4 pairs each.
        {
            int r = tid >> 3, cp0 = (tid & 7) * 4;
            const uint4* kp = (const uint4*)(QKV + (tokbase + kt + r) * QKVN + koff + cp0 * 2);
            *(uint4*)&Ksp[r][cp0] = *kp;
        }
        // V tile: interleave two key-rows into pairs along key. 16 pair-rows x 4 cols.
        {
            int kpi = tid >> 4, c0 = (tid & 15) * 4;
            const bf16* vb = QKV + (tokbase + kt + 2 * kpi) * QKVN + voff + c0;
            uint2 r0 = *(const uint2*)vb;
            uint2 r1 = *(const uint2*)(vb + QKVN);
            uint4 o;
            o.x = __byte_perm(r0.x, r1.x, 0x5410); o.y = __byte_perm(r0.x, r1.x, 0x7632);
            o.z = __byte_perm(r0.y, r1.y, 0x5410); o.w = __byte_perm(r0.y, r1.y, 0x7632);
            *(uint4*)&Vp[kpi][c0] = o;
        }
        __syncthreads();

        // S = Q K^T (warp: 16 q-rows x 32 keys), d=64 -> 4 ksteps of 16
        float s[4][4] = {};
        #pragma unroll
        for (int ks = 0; ks < 4; ks++) {
            int kp0 = ks * 8;
            unsigned a0 = Qsp[m0 + g][kp0 + tig];
            unsigned a1 = Qsp[m0 + g + 8][kp0 + tig];
            unsigned a2 = Qsp[m0 + g][kp0 + tig + 4];
            unsigned a3 = Qsp[m0 + g + 8][kp0 + tig + 4];
            #pragma unroll
            for (int nt = 0; nt < 4; nt++) {
                unsigned b0 = Ksp[nt * 8 + g][kp0 + tig];
                unsigned b1 = Ksp[nt * 8 + g][kp0 + tig + 4];
                mma_bf16(s[nt], a0, a1, a2, a3, b0, b1);
            }
        }

        // online softmax (quad rows; shfl_xor 1,2 reduce within row)
        const float sc = 0.125f;
        float mx0 = -1e30f, mx1 = -1e30f;
        #pragma unroll
        for (int nt = 0; nt < 4; nt++) {
            s[nt][0] *= sc; s[nt][1] *= sc; s[nt][2] *= sc; s[nt][3] *= sc;
            mx0 = fmaxf(mx0, fmaxf(s[nt][0], s[nt][1]));
            mx1 = fmaxf(mx1, fmaxf(s[nt][2], s[nt][3]));
        }
        mx0 = fmaxf(mx0, __shfl_xor_sync(~0u, mx0, 1));
        mx0 = fmaxf(mx0, __shfl_xor_sync(~0u, mx0, 2));
        mx1 = fmaxf(mx1, __shfl_xor_sync(~0u, mx1, 1));
        mx1 = fmaxf(mx1, __shfl_xor_sync(~0u, mx1, 2));
        float mn0 = fmaxf(m_prev[0], mx0);
        float mn1 = fmaxf(m_prev[1], mx1);
        float rs0 = 0.f, rs1 = 0.f;
        #pragma unroll
        for (int nt = 0; nt < 4; nt++) {
            s[nt][0] = __expf(s[nt][0] - mn0);
            s[nt][1] = __expf(s[nt][1] - mn0);
            s[nt][2] = __expf(s[nt][2] - mn1);
            s[nt][3] = __expf(s[nt][3] - mn1);
            rs0 += s[nt][0] + s[nt][1];
            rs1 += s[nt][2] + s[nt][3];
        }
        rs0 += __shfl_xor_sync(~0u, rs0, 1);
        rs0 += __shfl_xor_sync(~0u, rs0, 2);
        rs1 += __shfl_xor_sync(~0u, rs1, 1);
        rs1 += __shfl_xor_sync(~0u, rs1, 2);
        float scl0 = __expf(m_prev[0] - mn0);
        float scl1 = __expf(m_prev[1] - mn1);
        l_run[0] = l_run[0] * scl0 + rs0;
        l_run[1] = l_run[1] * scl1 + rs1;
        m_prev[0] = mn0; m_prev[1] = mn1;
        #pragma unroll
        for (int nt = 0; nt < 8; nt++) {
            o_acc[nt][0] *= scl0; o_acc[nt][1] *= scl0;
            o_acc[nt][2] *= scl1; o_acc[nt][3] *= scl1;
        }
        // stage P as bf16 pairs along key (warp-private rows -> warp sync only)
        #pragma unroll
        for (int nt = 0; nt < 4; nt++) {
            Pp[m0 + g][nt * 4 + tig]     = pack_bf16(s[nt][0], s[nt][1]);
            Pp[m0 + g + 8][nt * 4 + tig] = pack_bf16(s[nt][2], s[nt][3]);
        }
        __syncwarp();

        // O += P V : key=32 -> 2 ksteps of 16
        #pragma unroll
        for (int ks = 0; ks < 2; ks++) {
            int kp0 = ks * 8;
            unsigned a0 = Pp[m0 + g][kp0 + tig];
            unsigned a1 = Pp[m0 + g + 8][kp0 + tig];
            unsigned a2 = Pp[m0 + g][kp0 + tig + 4];
            unsigned a3 = Pp[m0 + g + 8][kp0 + tig + 4];
            #pragma unroll
            for (int nt = 0; nt < 8; nt++) {
                unsigned b0 = Vp[kp0 + tig][nt * 8 + g];
                unsigned b1 = Vp[kp0 + tig + 4][nt * 8 + g];
                mma_bf16(o_acc[nt], a0, a1, a2, a3, b0, b1);
            }
        }
        __syncthreads();
    }

    float inv0 = 1.f / l_run[0];
    float inv1 = 1.f / l_run[1];
    size_t obase = tokbase * D + h * HD;
    int q0 = qt * 128 + m0 + g;
    #pragma unroll
    for (int nt = 0; nt < 8; nt++) {
        int col = nt * 8 + tig * 2;
        *(unsigned*)(O + obase + (size_t)q0 * D + col) =
            pack_bf16(o_acc[nt][0] * inv0, o_acc[nt][1] * inv0);
        *(unsigned*)(O + obase + (size_t)(q0 + 8) * D + col) =
            pack_bf16(o_acc[nt][2] * inv1, o_acc[nt][3] * inv1);
    }
}

// =================================================================================
extern "C" void kernel_launch(void* const* d_in, const int* in_sizes, int n_in,
                              void* d_out, int out_size)
{
    const float* x        = (const float*)d_in[0];
    const float* norm_w   = (const float*)d_in[1];
    const float* phi_pre  = (const float*)d_in[2];
    const float* phi_post = (const float*)d_in[3];
    const float* phi_res  = (const float*)d_in[4];
    const float* b_pre    = (const float*)d_in[5];
    const float* b_post   = (const float*)d_in[6];
    const float* b_res    = (const float*)d_in[7];
    const float* a_pre    = (const float*)d_in[8];
    const float* a_post   = (const float*)d_in[9];
    const float* a_res    = (const float*)d_in[10];
    const float* ln1_w    = (const float*)d_in[11];
    const float* ln1_b    = (const float*)d_in[12];
    const float* Wq       = (const float*)d_in[13];
    const float* Wk       = (const float*)d_in[14];
    const float* Wv       = (const float*)d_in[15];
    const float* Wo       = (const float*)d_in[16];
    const float* ln2_w    = (const float*)d_in[17];
    const float* ln2_b    = (const float*)d_in[18];
    const float* W1       = (const float*)d_in[19];
    const float* W2       = (const float*)d_in[20];
    float* out = (float*)d_out;

    void *p;
    cudaGetSymbolAddress(&p, g_xin);     float* xin    = (float*)p;
    cudaGetSymbolAddress(&p, g_x2);      float* x2     = (float*)p;
    cudaGetSymbolAddress(&p, g_hpost);   float* hpost  = (float*)p;
    cudaGetSymbolAddress(&p, g_tilde);   float* tilde  = (float*)p;
    cudaGetSymbolAddress(&p, g_streams); bf16* streams = (bf16*)p;
    cudaGetSymbolAddress(&p, g_h);       bf16* h       = (bf16*)p;
    cudaGetSymbolAddress(&p, g_qkv);     bf16* qkv     = (bf16*)p;
    cudaGetSymbolAddress(&p, g_o);       bf16* o       = (bf16*)p;
    cudaGetSymbolAddress(&p, g_g);       bf16* gbuf    = (bf16*)p;
    cudaGetSymbolAddress(&p, g_wqkv);    bf16* wqkv    = (bf16*)p;
    cudaGetSymbolAddress(&p, g_wo);      bf16* wo      = (bf16*)p;
    cudaGetSymbolAddress(&p, g_w1);      bf16* w1      = (bf16*)p;
    cudaGetSymbolAddress(&p, g_w2);      bf16* w2      = (bf16*)p;
    cudaGetSymbolAddress(&p, g_phiC);    bf16* phiC    = (bf16*)p;

    // 0) weight conversion
    convert_kernel<<<576, 256>>>(Wq, Wk, Wv, Wo, W1, W2, phi_pre, phi_post, phi_res,
                                 b_pre, b_post, b_res, a_pre, a_post, a_res);
    // 1) rmsnorm -> streams bf16
    rms_kernel<<<BT, 192>>>(x, norm_w);
    // 2) projections -> tilde (+bias)
    gemm_bf<4><<<dim3(1, BT / 128), 256>>>(streams, phiC, nullptr, nullptr, tilde, 64, ND);
    // 3a) sigmoid + sinkhorn -> gates, hpost
    gates_kernel<<<BT / 8, 256>>>(hpost);
    // 3b) mix + LN1 -> out(x_res), xin, h
    sinkmix_kernel<<<BT / 8, 256>>>(x, ln1_w, ln1_b, out, xin);
    // 4) fused QKV
    dim3 g192(D / 64, BT / 128), g576(QKVN / 64, BT / 128), g768(MLP / 64, BT / 128);
    gemm_bf<0><<<g576, 256>>>(h, wqkv, nullptr, nullptr, qkv, QKVN, D);
    // 5) attention
    flash_bf<<<dim3(T_SEQ / 128, NH, NB), 256>>>(qkv, o);
    // 6) Wo + residual -> x2 (f32)
    gemm_bf<1><<<g192, 256>>>(o, wo, xin, nullptr, x2, D, D);
    // 7) LN2 -> h bf16
    ln2_kernel<<<BT, 192>>>(x2, ln2_w, ln2_b);
    // 8) MLP up + GELU -> g bf16
    gemm_bf<2><<<g768, 256>>>(h, w1, nullptr, nullptr, gbuf, MLP, D);
    // 9) MLP down + residual + fused gated scatter into out
    gemm_bf<3><<<g192, 256>>>(gbuf, w2, x2, hpost, out, D, MLP);
}

// round 9
// speedup vs baseline: 6.1153x; 1.2640x over previous
#include <cuda_runtime.h>
#include <cuda_bf16.h>
#include <math.h>

#define BT 32768
#define NSTREAM 4
#define D 192
#define ND 768
#define MLP 768
#define T_SEQ 1024
#define NB 32
#define NH 3
#define HD 64
#define QKVN 576

typedef __nv_bfloat16 bf16;

// ---------------- scratch (device globals; no allocation allowed) ----------------
__device__ float g_xin[BT * D];
__device__ float g_x2[BT * D];
__device__ float g_hpost[BT * NSTREAM];
__device__ float g_tilde[BT * 24];
__device__ float g_gates[BT * 20];       // 16 hres + 4 hpre per token
__device__ float g_bias24[24];
__device__ bf16  g_streams[BT * ND];
__device__ bf16  g_h[BT * D];
__device__ bf16  g_qkv[BT * QKVN];
__device__ bf16  g_o[BT * D];
__device__ bf16  g_g[BT * MLP];
// k-pair-interleaved weights: W_p[kp][n] = pack(W[2kp][n], W[2kp+1][n])
__device__ unsigned g_wqkv_p[(D / 2) * QKVN];
__device__ unsigned g_wo_p[(D / 2) * D];
__device__ unsigned g_w1_p[(D / 2) * MLP];
__device__ unsigned g_w2_p[(MLP / 2) * D];
__device__ unsigned g_phiC_p[(ND / 2) * 64];

// ---------------- helpers ----------------
__device__ __forceinline__ unsigned pack_bf16(float lo, float hi) {
    unsigned r;
    asm("cvt.rn.bf16x2.f32 %0, %1, %2;" : "=r"(r) : "f"(hi), "f"(lo));
    return r;
}

__device__ __forceinline__ void mma_bf16(float c[4],
    unsigned a0, unsigned a1, unsigned a2, unsigned a3,
    unsigned b0, unsigned b1)
{
    asm volatile(
        "mma.sync.aligned.m16n8k16.row.col.f32.bf16.bf16.f32 "
        "{%0,%1,%2,%3}, {%4,%5,%6,%7}, {%8,%9}, {%0,%1,%2,%3};\n"
        : "+f"(c[0]), "+f"(c[1]), "+f"(c[2]), "+f"(c[3])
        : "r"(a0), "r"(a1), "r"(a2), "r"(a3), "r"(b0), "r"(b1));
}

__device__ __forceinline__ void cp16(void* smem, const void* g) {
    unsigned saddr = (unsigned)__cvta_generic_to_shared(smem);
    asm volatile("cp.async.cg.shared.global [%0], [%1], 16;\n" :: "r"(saddr), "l"(g));
}
#define CP_COMMIT() asm volatile("cp.async.commit_group;\n" ::: "memory")

__device__ __forceinline__ float frcp(float x) {
    float r;
    asm("rcp.approx.f32 %0, %1;" : "=f"(r) : "f"(x));
    return r;
}

__device__ __forceinline__ float gelu_f(float x) {
    float x3 = x * x * x;
    float t = tanhf(0.7978845608028654f * (x + 0.044715f * x3));
    return 0.5f * x * (1.f + t);
}

// =================================================================================
// Kernel 0: weight conversion fp32 -> bf16 k-pair-interleaved (+ phi combine, bias24)
// =================================================================================
__global__ void convert_kernel(
    const float* __restrict__ Wq, const float* __restrict__ Wk,
    const float* __restrict__ Wv, const float* __restrict__ Wo,
    const float* __restrict__ W1, const float* __restrict__ W2,
    const float* __restrict__ phi_pre, const float* __restrict__ phi_post,
    const float* __restrict__ phi_res,
    const float* __restrict__ b_pre, const float* __restrict__ b_post,
    const float* __restrict__ b_res,
    const float* __restrict__ a_pre, const float* __restrict__ a_post,
    const float* __restrict__ a_res)
{
    int idx = blockIdx.x * blockDim.x + threadIdx.x;
    // wqkv: KP=96, N=576
    if (idx < (D / 2) * QKVN) {
        int kp = idx / QKVN, c = idx % QKVN;
        const float* W; int cc;
        if (c < D)          { W = Wq; cc = c; }
        else if (c < 2 * D) { W = Wk; cc = c - D; }
        else                { W = Wv; cc = c - 2 * D; }
        g_wqkv_p[idx] = pack_bf16(W[(2 * kp) * D + cc], W[(2 * kp + 1) * D + cc]);
    }
    if (idx < (D / 2) * D) {
        int kp = idx / D, c = idx % D;
        g_wo_p[idx] = pack_bf16(Wo[(2 * kp) * D + c], Wo[(2 * kp + 1) * D + c]);
    }
    if (idx < (D / 2) * MLP) {
        int kp = idx / MLP, c = idx % MLP;
        g_w1_p[idx] = pack_bf16(W1[(2 * kp) * MLP + c], W1[(2 * kp + 1) * MLP + c]);
    }
    if (idx < (MLP / 2) * D) {
        int kp = idx / D, c = idx % D;
        g_w2_p[idx] = pack_bf16(W2[(2 * kp) * D + c], W2[(2 * kp + 1) * D + c]);
    }
    if (idx < (ND / 2) * 64) {
        int kp = idx >> 6, c = idx & 63;
        float v[2];
        #pragma unroll
        for (int u = 0; u < 2; u++) {
            int d = 2 * kp + u;
            float t = 0.f;
            if (c < 4)       t = a_pre[0]  * phi_pre[d * 4 + c];
            else if (c < 8)  t = a_post[0] * phi_post[d * 4 + (c - 4)];
            else if (c < 24) t = a_res[0]  * phi_res[d * 16 + (c - 8)];
            v[u] = t;
        }
        g_phiC_p[idx] = pack_bf16(v[0], v[1]);
    }
    if (idx < 24) {
        float v;
        if (idx < 4)      v = b_pre[idx];
        else if (idx < 8) v = b_post[idx - 4];
        else              v = b_res[idx - 8];
        g_bias24[idx] = v;
    }
}

// =================================================================================
// Kernel 1: rmsnorm -> streams (bf16). One block (192 threads, float4 each) / token.
// =================================================================================
__global__ __launch_bounds__(192) void rms_kernel(
    const float* __restrict__ x, const float* __restrict__ norm_w)
{
    int tok = blockIdx.x, tid = threadIdx.x;
    int lane = tid & 31, wid = tid >> 5;
    __shared__ float red[6];
    __shared__ float s_inv;

    float4 xv = *(const float4*)(x + (size_t)tok * ND + tid * 4);
    float sq = xv.x * xv.x + xv.y * xv.y + xv.z * xv.z + xv.w * xv.w;
    #pragma unroll
    for (int o = 16; o; o >>= 1) sq += __shfl_xor_sync(~0u, sq, o);
    if (lane == 0) red[wid] = sq;
    __syncthreads();
    if (tid == 0) {
        float s = red[0] + red[1] + red[2] + red[3] + red[4] + red[5];
        s_inv = rsqrtf(s / (float)ND + 1e-8f);
    }
    __syncthreads();
    float inv = s_inv;
    float4 wv = *(const float4*)(norm_w + tid * 4);
    unsigned p0 = pack_bf16(xv.x * inv * wv.x, xv.y * inv * wv.y);
    unsigned p1 = pack_bf16(xv.z * inv * wv.z, xv.w * inv * wv.w);
    *(uint2*)((unsigned*)g_streams + (size_t)tok * (ND / 2) + tid * 2) = make_uint2(p0, p1);
}

// =================================================================================
// Kernel 2: bf16 tensor-core GEMM, cp.async 2-stage pipeline.
// BM=128 BN=64 BK=32, 256 threads, 8 warps. B passed pre-interleaved (k-pairs).
// EPI: 0 plain->bf16, 1 +Res->f32, 2 gelu->bf16, 3 scatter out+=(acc+Res)*hpost,
//      4 tilde (f32, cols<24, +bias24)
// =================================================================================
template <int EPI>
__global__ __launch_bounds__(256) void gemm_bf(
    const bf16* __restrict__ A, const unsigned* __restrict__ Bp,
    const float* __restrict__ Res, const float* __restrict__ hpost,
    void* __restrict__ Cv, int N, int K)
{
    __shared__ __align__(16) unsigned Asp[2][128][20];  // [m][kpair], (20g+tig) CF
    __shared__ __align__(16) unsigned Bsp[2][16][72];   // [kpair][n], (8tig+g) CF

    int tid = threadIdx.x;
    int wid = tid >> 5, lane = tid & 31;
    int g = lane >> 2, tig = lane & 3;
    int wm = wid & 3, wn = wid >> 2;     // 4 x 2 warp grid
    int bm = blockIdx.y, bn = blockIdx.x;

    float acc[2][4][4] = {};

    int ar = tid >> 1, acp = (tid & 1) * 8;   // A: row, pair-col base
    int bkp = tid >> 4, bc = (tid & 15) * 4;  // B: pair-row, col base

    const bf16* Abase = A + (size_t)(bm * 128 + ar) * K + acp * 2;
    const unsigned* Bbase = Bp + (size_t)bkp * N + bn * 64 + bc;

    // prefetch stage 0
    cp16(&Asp[0][ar][acp],     Abase);
    cp16(&Asp[0][ar][acp + 4], Abase + 8);
    cp16(&Bsp[0][bkp][bc],     Bbase);
    CP_COMMIT();

    int nk = K >> 5;
    for (int it = 0; it < nk; it++) {
        if (it + 1 < nk) {
            int st = (it + 1) & 1;
            cp16(&Asp[st][ar][acp],     Abase + (it + 1) * 32);
            cp16(&Asp[st][ar][acp + 4], Abase + (it + 1) * 32 + 8);
            cp16(&Bsp[st][bkp][bc],     Bbase + (size_t)16 * (it + 1) * N);
            CP_COMMIT();
            asm volatile("cp.async.wait_group 1;\n" ::: "memory");
        } else {
            asm volatile("cp.async.wait_group 0;\n" ::: "memory");
        }
        __syncthreads();

        const unsigned (*As)[20] = Asp[it & 1];
        const unsigned (*Bs)[72] = Bsp[it & 1];
        #pragma unroll
        for (int ks = 0; ks < 2; ks++) {
            int kp0 = ks * 8;
            unsigned a[2][4], b[4][2];
            #pragma unroll
            for (int mt = 0; mt < 2; mt++) {
                int m0 = wm * 32 + mt * 16;
                a[mt][0] = As[m0 + g][kp0 + tig];
                a[mt][1] = As[m0 + g + 8][kp0 + tig];
                a[mt][2] = As[m0 + g][kp0 + tig + 4];
                a[mt][3] = As[m0 + g + 8][kp0 + tig + 4];
            }
            #pragma unroll
            for (int nt = 0; nt < 4; nt++) {
                int n0 = wn * 32 + nt * 8;
                b[nt][0] = Bs[kp0 + tig][n0 + g];
                b[nt][1] = Bs[kp0 + tig + 4][n0 + g];
            }
            #pragma unroll
            for (int mt = 0; mt < 2; mt++)
                #pragma unroll
                for (int nt = 0; nt < 4; nt++)
                    mma_bf16(acc[mt][nt], a[mt][0], a[mt][1], a[mt][2], a[mt][3],
                             b[nt][0], b[nt][1]);
        }
        __syncthreads();
    }

    #pragma unroll
    for (int mt = 0; mt < 2; mt++) {
        #pragma unroll
        for (int half = 0; half < 2; half++) {
            int row = bm * 128 + wm * 32 + mt * 16 + g + half * 8;
            #pragma unroll
            for (int nt = 0; nt < 4; nt++) {
                int col = bn * 64 + wn * 32 + nt * 8 + tig * 2;
                float v0 = acc[mt][nt][half * 2 + 0];
                float v1 = acc[mt][nt][half * 2 + 1];
                if (EPI == 0) {
                    bf16* C = (bf16*)Cv;
                    *(unsigned*)(C + (size_t)row * N + col) = pack_bf16(v0, v1);
                } else if (EPI == 1) {
                    float* C = (float*)Cv;
                    float2 r = *(const float2*)(Res + (size_t)row * N + col);
                    *(float2*)(C + (size_t)row * N + col) = make_float2(v0 + r.x, v1 + r.y);
                } else if (EPI == 2) {
                    bf16* C = (bf16*)Cv;
                    *(unsigned*)(C + (size_t)row * N + col) = pack_bf16(gelu_f(v0), gelu_f(v1));
                } else if (EPI == 3) {
                    float* C = (float*)Cv;
                    float2 r = *(const float2*)(Res + (size_t)row * N + col);
                    float vx = v0 + r.x, vy = v1 + r.y;
                    #pragma unroll
                    for (int s = 0; s < 4; s++) {
                        float hp = hpost[(size_t)row * 4 + s];
                        float* op = C + (size_t)row * ND + s * D + col;
                        float2 o = *(const float2*)op;
                        o.x += vx * hp; o.y += vy * hp;
                        *(float2*)op = o;
                    }
                } else { // EPI == 4: tilde (width 24), add bias24
                    if (wn == 0 && nt < 3) {
                        float* C = (float*)Cv;
                        float2 bv = *(const float2*)(g_bias24 + col);
                        *(float2*)(C + (size_t)row * 24 + col) = make_float2(v0 + bv.x, v1 + bv.y);
                    }
                }
            }
        }
    }
}

// =================================================================================
// Kernel 3a: gates kernel. ONE THREAD per token: sigmoid gates + 4x4 sinkhorn in regs.
// =================================================================================
__global__ __launch_bounds__(256) void gates_kernel(float* __restrict__ hpost)
{
    __shared__ float sm[256 * 25];
    int tid = threadIdx.x;
    size_t b0 = (size_t)blockIdx.x * 256;

    // coalesced load + transpose (stride-25 banks conflict-free)
    for (int i = tid; i < 256 * 24; i += 256) {
        int t = i / 24, e = i - t * 24;
        sm[t * 25 + e] = g_tilde[b0 * 24 + i];
    }
    __syncthreads();

    size_t tok = b0 + tid;
    const float* tl = &sm[tid * 25];

    float hp[4];
    #pragma unroll
    for (int j = 0; j < 4; j++) hp[j] = frcp(1.f + __expf(-tl[j]));
    float4 hp4;
    hp4.x = 2.f * frcp(1.f + __expf(-tl[4]));
    hp4.y = 2.f * frcp(1.f + __expf(-tl[5]));
    hp4.z = 2.f * frcp(1.f + __expf(-tl[6]));
    hp4.w = 2.f * frcp(1.f + __expf(-tl[7]));
    *(float4*)(hpost + tok * 4) = hp4;

    // sinkhorn on tl[8..23], all in registers
    float m[16];
    float mx = tl[8];
    #pragma unroll
    for (int j = 1; j < 16; j++) mx = fmaxf(mx, tl[8 + j]);
    #pragma unroll
    for (int j = 0; j < 16; j++) m[j] = __expf(tl[8 + j] - mx);

    #pragma unroll 1
    for (int it = 0; it < 20; it++) {
        #pragma unroll
        for (int i = 0; i < 4; i++) {
            float rs = m[4 * i] + m[4 * i + 1] + m[4 * i + 2] + m[4 * i + 3];
            float inv = frcp(rs + 1e-8f);
            m[4 * i] *= inv; m[4 * i + 1] *= inv; m[4 * i + 2] *= inv; m[4 * i + 3] *= inv;
        }
        #pragma unroll
        for (int j = 0; j < 4; j++) {
            float cs = m[j] + m[4 + j] + m[8 + j] + m[12 + j];
            float inv = frcp(cs + 1e-8f);
            m[j] *= inv; m[4 + j] *= inv; m[8 + j] *= inv; m[12 + j] *= inv;
        }
    }

    float* gp = g_gates + tok * 20;
    *(float4*)(gp + 0)  = make_float4(m[0], m[1], m[2], m[3]);
    *(float4*)(gp + 4)  = make_float4(m[4], m[5], m[6], m[7]);
    *(float4*)(gp + 8)  = make_float4(m[8], m[9], m[10], m[11]);
    *(float4*)(gp + 12) = make_float4(m[12], m[13], m[14], m[15]);
    *(float4*)(gp + 16) = make_float4(hp[0], hp[1], hp[2], hp[3]);
}

// =================================================================================
// Kernel 3b: stream mixing + fused LN1 (pure streaming). 1 warp/token, 8 tok/block.
// =================================================================================
__global__ __launch_bounds__(256) void sinkmix_kernel(
    const float* __restrict__ x,
    const float* __restrict__ ln1_w, const float* __restrict__ ln1_b,
    float* __restrict__ out, float* __restrict__ xin)
{
    int wid = threadIdx.x >> 5, lane = threadIdx.x & 31;
    int tok = blockIdx.x * 8 + wid;

    float gv = (lane < 20) ? g_gates[(size_t)tok * 20 + lane] : 0.f;
    float hr[16], hp[4];
    #pragma unroll
    for (int i = 0; i < 16; i++) hr[i] = __shfl_sync(~0u, gv, i);
    #pragma unroll
    for (int i = 0; i < 4; i++) hp[i] = __shfl_sync(~0u, gv, 16 + i);

    const float* xrow = x + (size_t)tok * ND;
    float xi_c[6];
    float sum = 0.f, sumsq = 0.f;
    #pragma unroll
    for (int c = 0; c < 6; c++) {
        int dd = c * 32 + lane;
        float x0 = xrow[dd], x1 = xrow[D + dd], x2v = xrow[2 * D + dd], x3 = xrow[3 * D + dd];
        #pragma unroll
        for (int i = 0; i < 4; i++) {
            float r = hr[i * 4 + 0] * x0 + hr[i * 4 + 1] * x1
                    + hr[i * 4 + 2] * x2v + hr[i * 4 + 3] * x3;
            out[(size_t)tok * ND + i * D + dd] = r;
        }
        float xi = hp[0] * x0 + hp[1] * x1 + hp[2] * x2v + hp[3] * x3;
        xin[(size_t)tok * D + dd] = xi;
        xi_c[c] = xi;
        sum += xi; sumsq += xi * xi;
    }
    #pragma unroll
    for (int o = 16; o; o >>= 1) {
        sum += __shfl_xor_sync(~0u, sum, o);
        sumsq += __shfl_xor_sync(~0u, sumsq, o);
    }
    float mean = sum / (float)D;
    float var = sumsq / (float)D - mean * mean;
    float invstd = rsqrtf(var + 1e-5f);
    #pragma unroll
    for (int c = 0; c < 6; c++) {
        int dd = c * 32 + lane;
        float hv = (xi_c[c] - mean) * invstd * ln1_w[dd] + ln1_b[dd];
        g_h[(size_t)tok * D + dd] = __float2bfloat16(hv);
    }
}

// =================================================================================
// Kernel 4: LayerNorm (x2 f32 -> h bf16). One block (192 threads) per token.
// =================================================================================
__global__ __launch_bounds__(192) void ln2_kernel(
    const float* __restrict__ in, const float* __restrict__ w,
    const float* __restrict__ b)
{
    int tok = blockIdx.x, tid = threadIdx.x;
    int lane = tid & 31, wid = tid >> 5;
    __shared__ float red[6];
    __shared__ float s_mean, s_invstd;

    float v = in[(size_t)tok * D + tid];
    float sm = v;
    #pragma unroll
    for (int o = 16; o; o >>= 1) sm += __shfl_xor_sync(~0u, sm, o);
    if (lane == 0) red[wid] = sm;
    __syncthreads();
    if (tid == 0) {
        float s = red[0] + red[1] + red[2] + red[3] + red[4] + red[5];
        s_mean = s / (float)D;
    }
    __syncthreads();
    float dv = v - s_mean;
    float sq = dv * dv;
    #pragma unroll
    for (int o = 16; o; o >>= 1) sq += __shfl_xor_sync(~0u, sq, o);
    __syncthreads();
    if (lane == 0) red[wid] = sq;
    __syncthreads();
    if (tid == 0) {
        float s = red[0] + red[1] + red[2] + red[3] + red[4] + red[5];
        s_invstd = rsqrtf(s / (float)D + 1e-5f);
    }
    __syncthreads();
    g_h[(size_t)tok * D + tid] = __float2bfloat16(dv * s_invstd * w[tid] + b[tid]);
}

// =================================================================================
// Kernel 5: bf16 flash attention. BQ=128, BKEY=32, HD=64, 256 threads (8 warps).
// Register prefetch of next K/V tile overlaps gmem latency with compute.
// =================================================================================
__global__ __launch_bounds__(256, 2) void flash_bf(
    const bf16* __restrict__ QKV, bf16* __restrict__ O)
{
    __shared__ __align__(16) unsigned Qsp[128][36];  // [q][dpair]   (4g+tig) CF
    __shared__ __align__(16) unsigned Ksp[32][36];   // [key][dpair] (4g+tig) CF
    __shared__ __align__(16) unsigned Vp[16][72];    // [keypair][d] (8tig+g) CF
    __shared__ __align__(16) unsigned Pp[128][20];   // [q][keypair] (20g+tig) CF

    int tid = threadIdx.x, wid = tid >> 5, lane = tid & 31;
    int g = lane >> 2, tig = lane & 3;
    int qt = blockIdx.x, h = blockIdx.y, b = blockIdx.z;
    size_t tokbase = (size_t)b * T_SEQ;
    int qoff = h * HD, koff = D + h * HD, voff = 2 * D + h * HD;
    int m0 = wid * 16;

    // per-thread K/V load coords (fixed)
    int kr = tid >> 3, kcp = (tid & 7) * 4;    // K: row, pair-col
    int vkp = tid >> 4, vc = (tid & 15) * 4;   // V: pair-row, col

    // load Q tile (128 rows x 32 pairs)
    {
        int r = tid >> 1, cp0 = (tid & 1) * 16;
        const uint4* qp = (const uint4*)(QKV + (tokbase + qt * 128 + r) * QKVN + qoff + cp0 * 2);
        #pragma unroll
        for (int u = 0; u < 4; u++)
            *(uint4*)&Qsp[r][cp0 + u * 4] = qp[u];
    }
    float m_prev[2] = {-1e30f, -1e30f};
    float l_run[2] = {0.f, 0.f};
    float o_acc[8][4] = {};

    // prefetch tile 0 into regs
    uint4 kreg; uint2 vreg0, vreg1;
    kreg = *(const uint4*)(QKV + (tokbase + kr) * QKVN + koff + kcp * 2);
    {
        const bf16* vb = QKV + (tokbase + 2 * vkp) * QKVN + voff + vc;
        vreg0 = *(const uint2*)vb;
        vreg1 = *(const uint2*)(vb + QKVN);
    }
    __syncthreads();

    for (int kt = 0; kt < T_SEQ; kt += 32) {
        // commit prefetched tile to smem
        *(uint4*)&Ksp[kr][kcp] = kreg;
        {
            uint4 o;
            o.x = __byte_perm(vreg0.x, vreg1.x, 0x5410); o.y = __byte_perm(vreg0.x, vreg1.x, 0x7632);
            o.z = __byte_perm(vreg0.y, vreg1.y, 0x5410); o.w = __byte_perm(vreg0.y, vreg1.y, 0x7632);
            *(uint4*)&Vp[vkp][vc] = o;
        }
        __syncthreads();

        // issue prefetch for next tile (consumed after next barrier)
        if (kt + 32 < T_SEQ) {
            kreg = *(const uint4*)(QKV + (tokbase + kt + 32 + kr) * QKVN + koff + kcp * 2);
            const bf16* vb = QKV + (tokbase + kt + 32 + 2 * vkp) * QKVN + voff + vc;
            vreg0 = *(const uint2*)vb;
            vreg1 = *(const uint2*)(vb + QKVN);
        }

        // S = Q K^T (warp: 16 q-rows x 32 keys), d=64 -> 4 ksteps of 16
        float s[4][4] = {};
        #pragma unroll
        for (int ks = 0; ks < 4; ks++) {
            int kp0 = ks * 8;
            unsigned a0 = Qsp[m0 + g][kp0 + tig];
            unsigned a1 = Qsp[m0 + g + 8][kp0 + tig];
            unsigned a2 = Qsp[m0 + g][kp0 + tig + 4];
            unsigned a3 = Qsp[m0 + g + 8][kp0 + tig + 4];
            #pragma unroll
            for (int nt = 0; nt < 4; nt++) {
                unsigned b0 = Ksp[nt * 8 + g][kp0 + tig];
                unsigned b1 = Ksp[nt * 8 + g][kp0 + tig + 4];
                mma_bf16(s[nt], a0, a1, a2, a3, b0, b1);
            }
        }

        // online softmax (quad rows; shfl_xor 1,2 reduce within row)
        const float sc = 0.125f;
        float mx0 = -1e30f, mx1 = -1e30f;
        #pragma unroll
        for (int nt = 0; nt < 4; nt++) {
            s[nt][0] *= sc; s[nt][1] *= sc; s[nt][2] *= sc; s[nt][3] *= sc;
            mx0 = fmaxf(mx0, fmaxf(s[nt][0], s[nt][1]));
            mx1 = fmaxf(mx1, fmaxf(s[nt][2], s[nt][3]));
        }
        mx0 = fmaxf(mx0, __shfl_xor_sync(~0u, mx0, 1));
        mx0 = fmaxf(mx0, __shfl_xor_sync(~0u, mx0, 2));
        mx1 = fmaxf(mx1, __shfl_xor_sync(~0u, mx1, 1));
        mx1 = fmaxf(mx1, __shfl_xor_sync(~0u, mx1, 2));
        float mn0 = fmaxf(m_prev[0], mx0);
        float mn1 = fmaxf(m_prev[1], mx1);
        float rs0 = 0.f, rs1 = 0.f;
        #pragma unroll
        for (int nt = 0; nt < 4; nt++) {
            s[nt][0] = __expf(s[nt][0] - mn0);
            s[nt][1] = __expf(s[nt][1] - mn0);
            s[nt][2] = __expf(s[nt][2] - mn1);
            s[nt][3] = __expf(s[nt][3] - mn1);
            rs0 += s[nt][0] + s[nt][1];
            rs1 += s[nt][2] + s[nt][3];
        }
        rs0 += __shfl_xor_sync(~0u, rs0, 1);
        rs0 += __shfl_xor_sync(~0u, rs0, 2);
        rs1 += __shfl_xor_sync(~0u, rs1, 1);
        rs1 += __shfl_xor_sync(~0u, rs1, 2);
        float scl0 = __expf(m_prev[0] - mn0);
        float scl1 = __expf(m_prev[1] - mn1);
        l_run[0] = l_run[0] * scl0 + rs0;
        l_run[1] = l_run[1] * scl1 + rs1;
        m_prev[0] = mn0; m_prev[1] = mn1;
        #pragma unroll
        for (int nt = 0; nt < 8; nt++) {
            o_acc[nt][0] *= scl0; o_acc[nt][1] *= scl0;
            o_acc[nt][2] *= scl1; o_acc[nt][3] *= scl1;
        }
        // stage P as bf16 pairs along key (warp-private rows -> warp sync only)
        #pragma unroll
        for (int nt = 0; nt < 4; nt++) {
            Pp[m0 + g][nt * 4 + tig]     = pack_bf16(s[nt][0], s[nt][1]);
            Pp[m0 + g + 8][nt * 4 + tig] = pack_bf16(s[nt][2], s[nt][3]);
        }
        __syncwarp();

        // O += P V : key=32 -> 2 ksteps of 16
        #pragma unroll
        for (int ks = 0; ks < 2; ks++) {
            int kp0 = ks * 8;
            unsigned a0 = Pp[m0 + g][kp0 + tig];
            unsigned a1 = Pp[m0 + g + 8][kp0 + tig];
            unsigned a2 = Pp[m0 + g][kp0 + tig + 4];
            unsigned a3 = Pp[m0 + g + 8][kp0 + tig + 4];
            #pragma unroll
            for (int nt = 0; nt < 8; nt++) {
                unsigned b0 = Vp[kp0 + tig][nt * 8 + g];
                unsigned b1 = Vp[kp0 + tig + 4][nt * 8 + g];
                mma_bf16(o_acc[nt], a0, a1, a2, a3, b0, b1);
            }
        }
        __syncthreads();
    }

    float inv0 = 1.f / l_run[0];
    float inv1 = 1.f / l_run[1];
    size_t obase = tokbase * D + h * HD;
    int q0 = qt * 128 + m0 + g;
    #pragma unroll
    for (int nt = 0; nt < 8; nt++) {
        int col = nt * 8 + tig * 2;
        *(unsigned*)(O + obase + (size_t)q0 * D + col) =
            pack_bf16(o_acc[nt][0] * inv0, o_acc[nt][1] * inv0);
        *(unsigned*)(O + obase + (size_t)(q0 + 8) * D + col) =
            pack_bf16(o_acc[nt][2] * inv1, o_acc[nt][3] * inv1);
    }
}

// =================================================================================
extern "C" void kernel_launch(void* const* d_in, const int* in_sizes, int n_in,
                              void* d_out, int out_size)
{
    const float* x        = (const float*)d_in[0];
    const float* norm_w   = (const float*)d_in[1];
    const float* phi_pre  = (const float*)d_in[2];
    const float* phi_post = (const float*)d_in[3];
    const float* phi_res  = (const float*)d_in[4];
    const float* b_pre    = (const float*)d_in[5];
    const float* b_post   = (const float*)d_in[6];
    const float* b_res    = (const float*)d_in[7];
    const float* a_pre    = (const float*)d_in[8];
    const float* a_post   = (const float*)d_in[9];
    const float* a_res    = (const float*)d_in[10];
    const float* ln1_w    = (const float*)d_in[11];
    const float* ln1_b    = (const float*)d_in[12];
    const float* Wq       = (const float*)d_in[13];
    const float* Wk       = (const float*)d_in[14];
    const float* Wv       = (const float*)d_in[15];
    const float* Wo       = (const float*)d_in[16];
    const float* ln2_w    = (const float*)d_in[17];
    const float* ln2_b    = (const float*)d_in[18];
    const float* W1       = (const float*)d_in[19];
    const float* W2       = (const float*)d_in[20];
    float* out = (float*)d_out;

    void *p;
    cudaGetSymbolAddress(&p, g_xin);     float* xin       = (float*)p;
    cudaGetSymbolAddress(&p, g_x2);      float* x2        = (float*)p;
    cudaGetSymbolAddress(&p, g_hpost);   float* hpost     = (float*)p;
    cudaGetSymbolAddress(&p, g_tilde);   float* tilde     = (float*)p;
    cudaGetSymbolAddress(&p, g_streams); bf16* streams    = (bf16*)p;
    cudaGetSymbolAddress(&p, g_h);       bf16* h          = (bf16*)p;
    cudaGetSymbolAddress(&p, g_qkv);     bf16* qkv        = (bf16*)p;
    cudaGetSymbolAddress(&p, g_o);       bf16* o          = (bf16*)p;
    cudaGetSymbolAddress(&p, g_g);       bf16* gbuf       = (bf16*)p;
    cudaGetSymbolAddress(&p, g_wqkv_p);  unsigned* wqkv   = (unsigned*)p;
    cudaGetSymbolAddress(&p, g_wo_p);    unsigned* wo     = (unsigned*)p;
    cudaGetSymbolAddress(&p, g_w1_p);    unsigned* w1     = (unsigned*)p;
    cudaGetSymbolAddress(&p, g_w2_p);    unsigned* w2     = (unsigned*)p;
    cudaGetSymbolAddress(&p, g_phiC_p);  unsigned* phiC   = (unsigned*)p;

    // 0) weight conversion (k-pair interleaved)
    convert_kernel<<<288, 256>>>(Wq, Wk, Wv, Wo, W1, W2, phi_pre, phi_post, phi_res,
                                 b_pre, b_post, b_res, a_pre, a_post, a_res);
    // 1) rmsnorm -> streams bf16
    rms_kernel<<<BT, 192>>>(x, norm_w);
    // 2) projections -> tilde (+bias)
    gemm_bf<4><<<dim3(1, BT / 128), 256>>>(streams, phiC, nullptr, nullptr, tilde, 64, ND);
    // 3a) sigmoid + sinkhorn (one thread per token) -> gates, hpost
    gates_kernel<<<BT / 256, 256>>>(hpost);
    // 3b) mix + LN1 -> out(x_res), xin, h
    sinkmix_kernel<<<BT / 8, 256>>>(x, ln1_w, ln1_b, out, xin);
    // 4) fused QKV
    dim3 g192(D / 64, BT / 128), g576(QKVN / 64, BT / 128), g768(MLP / 64, BT / 128);
    gemm_bf<0><<<g576, 256>>>(h, wqkv, nullptr, nullptr, qkv, QKVN, D);
    // 5) attention
    flash_bf<<<dim3(T_SEQ / 128, NH, NB), 256>>>(qkv, o);
    // 6) Wo + residual -> x2 (f32)
    gemm_bf<1><<<g192, 256>>>(o, wo, xin, nullptr, x2, D, D);
    // 7) LN2 -> h bf16
    ln2_kernel<<<BT, 192>>>(x2, ln2_w, ln2_b);
    // 8) MLP up + GELU -> g bf16
    gemm_bf<2><<<g768, 256>>>(h, w1, nullptr, nullptr, gbuf, MLP, D);
    // 9) MLP down + residual + fused gated scatter into out
    gemm_bf<3><<<g192, 256>>>(gbuf, w2, x2, hpost, out, D, MLP);
}

// round 10
// speedup vs baseline: 6.4833x; 1.0602x over previous
#include <cuda_runtime.h>
#include <cuda_bf16.h>
#include <math.h>

#define BT 32768
#define NSTREAM 4
#define D 192
#define ND 768
#define MLP 768
#define T_SEQ 1024
#define NB 32
#define NH 3
#define HD 64
#define QKVN 576

typedef __nv_bfloat16 bf16;

// ---------------- scratch (device globals; no allocation allowed) ----------------
__device__ float g_xin[BT * D];
__device__ float g_x2[BT * D];
__device__ float g_hpost[BT * NSTREAM];
__device__ float g_tilde[BT * 24];
__device__ float g_gates[BT * 20];       // 16 hres + 4 hpre per token
__device__ float g_bias24[24];
__device__ bf16  g_streams[BT * ND];
__device__ bf16  g_h[BT * D];
__device__ bf16  g_qkv[BT * QKVN];
__device__ bf16  g_o[BT * D];
__device__ bf16  g_g[BT * MLP];
// k-pair-interleaved weights: W_p[kp][n] = pack(W[2kp][n], W[2kp+1][n])
__device__ unsigned g_wqkv_p[(D / 2) * QKVN];
__device__ unsigned g_wo_p[(D / 2) * D];
__device__ unsigned g_w1_p[(D / 2) * MLP];
__device__ unsigned g_w2_p[(MLP / 2) * D];
__device__ unsigned g_phiC_p[(ND / 2) * 64];

// ---------------- helpers ----------------
__device__ __forceinline__ unsigned pack_bf16(float lo, float hi) {
    unsigned r;
    asm("cvt.rn.bf16x2.f32 %0, %1, %2;" : "=r"(r) : "f"(hi), "f"(lo));
    return r;
}

__device__ __forceinline__ void mma_bf16(float c[4],
    unsigned a0, unsigned a1, unsigned a2, unsigned a3,
    unsigned b0, unsigned b1)
{
    asm volatile(
        "mma.sync.aligned.m16n8k16.row.col.f32.bf16.bf16.f32 "
        "{%0,%1,%2,%3}, {%4,%5,%6,%7}, {%8,%9}, {%0,%1,%2,%3};\n"
        : "+f"(c[0]), "+f"(c[1]), "+f"(c[2]), "+f"(c[3])
        : "r"(a0), "r"(a1), "r"(a2), "r"(a3), "r"(b0), "r"(b1));
}

__device__ __forceinline__ void cp16(void* smem, const void* g) {
    unsigned saddr = (unsigned)__cvta_generic_to_shared(smem);
    asm volatile("cp.async.cg.shared.global [%0], [%1], 16;\n" :: "r"(saddr), "l"(g));
}
#define CP_COMMIT() asm volatile("cp.async.commit_group;\n" ::: "memory")

__device__ __forceinline__ float frcp(float x) {
    float r;
    asm("rcp.approx.f32 %0, %1;" : "=f"(r) : "f"(x));
    return r;
}

__device__ __forceinline__ float tanh_ap(float x) {
    float r;
    asm("tanh.approx.f32 %0, %1;" : "=f"(r) : "f"(x));
    return r;
}

__device__ __forceinline__ float gelu_f(float x) {
    float x3 = x * x * x;
    float t = tanh_ap(0.7978845608028654f * (x + 0.044715f * x3));
    return 0.5f * x * (1.f + t);
}

// =================================================================================
// Kernel 0: weight conversion fp32 -> bf16 k-pair-interleaved (+ phi combine, bias24)
// =================================================================================
__global__ void convert_kernel(
    const float* __restrict__ Wq, const float* __restrict__ Wk,
    const float* __restrict__ Wv, const float* __restrict__ Wo,
    const float* __restrict__ W1, const float* __restrict__ W2,
    const float* __restrict__ phi_pre, const float* __restrict__ phi_post,
    const float* __restrict__ phi_res,
    const float* __restrict__ b_pre, const float* __restrict__ b_post,
    const float* __restrict__ b_res,
    const float* __restrict__ a_pre, const float* __restrict__ a_post,
    const float* __restrict__ a_res)
{
    int idx = blockIdx.x * blockDim.x + threadIdx.x;
    if (idx < (D / 2) * QKVN) {
        int kp = idx / QKVN, c = idx % QKVN;
        const float* W; int cc;
        if (c < D)          { W = Wq; cc = c; }
        else if (c < 2 * D) { W = Wk; cc = c - D; }
        else                { W = Wv; cc = c - 2 * D; }
        g_wqkv_p[idx] = pack_bf16(W[(2 * kp) * D + cc], W[(2 * kp + 1) * D + cc]);
    }
    if (idx < (D / 2) * D) {
        int kp = idx / D, c = idx % D;
        g_wo_p[idx] = pack_bf16(Wo[(2 * kp) * D + c], Wo[(2 * kp + 1) * D + c]);
    }
    if (idx < (D / 2) * MLP) {
        int kp = idx / MLP, c = idx % MLP;
        g_w1_p[idx] = pack_bf16(W1[(2 * kp) * MLP + c], W1[(2 * kp + 1) * MLP + c]);
    }
    if (idx < (MLP / 2) * D) {
        int kp = idx / D, c = idx % D;
        g_w2_p[idx] = pack_bf16(W2[(2 * kp) * D + c], W2[(2 * kp + 1) * D + c]);
    }
    if (idx < (ND / 2) * 64) {
        int kp = idx >> 6, c = idx & 63;
        float v[2];
        #pragma unroll
        for (int u = 0; u < 2; u++) {
            int d = 2 * kp + u;
            float t = 0.f;
            if (c < 4)       t = a_pre[0]  * phi_pre[d * 4 + c];
            else if (c < 8)  t = a_post[0] * phi_post[d * 4 + (c - 4)];
            else if (c < 24) t = a_res[0]  * phi_res[d * 16 + (c - 8)];
            v[u] = t;
        }
        g_phiC_p[idx] = pack_bf16(v[0], v[1]);
    }
    if (idx < 24) {
        float v;
        if (idx < 4)      v = b_pre[idx];
        else if (idx < 8) v = b_post[idx - 4];
        else              v = b_res[idx - 8];
        g_bias24[idx] = v;
    }
}

// =================================================================================
// Kernel 1: rmsnorm -> streams (bf16). One block (192 threads, float4 each) / token.
// =================================================================================
__global__ __launch_bounds__(192) void rms_kernel(
    const float* __restrict__ x, const float* __restrict__ norm_w)
{
    int tok = blockIdx.x, tid = threadIdx.x;
    int lane = tid & 31, wid = tid >> 5;
    __shared__ float red[6];
    __shared__ float s_inv;

    float4 xv = *(const float4*)(x + (size_t)tok * ND + tid * 4);
    float sq = xv.x * xv.x + xv.y * xv.y + xv.z * xv.z + xv.w * xv.w;
    #pragma unroll
    for (int o = 16; o; o >>= 1) sq += __shfl_xor_sync(~0u, sq, o);
    if (lane == 0) red[wid] = sq;
    __syncthreads();
    if (tid == 0) {
        float s = red[0] + red[1] + red[2] + red[3] + red[4] + red[5];
        s_inv = rsqrtf(s / (float)ND + 1e-8f);
    }
    __syncthreads();
    float inv = s_inv;
    float4 wv = *(const float4*)(norm_w + tid * 4);
    unsigned p0 = pack_bf16(xv.x * inv * wv.x, xv.y * inv * wv.y);
    unsigned p1 = pack_bf16(xv.z * inv * wv.z, xv.w * inv * wv.w);
    *(uint2*)((unsigned*)g_streams + (size_t)tok * (ND / 2) + tid * 2) = make_uint2(p0, p1);
}

// =================================================================================
// Kernel 2: bf16 tensor-core GEMM, cp.async 2-stage pipeline.
// BM=128 BN=64 BK=32, 256 threads, 8 warps. B passed pre-interleaved (k-pairs).
// EPI: 0 plain->bf16, 1 +Res->f32, 2 gelu->bf16, 3 scatter out+=(acc+Res)*hpost,
//      4 tilde (f32, cols<24, +bias24)
// =================================================================================
template <int EPI>
__global__ __launch_bounds__(256) void gemm_bf(
    const bf16* __restrict__ A, const unsigned* __restrict__ Bp,
    const float* __restrict__ Res, const float* __restrict__ hpost,
    void* __restrict__ Cv, int N, int K)
{
    __shared__ __align__(16) unsigned Asp[2][128][20];  // [m][kpair], (20g+tig) CF
    __shared__ __align__(16) unsigned Bsp[2][16][72];   // [kpair][n], (8tig+g) CF

    int tid = threadIdx.x;
    int wid = tid >> 5, lane = tid & 31;
    int g = lane >> 2, tig = lane & 3;
    int wm = wid & 3, wn = wid >> 2;     // 4 x 2 warp grid
    int bm = blockIdx.y, bn = blockIdx.x;

    float acc[2][4][4] = {};

    int ar = tid >> 1, acp = (tid & 1) * 8;   // A: row, pair-col base
    int bkp = tid >> 4, bc = (tid & 15) * 4;  // B: pair-row, col base

    const bf16* Abase = A + (size_t)(bm * 128 + ar) * K + acp * 2;
    const unsigned* Bbase = Bp + (size_t)bkp * N + bn * 64 + bc;

    // prefetch stage 0
    cp16(&Asp[0][ar][acp],     Abase);
    cp16(&Asp[0][ar][acp + 4], Abase + 8);
    cp16(&Bsp[0][bkp][bc],     Bbase);
    CP_COMMIT();

    int nk = K >> 5;
    for (int it = 0; it < nk; it++) {
        if (it + 1 < nk) {
            int st = (it + 1) & 1;
            cp16(&Asp[st][ar][acp],     Abase + (it + 1) * 32);
            cp16(&Asp[st][ar][acp + 4], Abase + (it + 1) * 32 + 8);
            cp16(&Bsp[st][bkp][bc],     Bbase + (size_t)16 * (it + 1) * N);
            CP_COMMIT();
            asm volatile("cp.async.wait_group 1;\n" ::: "memory");
        } else {
            asm volatile("cp.async.wait_group 0;\n" ::: "memory");
        }
        __syncthreads();

        const unsigned (*As)[20] = Asp[it & 1];
        const unsigned (*Bs)[72] = Bsp[it & 1];
        #pragma unroll
        for (int ks = 0; ks < 2; ks++) {
            int kp0 = ks * 8;
            unsigned a[2][4], b[4][2];
            #pragma unroll
            for (int mt = 0; mt < 2; mt++) {
                int m0 = wm * 32 + mt * 16;
                a[mt][0] = As[m0 + g][kp0 + tig];
                a[mt][1] = As[m0 + g + 8][kp0 + tig];
                a[mt][2] = As[m0 + g][kp0 + tig + 4];
                a[mt][3] = As[m0 + g + 8][kp0 + tig + 4];
            }
            #pragma unroll
            for (int nt = 0; nt < 4; nt++) {
                int n0 = wn * 32 + nt * 8;
                b[nt][0] = Bs[kp0 + tig][n0 + g];
                b[nt][1] = Bs[kp0 + tig + 4][n0 + g];
            }
            #pragma unroll
            for (int mt = 0; mt < 2; mt++)
                #pragma unroll
                for (int nt = 0; nt < 4; nt++)
                    mma_bf16(acc[mt][nt], a[mt][0], a[mt][1], a[mt][2], a[mt][3],
                             b[nt][0], b[nt][1]);
        }
        __syncthreads();
    }

    #pragma unroll
    for (int mt = 0; mt < 2; mt++) {
        #pragma unroll
        for (int half = 0; half < 2; half++) {
            int row = bm * 128 + wm * 32 + mt * 16 + g + half * 8;
            #pragma unroll
            for (int nt = 0; nt < 4; nt++) {
                int col = bn * 64 + wn * 32 + nt * 8 + tig * 2;
                float v0 = acc[mt][nt][half * 2 + 0];
                float v1 = acc[mt][nt][half * 2 + 1];
                if (EPI == 0) {
                    bf16* C = (bf16*)Cv;
                    *(unsigned*)(C + (size_t)row * N + col) = pack_bf16(v0, v1);
                } else if (EPI == 1) {
                    float* C = (float*)Cv;
                    float2 r = *(const float2*)(Res + (size_t)row * N + col);
                    *(float2*)(C + (size_t)row * N + col) = make_float2(v0 + r.x, v1 + r.y);
                } else if (EPI == 2) {
                    bf16* C = (bf16*)Cv;
                    *(unsigned*)(C + (size_t)row * N + col) = pack_bf16(gelu_f(v0), gelu_f(v1));
                } else if (EPI == 3) {
                    float* C = (float*)Cv;
                    float2 r = *(const float2*)(Res + (size_t)row * N + col);
                    float vx = v0 + r.x, vy = v1 + r.y;
                    #pragma unroll
                    for (int s = 0; s < 4; s++) {
                        float hp = hpost[(size_t)row * 4 + s];
                        float* op = C + (size_t)row * ND + s * D + col;
                        float2 o = *(const float2*)op;
                        o.x += vx * hp; o.y += vy * hp;
                        *(float2*)op = o;
                    }
                } else { // EPI == 4: tilde (width 24), add bias24
                    if (wn == 0 && nt < 3) {
                        float* C = (float*)Cv;
                        float2 bv = *(const float2*)(g_bias24 + col);
                        *(float2*)(C + (size_t)row * 24 + col) = make_float2(v0 + bv.x, v1 + bv.y);
                    }
                }
            }
        }
    }
}

// =================================================================================
// Kernel 3a: gates kernel. ONE THREAD per token. 128 thr/block, 256 blocks (>148 SMs).
// =================================================================================
__global__ __launch_bounds__(128) void gates_kernel(float* __restrict__ hpost)
{
    __shared__ float sm[128 * 25];
    int tid = threadIdx.x;
    size_t b0 = (size_t)blockIdx.x * 128;

    for (int i = tid; i < 128 * 24; i += 128) {
        int t = i / 24, e = i - t * 24;
        sm[t * 25 + e] = g_tilde[b0 * 24 + i];
    }
    __syncthreads();

    size_t tok = b0 + tid;
    const float* tl = &sm[tid * 25];

    float hp[4];
    #pragma unroll
    for (int j = 0; j < 4; j++) hp[j] = frcp(1.f + __expf(-tl[j]));
    float4 hp4;
    hp4.x = 2.f * frcp(1.f + __expf(-tl[4]));
    hp4.y = 2.f * frcp(1.f + __expf(-tl[5]));
    hp4.z = 2.f * frcp(1.f + __expf(-tl[6]));
    hp4.w = 2.f * frcp(1.f + __expf(-tl[7]));
    *(float4*)(hpost + tok * 4) = hp4;

    float m[16];
    float mx = tl[8];
    #pragma unroll
    for (int j = 1; j < 16; j++) mx = fmaxf(mx, tl[8 + j]);
    #pragma unroll
    for (int j = 0; j < 16; j++) m[j] = __expf(tl[8 + j] - mx);

    #pragma unroll 1
    for (int it = 0; it < 20; it++) {
        #pragma unroll
        for (int i = 0; i < 4; i++) {
            float rs = m[4 * i] + m[4 * i + 1] + m[4 * i + 2] + m[4 * i + 3];
            float inv = frcp(rs + 1e-8f);
            m[4 * i] *= inv; m[4 * i + 1] *= inv; m[4 * i + 2] *= inv; m[4 * i + 3] *= inv;
        }
        #pragma unroll
        for (int j = 0; j < 4; j++) {
            float cs = m[j] + m[4 + j] + m[8 + j] + m[12 + j];
            float inv = frcp(cs + 1e-8f);
            m[j] *= inv; m[4 + j] *= inv; m[8 + j] *= inv; m[12 + j] *= inv;
        }
    }

    float* gp = g_gates + tok * 20;
    *(float4*)(gp + 0)  = make_float4(m[0], m[1], m[2], m[3]);
    *(float4*)(gp + 4)  = make_float4(m[4], m[5], m[6], m[7]);
    *(float4*)(gp + 8)  = make_float4(m[8], m[9], m[10], m[11]);
    *(float4*)(gp + 12) = make_float4(m[12], m[13], m[14], m[15]);
    *(float4*)(gp + 16) = make_float4(hp[0], hp[1], hp[2], hp[3]);
}

// =================================================================================
// Kernel 3b: stream mixing + fused LN1 (pure streaming). 1 warp/token, 8 tok/block.
// =================================================================================
__global__ __launch_bounds__(256) void sinkmix_kernel(
    const float* __restrict__ x,
    const float* __restrict__ ln1_w, const float* __restrict__ ln1_b,
    float* __restrict__ out, float* __restrict__ xin)
{
    int wid = threadIdx.x >> 5, lane = threadIdx.x & 31;
    int tok = blockIdx.x * 8 + wid;

    float gv = (lane < 20) ? g_gates[(size_t)tok * 20 + lane] : 0.f;
    float hr[16], hp[4];
    #pragma unroll
    for (int i = 0; i < 16; i++) hr[i] = __shfl_sync(~0u, gv, i);
    #pragma unroll
    for (int i = 0; i < 4; i++) hp[i] = __shfl_sync(~0u, gv, 16 + i);

    const float* xrow = x + (size_t)tok * ND;
    float xi_c[6];
    float sum = 0.f, sumsq = 0.f;
    #pragma unroll
    for (int c = 0; c < 6; c++) {
        int dd = c * 32 + lane;
        float x0 = xrow[dd], x1 = xrow[D + dd], x2v = xrow[2 * D + dd], x3 = xrow[3 * D + dd];
        #pragma unroll
        for (int i = 0; i < 4; i++) {
            float r = hr[i * 4 + 0] * x0 + hr[i * 4 + 1] * x1
                    + hr[i * 4 + 2] * x2v + hr[i * 4 + 3] * x3;
            out[(size_t)tok * ND + i * D + dd] = r;
        }
        float xi = hp[0] * x0 + hp[1] * x1 + hp[2] * x2v + hp[3] * x3;
        xin[(size_t)tok * D + dd] = xi;
        xi_c[c] = xi;
        sum += xi; sumsq += xi * xi;
    }
    #pragma unroll
    for (int o = 16; o; o >>= 1) {
        sum += __shfl_xor_sync(~0u, sum, o);
        sumsq += __shfl_xor_sync(~0u, sumsq, o);
    }
    float mean = sum / (float)D;
    float var = sumsq / (float)D - mean * mean;
    float invstd = rsqrtf(var + 1e-5f);
    #pragma unroll
    for (int c = 0; c < 6; c++) {
        int dd = c * 32 + lane;
        float hv = (xi_c[c] - mean) * invstd * ln1_w[dd] + ln1_b[dd];
        g_h[(size_t)tok * D + dd] = __float2bfloat16(hv);
    }
}

// =================================================================================
// Kernel 4: LayerNorm (x2 f32 -> h bf16). One block (192 threads) per token.
// =================================================================================
__global__ __launch_bounds__(192) void ln2_kernel(
    const float* __restrict__ in, const float* __restrict__ w,
    const float* __restrict__ b)
{
    int tok = blockIdx.x, tid = threadIdx.x;
    int lane = tid & 31, wid = tid >> 5;
    __shared__ float red[6];
    __shared__ float s_mean, s_invstd;

    float v = in[(size_t)tok * D + tid];
    float sm = v;
    #pragma unroll
    for (int o = 16; o; o >>= 1) sm += __shfl_xor_sync(~0u, sm, o);
    if (lane == 0) red[wid] = sm;
    __syncthreads();
    if (tid == 0) {
        float s = red[0] + red[1] + red[2] + red[3] + red[4] + red[5];
        s_mean = s / (float)D;
    }
    __syncthreads();
    float dv = v - s_mean;
    float sq = dv * dv;
    #pragma unroll
    for (int o = 16; o; o >>= 1) sq += __shfl_xor_sync(~0u, sq, o);
    __syncthreads();
    if (lane == 0) red[wid] = sq;
    __syncthreads();
    if (tid == 0) {
        float s = red[0] + red[1] + red[2] + red[3] + red[4] + red[5];
        s_invstd = rsqrtf(s / (float)D + 1e-5f);
    }
    __syncthreads();
    g_h[(size_t)tok * D + tid] = __float2bfloat16(dv * s_invstd * w[tid] + b[tid]);
}

// =================================================================================
// Kernel 5: bf16 flash attention. BQ=128, BKEY=64, HD=64, 256 threads (8 warps).
// P stays in registers (C-frag of QK^T == A-frag of PV). Register K/V prefetch.
// =================================================================================
__global__ __launch_bounds__(256, 2) void flash_bf(
    const bf16* __restrict__ QKV, bf16* __restrict__ O)
{
    __shared__ __align__(16) unsigned Qsp[128][36];  // [q][dpair]   (4g+tig) CF
    __shared__ __align__(16) unsigned Ksp[64][36];   // [key][dpair] (4g+tig) CF
    __shared__ __align__(16) unsigned Vp[32][72];    // [keypair][d] (8tig+g) CF

    int tid = threadIdx.x, wid = tid >> 5, lane = tid & 31;
    int g = lane >> 2, tig = lane & 3;
    int qt = blockIdx.x, h = blockIdx.y, b = blockIdx.z;
    size_t tokbase = (size_t)b * T_SEQ;
    int qoff = h * HD, koff = D + h * HD, voff = 2 * D + h * HD;
    int m0 = wid * 16;

    // per-thread K/V load coords (fixed)
    int kr = tid >> 2, kcp = (tid & 3) * 8;    // K: row (64), pair-col base (2 uint4)
    int vkp = tid >> 3, vc = (tid & 7) * 8;    // V: pair-row (32), col base (8 cols)

    // load Q tile (128 rows x 32 pairs)
    {
        int r = tid >> 1, cp0 = (tid & 1) * 16;
        const uint4* qp = (const uint4*)(QKV + (tokbase + qt * 128 + r) * QKVN + qoff + cp0 * 2);
        #pragma unroll
        for (int u = 0; u < 4; u++)
            *(uint4*)&Qsp[r][cp0 + u * 4] = qp[u];
    }
    float m_prev[2] = {-1e30f, -1e30f};
    float l_run[2] = {0.f, 0.f};
    float o_acc[8][4] = {};

    // prefetch tile 0 into regs
    uint4 kreg0, kreg1, vreg0, vreg1;
    kreg0 = *(const uint4*)(QKV + (tokbase + kr) * QKVN + koff + kcp * 2);
    kreg1 = *(const uint4*)(QKV + (tokbase + kr) * QKVN + koff + (kcp + 4) * 2);
    {
        const bf16* vb = QKV + (tokbase + 2 * vkp) * QKVN + voff + vc;
        vreg0 = *(const uint4*)vb;
        vreg1 = *(const uint4*)(vb + QKVN);
    }
    __syncthreads();

    for (int kt = 0; kt < T_SEQ; kt += 64) {
        // commit prefetched tile to smem
        *(uint4*)&Ksp[kr][kcp]     = kreg0;
        *(uint4*)&Ksp[kr][kcp + 4] = kreg1;
        {
            uint4 oA, oB;
            oA.x = __byte_perm(vreg0.x, vreg1.x, 0x5410); oA.y = __byte_perm(vreg0.x, vreg1.x, 0x7632);
            oA.z = __byte_perm(vreg0.y, vreg1.y, 0x5410); oA.w = __byte_perm(vreg0.y, vreg1.y, 0x7632);
            oB.x = __byte_perm(vreg0.z, vreg1.z, 0x5410); oB.y = __byte_perm(vreg0.z, vreg1.z, 0x7632);
            oB.z = __byte_perm(vreg0.w, vreg1.w, 0x5410); oB.w = __byte_perm(vreg0.w, vreg1.w, 0x7632);
            *(uint4*)&Vp[vkp][vc]     = oA;
            *(uint4*)&Vp[vkp][vc + 4] = oB;
        }
        __syncthreads();

        // issue prefetch for next tile (consumed after next barrier)
        if (kt + 64 < T_SEQ) {
            const bf16* kb = QKV + (tokbase + kt + 64 + kr) * QKVN + koff;
            kreg0 = *(const uint4*)(kb + kcp * 2);
            kreg1 = *(const uint4*)(kb + (kcp + 4) * 2);
            const bf16* vb = QKV + (tokbase + kt + 64 + 2 * vkp) * QKVN + voff + vc;
            vreg0 = *(const uint4*)vb;
            vreg1 = *(const uint4*)(vb + QKVN);
        }

        // S = Q K^T (warp: 16 q-rows x 64 keys), d=64 -> 4 ksteps of 16
        float s[8][4] = {};
        #pragma unroll
        for (int ks = 0; ks < 4; ks++) {
            int kp0 = ks * 8;
            unsigned a0 = Qsp[m0 + g][kp0 + tig];
            unsigned a1 = Qsp[m0 + g + 8][kp0 + tig];
            unsigned a2 = Qsp[m0 + g][kp0 + tig + 4];
            unsigned a3 = Qsp[m0 + g + 8][kp0 + tig + 4];
            #pragma unroll
            for (int nt = 0; nt < 8; nt++) {
                unsigned b0 = Ksp[nt * 8 + g][kp0 + tig];
                unsigned b1 = Ksp[nt * 8 + g][kp0 + tig + 4];
                mma_bf16(s[nt], a0, a1, a2, a3, b0, b1);
            }
        }

        // online softmax (quad rows; shfl_xor 1,2 reduce within row)
        const float sc = 0.125f;
        float mx0 = -1e30f, mx1 = -1e30f;
        #pragma unroll
        for (int nt = 0; nt < 8; nt++) {
            s[nt][0] *= sc; s[nt][1] *= sc; s[nt][2] *= sc; s[nt][3] *= sc;
            mx0 = fmaxf(mx0, fmaxf(s[nt][0], s[nt][1]));
            mx1 = fmaxf(mx1, fmaxf(s[nt][2], s[nt][3]));
        }
        mx0 = fmaxf(mx0, __shfl_xor_sync(~0u, mx0, 1));
        mx0 = fmaxf(mx0, __shfl_xor_sync(~0u, mx0, 2));
        mx1 = fmaxf(mx1, __shfl_xor_sync(~0u, mx1, 1));
        mx1 = fmaxf(mx1, __shfl_xor_sync(~0u, mx1, 2));
        float mn0 = fmaxf(m_prev[0], mx0);
        float mn1 = fmaxf(m_prev[1], mx1);
        float rs0 = 0.f, rs1 = 0.f;
        #pragma unroll
        for (int nt = 0; nt < 8; nt++) {
            s[nt][0] = __expf(s[nt][0] - mn0);
            s[nt][1] = __expf(s[nt][1] - mn0);
            s[nt][2] = __expf(s[nt][2] - mn1);
            s[nt][3] = __expf(s[nt][3] - mn1);
            rs0 += s[nt][0] + s[nt][1];
            rs1 += s[nt][2] + s[nt][3];
        }
        rs0 += __shfl_xor_sync(~0u, rs0, 1);
        rs0 += __shfl_xor_sync(~0u, rs0, 2);
        rs1 += __shfl_xor_sync(~0u, rs1, 1);
        rs1 += __shfl_xor_sync(~0u, rs1, 2);
        float scl0 = __expf(m_prev[0] - mn0);
        float scl1 = __expf(m_prev[1] - mn1);
        l_run[0] = l_run[0] * scl0 + rs0;
        l_run[1] = l_run[1] * scl1 + rs1;
        m_prev[0] = mn0; m_prev[1] = mn1;
        #pragma unroll
        for (int nt = 0; nt < 8; nt++) {
            o_acc[nt][0] *= scl0; o_acc[nt][1] *= scl0;
            o_acc[nt][2] *= scl1; o_acc[nt][3] *= scl1;
        }

        // O += P V : P stays in registers (C-frag == A-frag). key=64 -> 4 ksteps.
        #pragma unroll
        for (int ks = 0; ks < 4; ks++) {
            int kp0 = ks * 8;
            unsigned a0 = pack_bf16(s[2 * ks][0],     s[2 * ks][1]);
            unsigned a1 = pack_bf16(s[2 * ks][2],     s[2 * ks][3]);
            unsigned a2 = pack_bf16(s[2 * ks + 1][0], s[2 * ks + 1][1]);
            unsigned a3 = pack_bf16(s[2 * ks + 1][2], s[2 * ks + 1][3]);
            #pragma unroll
            for (int nt = 0; nt < 8; nt++) {
                unsigned b0 = Vp[kp0 + tig][nt * 8 + g];
                unsigned b1 = Vp[kp0 + tig + 4][nt * 8 + g];
                mma_bf16(o_acc[nt], a0, a1, a2, a3, b0, b1);
            }
        }
        __syncthreads();
    }

    float inv0 = 1.f / l_run[0];
    float inv1 = 1.f / l_run[1];
    size_t obase = tokbase * D + h * HD;
    int q0 = qt * 128 + m0 + g;
    #pragma unroll
    for (int nt = 0; nt < 8; nt++) {
        int col = nt * 8 + tig * 2;
        *(unsigned*)(O + obase + (size_t)q0 * D + col) =
            pack_bf16(o_acc[nt][0] * inv0, o_acc[nt][1] * inv0);
        *(unsigned*)(O + obase + (size_t)(q0 + 8) * D + col) =
            pack_bf16(o_acc[nt][2] * inv1, o_acc[nt][3] * inv1);
    }
}

// =================================================================================
extern "C" void kernel_launch(void* const* d_in, const int* in_sizes, int n_in,
                              void* d_out, int out_size)
{
    const float* x        = (const float*)d_in[0];
    const float* norm_w   = (const float*)d_in[1];
    const float* phi_pre  = (const float*)d_in[2];
    const float* phi_post = (const float*)d_in[3];
    const float* phi_res  = (const float*)d_in[4];
    const float* b_pre    = (const float*)d_in[5];
    const float* b_post   = (const float*)d_in[6];
    const float* b_res    = (const float*)d_in[7];
    const float* a_pre    = (const float*)d_in[8];
    const float* a_post   = (const float*)d_in[9];
    const float* a_res    = (const float*)d_in[10];
    const float* ln1_w    = (const float*)d_in[11];
    const float* ln1_b    = (const float*)d_in[12];
    const float* Wq       = (const float*)d_in[13];
    const float* Wk       = (const float*)d_in[14];
    const float* Wv       = (const float*)d_in[15];
    const float* Wo       = (const float*)d_in[16];
    const float* ln2_w    = (const float*)d_in[17];
    const float* ln2_b    = (const float*)d_in[18];
    const float* W1       = (const float*)d_in[19];
    const float* W2       = (const float*)d_in[20];
    float* out = (float*)d_out;

    void *p;
    cudaGetSymbolAddress(&p, g_xin);     float* xin       = (float*)p;
    cudaGetSymbolAddress(&p, g_x2);      float* x2        = (float*)p;
    cudaGetSymbolAddress(&p, g_hpost);   float* hpost     = (float*)p;
    cudaGetSymbolAddress(&p, g_tilde);   float* tilde     = (float*)p;
    cudaGetSymbolAddress(&p, g_streams); bf16* streams    = (bf16*)p;
    cudaGetSymbolAddress(&p, g_h);       bf16* h          = (bf16*)p;
    cudaGetSymbolAddress(&p, g_qkv);     bf16* qkv        = (bf16*)p;
    cudaGetSymbolAddress(&p, g_o);       bf16* o          = (bf16*)p;
    cudaGetSymbolAddress(&p, g_g);       bf16* gbuf       = (bf16*)p;
    cudaGetSymbolAddress(&p, g_wqkv_p);  unsigned* wqkv   = (unsigned*)p;
    cudaGetSymbolAddress(&p, g_wo_p);    unsigned* wo     = (unsigned*)p;
    cudaGetSymbolAddress(&p, g_w1_p);    unsigned* w1     = (unsigned*)p;
    cudaGetSymbolAddress(&p, g_w2_p);    unsigned* w2     = (unsigned*)p;
    cudaGetSymbolAddress(&p, g_phiC_p);  unsigned* phiC   = (unsigned*)p;

    // 0) weight conversion (k-pair interleaved)
    convert_kernel<<<288, 256>>>(Wq, Wk, Wv, Wo, W1, W2, phi_pre, phi_post, phi_res,
                                 b_pre, b_post, b_res, a_pre, a_post, a_res);
    // 1) rmsnorm -> streams bf16
    rms_kernel<<<BT, 192>>>(x, norm_w);
    // 2) projections -> tilde (+bias)
    gemm_bf<4><<<dim3(1, BT / 128), 256>>>(streams, phiC, nullptr, nullptr, tilde, 64, ND);
    // 3a) sigmoid + sinkhorn (one thread per token) -> gates, hpost
    gates_kernel<<<BT / 128, 128>>>(hpost);
    // 3b) mix + LN1 -> out(x_res), xin, h
    sinkmix_kernel<<<BT / 8, 256>>>(x, ln1_w, ln1_b, out, xin);
    // 4) fused QKV
    dim3 g192(D / 64, BT / 128), g576(QKVN / 64, BT / 128), g768(MLP / 64, BT / 128);
    gemm_bf<0><<<g576, 256>>>(h, wqkv, nullptr, nullptr, qkv, QKVN, D);
    // 5) attention
    flash_bf<<<dim3(T_SEQ / 128, NH, NB), 256>>>(qkv, o);
    // 6) Wo + residual -> x2 (f32)
    gemm_bf<1><<<g192, 256>>>(o, wo, xin, nullptr, x2, D, D);
    // 7) LN2 -> h bf16
    ln2_kernel<<<BT, 192>>>(x2, ln2_w, ln2_b);
    // 8) MLP up + GELU -> g bf16
    gemm_bf<2><<<g768, 256>>>(h, w1, nullptr, nullptr, gbuf, MLP, D);
    // 9) MLP down + residual + fused gated scatter into out
    gemm_bf<3><<<g192, 256>>>(gbuf, w2, x2, hpost, out, D, MLP);
}

// round 11
// speedup vs baseline: 6.8409x; 1.0552x over previous
#include <cuda_runtime.h>
#include <cuda_bf16.h>
#include <math.h>

#define BT 32768
#define NSTREAM 4
#define D 192
#define ND 768
#define MLP 768
#define T_SEQ 1024
#define NB 32
#define NH 3
#define HD 64
#define QKVN 576

typedef __nv_bfloat16 bf16;

// ---------------- scratch (device globals; no allocation allowed) ----------------
__device__ float g_xin[BT * D];
__device__ float g_x2[BT * D];
__device__ float g_hpost[BT * NSTREAM];
__device__ float g_tilde[BT * 24];
__device__ float g_gates[BT * 20];       // 16 hres + 4 hpre per token
__device__ float g_bias24[24];
__device__ bf16  g_streams[BT * ND];
__device__ bf16  g_h[BT * D];
__device__ bf16  g_qkv[BT * QKVN];
__device__ bf16  g_o[BT * D];
__device__ bf16  g_g[BT * MLP];
// k-pair-interleaved weights: W_p[kp][n] = pack(W[2kp][n], W[2kp+1][n])
__device__ unsigned g_wqkv_p[(D / 2) * QKVN];
__device__ unsigned g_wo_p[(D / 2) * D];
__device__ unsigned g_w1_p[(D / 2) * MLP];
__device__ unsigned g_w2_p[(MLP / 2) * D];
__device__ unsigned g_phiC_p[(ND / 2) * 64];

// ---------------- helpers ----------------
__device__ __forceinline__ unsigned pack_bf16(float lo, float hi) {
    unsigned r;
    asm("cvt.rn.bf16x2.f32 %0, %1, %2;" : "=r"(r) : "f"(hi), "f"(lo));
    return r;
}

__device__ __forceinline__ void mma_bf16(float c[4],
    unsigned a0, unsigned a1, unsigned a2, unsigned a3,
    unsigned b0, unsigned b1)
{
    asm volatile(
        "mma.sync.aligned.m16n8k16.row.col.f32.bf16.bf16.f32 "
        "{%0,%1,%2,%3}, {%4,%5,%6,%7}, {%8,%9}, {%0,%1,%2,%3};\n"
        : "+f"(c[0]), "+f"(c[1]), "+f"(c[2]), "+f"(c[3])
        : "r"(a0), "r"(a1), "r"(a2), "r"(a3), "r"(b0), "r"(b1));
}

__device__ __forceinline__ void cp16(void* smem, const void* g) {
    unsigned saddr = (unsigned)__cvta_generic_to_shared(smem);
    asm volatile("cp.async.cg.shared.global [%0], [%1], 16;\n" :: "r"(saddr), "l"(g));
}
#define CP_COMMIT() asm volatile("cp.async.commit_group;\n" ::: "memory")

__device__ __forceinline__ float frcp(float x) {
    float r;
    asm("rcp.approx.f32 %0, %1;" : "=f"(r) : "f"(x));
    return r;
}

__device__ __forceinline__ float fex2(float x) {
    float r;
    asm("ex2.approx.f32 %0, %1;" : "=f"(r) : "f"(x));
    return r;
}

__device__ __forceinline__ float tanh_ap(float x) {
    float r;
    asm("tanh.approx.f32 %0, %1;" : "=f"(r) : "f"(x));
    return r;
}

__device__ __forceinline__ float gelu_f(float x) {
    float x3 = x * x * x;
    float t = tanh_ap(0.7978845608028654f * (x + 0.044715f * x3));
    return 0.5f * x * (1.f + t);
}

// =================================================================================
// Kernel 0: weight conversion fp32 -> bf16 k-pair-interleaved (+ phi combine, bias24)
// =================================================================================
__global__ void convert_kernel(
    const float* __restrict__ Wq, const float* __restrict__ Wk,
    const float* __restrict__ Wv, const float* __restrict__ Wo,
    const float* __restrict__ W1, const float* __restrict__ W2,
    const float* __restrict__ phi_pre, const float* __restrict__ phi_post,
    const float* __restrict__ phi_res,
    const float* __restrict__ b_pre, const float* __restrict__ b_post,
    const float* __restrict__ b_res,
    const float* __restrict__ a_pre, const float* __restrict__ a_post,
    const float* __restrict__ a_res)
{
    int idx = blockIdx.x * blockDim.x + threadIdx.x;
    if (idx < (D / 2) * QKVN) {
        int kp = idx / QKVN, c = idx % QKVN;
        const float* W; int cc;
        if (c < D)          { W = Wq; cc = c; }
        else if (c < 2 * D) { W = Wk; cc = c - D; }
        else                { W = Wv; cc = c - 2 * D; }
        g_wqkv_p[idx] = pack_bf16(W[(2 * kp) * D + cc], W[(2 * kp + 1) * D + cc]);
    }
    if (idx < (D / 2) * D) {
        int kp = idx / D, c = idx % D;
        g_wo_p[idx] = pack_bf16(Wo[(2 * kp) * D + c], Wo[(2 * kp + 1) * D + c]);
    }
    if (idx < (D / 2) * MLP) {
        int kp = idx / MLP, c = idx % MLP;
        g_w1_p[idx] = pack_bf16(W1[(2 * kp) * MLP + c], W1[(2 * kp + 1) * MLP + c]);
    }
    if (idx < (MLP / 2) * D) {
        int kp = idx / D, c = idx % D;
        g_w2_p[idx] = pack_bf16(W2[(2 * kp) * D + c], W2[(2 * kp + 1) * D + c]);
    }
    if (idx < (ND / 2) * 64) {
        int kp = idx >> 6, c = idx & 63;
        float v[2];
        #pragma unroll
        for (int u = 0; u < 2; u++) {
            int d = 2 * kp + u;
            float t = 0.f;
            if (c < 4)       t = a_pre[0]  * phi_pre[d * 4 + c];
            else if (c < 8)  t = a_post[0] * phi_post[d * 4 + (c - 4)];
            else if (c < 24) t = a_res[0]  * phi_res[d * 16 + (c - 8)];
            v[u] = t;
        }
        g_phiC_p[idx] = pack_bf16(v[0], v[1]);
    }
    if (idx < 24) {
        float v;
        if (idx < 4)      v = b_pre[idx];
        else if (idx < 8) v = b_post[idx - 4];
        else              v = b_res[idx - 8];
        g_bias24[idx] = v;
    }
}

// =================================================================================
// Kernel 1: rmsnorm -> streams (bf16). One block (192 threads, float4 each) / token.
// =================================================================================
__global__ __launch_bounds__(192) void rms_kernel(
    const float* __restrict__ x, const float* __restrict__ norm_w)
{
    int tok = blockIdx.x, tid = threadIdx.x;
    int lane = tid & 31, wid = tid >> 5;
    __shared__ float red[6];
    __shared__ float s_inv;

    float4 xv = *(const float4*)(x + (size_t)tok * ND + tid * 4);
    float sq = xv.x * xv.x + xv.y * xv.y + xv.z * xv.z + xv.w * xv.w;
    #pragma unroll
    for (int o = 16; o; o >>= 1) sq += __shfl_xor_sync(~0u, sq, o);
    if (lane == 0) red[wid] = sq;
    __syncthreads();
    if (tid == 0) {
        float s = red[0] + red[1] + red[2] + red[3] + red[4] + red[5];
        s_inv = rsqrtf(s / (float)ND + 1e-8f);
    }
    __syncthreads();
    float inv = s_inv;
    float4 wv = *(const float4*)(norm_w + tid * 4);
    unsigned p0 = pack_bf16(xv.x * inv * wv.x, xv.y * inv * wv.y);
    unsigned p1 = pack_bf16(xv.z * inv * wv.z, xv.w * inv * wv.w);
    *(uint2*)((unsigned*)g_streams + (size_t)tok * (ND / 2) + tid * 2) = make_uint2(p0, p1);
}

// =================================================================================
// Kernel 2: bf16 tensor-core GEMM, cp.async 2-stage pipeline.
// BM=128 BN=64 BK=32, 256 threads, 8 warps. B passed pre-interleaved (k-pairs).
// EPI: 0 plain->bf16, 1 +Res->f32, 2 gelu->bf16,
//      3 final: out = x_res(from Xorig+gates) + (acc+Res)*hpost  [pure write]
//      4 tilde (f32, cols<24, +bias24)
// =================================================================================
template <int EPI>
__global__ __launch_bounds__(256) void gemm_bf(
    const bf16* __restrict__ A, const unsigned* __restrict__ Bp,
    const float* __restrict__ Res, const float* __restrict__ hpost,
    const float* __restrict__ Xorig,
    void* __restrict__ Cv, int N, int K)
{
    __shared__ __align__(16) unsigned Asp[2][128][20];  // [m][kpair], (20g+tig) CF
    __shared__ __align__(16) unsigned Bsp[2][16][72];   // [kpair][n], (8tig+g) CF

    int tid = threadIdx.x;
    int wid = tid >> 5, lane = tid & 31;
    int g = lane >> 2, tig = lane & 3;
    int wm = wid & 3, wn = wid >> 2;     // 4 x 2 warp grid
    int bm = blockIdx.y, bn = blockIdx.x;

    float acc[2][4][4] = {};

    int ar = tid >> 1, acp = (tid & 1) * 8;   // A: row, pair-col base
    int bkp = tid >> 4, bc = (tid & 15) * 4;  // B: pair-row, col base

    const bf16* Abase = A + (size_t)(bm * 128 + ar) * K + acp * 2;
    const unsigned* Bbase = Bp + (size_t)bkp * N + bn * 64 + bc;

    // prefetch stage 0
    cp16(&Asp[0][ar][acp],     Abase);
    cp16(&Asp[0][ar][acp + 4], Abase + 8);
    cp16(&Bsp[0][bkp][bc],     Bbase);
    CP_COMMIT();

    int nk = K >> 5;
    for (int it = 0; it < nk; it++) {
        if (it + 1 < nk) {
            int st = (it + 1) & 1;
            cp16(&Asp[st][ar][acp],     Abase + (it + 1) * 32);
            cp16(&Asp[st][ar][acp + 4], Abase + (it + 1) * 32 + 8);
            cp16(&Bsp[st][bkp][bc],     Bbase + (size_t)16 * (it + 1) * N);
            CP_COMMIT();
            asm volatile("cp.async.wait_group 1;\n" ::: "memory");
        } else {
            asm volatile("cp.async.wait_group 0;\n" ::: "memory");
        }
        __syncthreads();

        const unsigned (*As)[20] = Asp[it & 1];
        const unsigned (*Bs)[72] = Bsp[it & 1];
        #pragma unroll
        for (int ks = 0; ks < 2; ks++) {
            int kp0 = ks * 8;
            unsigned a[2][4], b[4][2];
            #pragma unroll
            for (int mt = 0; mt < 2; mt++) {
                int m0 = wm * 32 + mt * 16;
                a[mt][0] = As[m0 + g][kp0 + tig];
                a[mt][1] = As[m0 + g + 8][kp0 + tig];
                a[mt][2] = As[m0 + g][kp0 + tig + 4];
                a[mt][3] = As[m0 + g + 8][kp0 + tig + 4];
            }
            #pragma unroll
            for (int nt = 0; nt < 4; nt++) {
                int n0 = wn * 32 + nt * 8;
                b[nt][0] = Bs[kp0 + tig][n0 + g];
                b[nt][1] = Bs[kp0 + tig + 4][n0 + g];
            }
            #pragma unroll
            for (int mt = 0; mt < 2; mt++)
                #pragma unroll
                for (int nt = 0; nt < 4; nt++)
                    mma_bf16(acc[mt][nt], a[mt][0], a[mt][1], a[mt][2], a[mt][3],
                             b[nt][0], b[nt][1]);
        }
        __syncthreads();
    }

    #pragma unroll
    for (int mt = 0; mt < 2; mt++) {
        #pragma unroll
        for (int half = 0; half < 2; half++) {
            int row = bm * 128 + wm * 32 + mt * 16 + g + half * 8;

            float4 hr0, hr1, hr2, hr3, hps;
            if (EPI == 3) {
                const float4* gp4 = (const float4*)(g_gates + (size_t)row * 20);
                hr0 = gp4[0]; hr1 = gp4[1]; hr2 = gp4[2]; hr3 = gp4[3];
                hps = *(const float4*)(hpost + (size_t)row * 4);
            }

            #pragma unroll
            for (int nt = 0; nt < 4; nt++) {
                int col = bn * 64 + wn * 32 + nt * 8 + tig * 2;
                float v0 = acc[mt][nt][half * 2 + 0];
                float v1 = acc[mt][nt][half * 2 + 1];
                if (EPI == 0) {
                    bf16* C = (bf16*)Cv;
                    *(unsigned*)(C + (size_t)row * N + col) = pack_bf16(v0, v1);
                } else if (EPI == 1) {
                    float* C = (float*)Cv;
                    float2 r = *(const float2*)(Res + (size_t)row * N + col);
                    *(float2*)(C + (size_t)row * N + col) = make_float2(v0 + r.x, v1 + r.y);
                } else if (EPI == 2) {
                    bf16* C = (bf16*)Cv;
                    *(unsigned*)(C + (size_t)row * N + col) = pack_bf16(gelu_f(v0), gelu_f(v1));
                } else if (EPI == 3) {
                    float* C = (float*)Cv;
                    float2 r = *(const float2*)(Res + (size_t)row * N + col);
                    float vx = v0 + r.x, vy = v1 + r.y;
                    const float* xr = Xorig + (size_t)row * ND + col;
                    float2 xj0 = *(const float2*)(xr);
                    float2 xj1 = *(const float2*)(xr + D);
                    float2 xj2 = *(const float2*)(xr + 2 * D);
                    float2 xj3 = *(const float2*)(xr + 3 * D);
                    float* op = C + (size_t)row * ND + col;
                    float ox, oy;
                    ox = hr0.x * xj0.x + hr0.y * xj1.x + hr0.z * xj2.x + hr0.w * xj3.x + vx * hps.x;
                    oy = hr0.x * xj0.y + hr0.y * xj1.y + hr0.z * xj2.y + hr0.w * xj3.y + vy * hps.x;
                    *(float2*)(op) = make_float2(ox, oy);
                    ox = hr1.x * xj0.x + hr1.y * xj1.x + hr1.z * xj2.x + hr1.w * xj3.x + vx * hps.y;
                    oy = hr1.x * xj0.y + hr1.y * xj1.y + hr1.z * xj2.y + hr1.w * xj3.y + vy * hps.y;
                    *(float2*)(op + D) = make_float2(ox, oy);
                    ox = hr2.x * xj0.x + hr2.y * xj1.x + hr2.z * xj2.x + hr2.w * xj3.x + vx * hps.z;
                    oy = hr2.x * xj0.y + hr2.y * xj1.y + hr2.z * xj2.y + hr2.w * xj3.y + vy * hps.z;
                    *(float2*)(op + 2 * D) = make_float2(ox, oy);
                    ox = hr3.x * xj0.x + hr3.y * xj1.x + hr3.z * xj2.x + hr3.w * xj3.x + vx * hps.w;
                    oy = hr3.x * xj0.y + hr3.y * xj1.y + hr3.z * xj2.y + hr3.w * xj3.y + vy * hps.w;
                    *(float2*)(op + 3 * D) = make_float2(ox, oy);
                } else { // EPI == 4: tilde (width 24), add bias24
                    if (wn == 0 && nt < 3) {
                        float* C = (float*)Cv;
                        float2 bv = *(const float2*)(g_bias24 + col);
                        *(float2*)(C + (size_t)row * 24 + col) = make_float2(v0 + bv.x, v1 + bv.y);
                    }
                }
            }
        }
    }
}

// =================================================================================
// Kernel 3a: gates kernel. TWO tokens per thread (ILP hides serial sinkhorn chain).
// =================================================================================
__global__ __launch_bounds__(128) void gates_kernel(float* __restrict__ hpost)
{
    __shared__ float sm[256 * 25];
    int tid = threadIdx.x;
    size_t b0 = (size_t)blockIdx.x * 256;

    for (int i = tid; i < 256 * 24; i += 128) {
        int t = i / 24, e = i - t * 24;
        sm[t * 25 + e] = g_tilde[b0 * 24 + i];
    }
    __syncthreads();

    #pragma unroll
    for (int u = 0; u < 1; u++) {} // keep structure simple

    size_t tok0 = b0 + tid, tok1 = b0 + 128 + tid;
    const float* tlA = &sm[tid * 25];
    const float* tlB = &sm[(128 + tid) * 25];

    float hpA[4], hpB[4];
    #pragma unroll
    for (int j = 0; j < 4; j++) {
        hpA[j] = frcp(1.f + fex2(-1.44269504f * tlA[j]));
        hpB[j] = frcp(1.f + fex2(-1.44269504f * tlB[j]));
    }
    float4 h4A, h4B;
    h4A.x = 2.f * frcp(1.f + fex2(-1.44269504f * tlA[4]));
    h4A.y = 2.f * frcp(1.f + fex2(-1.44269504f * tlA[5]));
    h4A.z = 2.f * frcp(1.f + fex2(-1.44269504f * tlA[6]));
    h4A.w = 2.f * frcp(1.f + fex2(-1.44269504f * tlA[7]));
    h4B.x = 2.f * frcp(1.f + fex2(-1.44269504f * tlB[4]));
    h4B.y = 2.f * frcp(1.f + fex2(-1.44269504f * tlB[5]));
    h4B.z = 2.f * frcp(1.f + fex2(-1.44269504f * tlB[6]));
    h4B.w = 2.f * frcp(1.f + fex2(-1.44269504f * tlB[7]));
    *(float4*)(hpost + tok0 * 4) = h4A;
    *(float4*)(hpost + tok1 * 4) = h4B;

    float mA[16], mB[16];
    float mxA = tlA[8], mxB = tlB[8];
    #pragma unroll
    for (int j = 1; j < 16; j++) {
        mxA = fmaxf(mxA, tlA[8 + j]);
        mxB = fmaxf(mxB, tlB[8 + j]);
    }
    #pragma unroll
    for (int j = 0; j < 16; j++) {
        mA[j] = fex2(1.44269504f * (tlA[8 + j] - mxA));
        mB[j] = fex2(1.44269504f * (tlB[8 + j] - mxB));
    }

    #pragma unroll 1
    for (int it = 0; it < 20; it++) {
        #pragma unroll
        for (int i = 0; i < 4; i++) {
            float rsA = mA[4 * i] + mA[4 * i + 1] + mA[4 * i + 2] + mA[4 * i + 3];
            float rsB = mB[4 * i] + mB[4 * i + 1] + mB[4 * i + 2] + mB[4 * i + 3];
            float invA = frcp(rsA + 1e-8f);
            float invB = frcp(rsB + 1e-8f);
            mA[4 * i] *= invA; mA[4 * i + 1] *= invA; mA[4 * i + 2] *= invA; mA[4 * i + 3] *= invA;
            mB[4 * i] *= invB; mB[4 * i + 1] *= invB; mB[4 * i + 2] *= invB; mB[4 * i + 3] *= invB;
        }
        #pragma unroll
        for (int j = 0; j < 4; j++) {
            float csA = mA[j] + mA[4 + j] + mA[8 + j] + mA[12 + j];
            float csB = mB[j] + mB[4 + j] + mB[8 + j] + mB[12 + j];
            float invA = frcp(csA + 1e-8f);
            float invB = frcp(csB + 1e-8f);
            mA[j] *= invA; mA[4 + j] *= invA; mA[8 + j] *= invA; mA[12 + j] *= invA;
            mB[j] *= invB; mB[4 + j] *= invB; mB[8 + j] *= invB; mB[12 + j] *= invB;
        }
    }

    float* gpA = g_gates + tok0 * 20;
    *(float4*)(gpA + 0)  = make_float4(mA[0], mA[1], mA[2], mA[3]);
    *(float4*)(gpA + 4)  = make_float4(mA[4], mA[5], mA[6], mA[7]);
    *(float4*)(gpA + 8)  = make_float4(mA[8], mA[9], mA[10], mA[11]);
    *(float4*)(gpA + 12) = make_float4(mA[12], mA[13], mA[14], mA[15]);
    *(float4*)(gpA + 16) = make_float4(hpA[0], hpA[1], hpA[2], hpA[3]);
    float* gpB = g_gates + tok1 * 20;
    *(float4*)(gpB + 0)  = make_float4(mB[0], mB[1], mB[2], mB[3]);
    *(float4*)(gpB + 4)  = make_float4(mB[4], mB[5], mB[6], mB[7]);
    *(float4*)(gpB + 8)  = make_float4(mB[8], mB[9], mB[10], mB[11]);
    *(float4*)(gpB + 12) = make_float4(mB[12], mB[13], mB[14], mB[15]);
    *(float4*)(gpB + 16) = make_float4(hpB[0], hpB[1], hpB[2], hpB[3]);
}

// =================================================================================
// Kernel 3b: stream mixing + fused LN1. 1 warp/token, 8 tok/block.
// Writes xin (f32) + h (bf16) only — x_res moved to MLP-down epilogue.
// =================================================================================
__global__ __launch_bounds__(256) void sinkmix_kernel(
    const float* __restrict__ x,
    const float* __restrict__ ln1_w, const float* __restrict__ ln1_b,
    float* __restrict__ xin)
{
    int wid = threadIdx.x >> 5, lane = threadIdx.x & 31;
    int tok = blockIdx.x * 8 + wid;

    float gv = (lane < 4) ? g_gates[(size_t)tok * 20 + 16 + lane] : 0.f;
    float hp[4];
    #pragma unroll
    for (int i = 0; i < 4; i++) hp[i] = __shfl_sync(~0u, gv, i);

    const float* xrow = x + (size_t)tok * ND;
    float xi_c[6];
    float sum = 0.f, sumsq = 0.f;
    #pragma unroll
    for (int c = 0; c < 6; c++) {
        int dd = c * 32 + lane;
        float x0 = xrow[dd], x1 = xrow[D + dd], x2v = xrow[2 * D + dd], x3 = xrow[3 * D + dd];
        float xi = hp[0] * x0 + hp[1] * x1 + hp[2] * x2v + hp[3] * x3;
        xin[(size_t)tok * D + dd] = xi;
        xi_c[c] = xi;
        sum += xi; sumsq += xi * xi;
    }
    #pragma unroll
    for (int o = 16; o; o >>= 1) {
        sum += __shfl_xor_sync(~0u, sum, o);
        sumsq += __shfl_xor_sync(~0u, sumsq, o);
    }
    float mean = sum / (float)D;
    float var = sumsq / (float)D - mean * mean;
    float invstd = rsqrtf(var + 1e-5f);
    #pragma unroll
    for (int c = 0; c < 6; c++) {
        int dd = c * 32 + lane;
        float hv = (xi_c[c] - mean) * invstd * ln1_w[dd] + ln1_b[dd];
        g_h[(size_t)tok * D + dd] = __float2bfloat16(hv);
    }
}

// =================================================================================
// Kernel 4: LayerNorm (x2 f32 -> h bf16). One block (192 threads) per token.
// =================================================================================
__global__ __launch_bounds__(192) void ln2_kernel(
    const float* __restrict__ in, const float* __restrict__ w,
    const float* __restrict__ b)
{
    int tok = blockIdx.x, tid = threadIdx.x;
    int lane = tid & 31, wid = tid >> 5;
    __shared__ float red[6];
    __shared__ float s_mean, s_invstd;

    float v = in[(size_t)tok * D + tid];
    float sm = v;
    #pragma unroll
    for (int o = 16; o; o >>= 1) sm += __shfl_xor_sync(~0u, sm, o);
    if (lane == 0) red[wid] = sm;
    __syncthreads();
    if (tid == 0) {
        float s = red[0] + red[1] + red[2] + red[3] + red[4] + red[5];
        s_mean = s / (float)D;
    }
    __syncthreads();
    float dv = v - s_mean;
    float sq = dv * dv;
    #pragma unroll
    for (int o = 16; o; o >>= 1) sq += __shfl_xor_sync(~0u, sq, o);
    __syncthreads();
    if (lane == 0) red[wid] = sq;
    __syncthreads();
    if (tid == 0) {
        float s = red[0] + red[1] + red[2] + red[3] + red[4] + red[5];
        s_invstd = rsqrtf(s / (float)D + 1e-5f);
    }
    __syncthreads();
    g_h[(size_t)tok * D + tid] = __float2bfloat16(dv * s_invstd * w[tid] + b[tid]);
}

// =================================================================================
// Kernel 5: bf16 flash attention. BQ=128, BKEY=64, HD=64, 256 threads (8 warps).
// P stays in registers (C-frag of QK^T == A-frag of PV). Register K/V prefetch.
// Softmax in exp2 domain (scale folded into log2e).
// =================================================================================
__global__ __launch_bounds__(256, 2) void flash_bf(
    const bf16* __restrict__ QKV, bf16* __restrict__ O)
{
    __shared__ __align__(16) unsigned Qsp[128][36];  // [q][dpair]   (4g+tig) CF
    __shared__ __align__(16) unsigned Ksp[64][36];   // [key][dpair] (4g+tig) CF
    __shared__ __align__(16) unsigned Vp[32][72];    // [keypair][d] (8tig+g) CF

    int tid = threadIdx.x, wid = tid >> 5, lane = tid & 31;
    int g = lane >> 2, tig = lane & 3;
    int qt = blockIdx.x, h = blockIdx.y, b = blockIdx.z;
    size_t tokbase = (size_t)b * T_SEQ;
    int qoff = h * HD, koff = D + h * HD, voff = 2 * D + h * HD;
    int m0 = wid * 16;

    int kr = tid >> 2, kcp = (tid & 3) * 8;
    int vkp = tid >> 3, vc = (tid & 7) * 8;

    {
        int r = tid >> 1, cp0 = (tid & 1) * 16;
        const uint4* qp = (const uint4*)(QKV + (tokbase + qt * 128 + r) * QKVN + qoff + cp0 * 2);
        #pragma unroll
        for (int u = 0; u < 4; u++)
            *(uint4*)&Qsp[r][cp0 + u * 4] = qp[u];
    }
    float m_prev[2] = {-1e30f, -1e30f};
    float l_run[2] = {0.f, 0.f};
    float o_acc[8][4] = {};

    uint4 kreg0, kreg1, vreg0, vreg1;
    kreg0 = *(const uint4*)(QKV + (tokbase + kr) * QKVN + koff + kcp * 2);
    kreg1 = *(const uint4*)(QKV + (tokbase + kr) * QKVN + koff + (kcp + 4) * 2);
    {
        const bf16* vb = QKV + (tokbase + 2 * vkp) * QKVN + voff + vc;
        vreg0 = *(const uint4*)vb;
        vreg1 = *(const uint4*)(vb + QKVN);
    }
    __syncthreads();

    for (int kt = 0; kt < T_SEQ; kt += 64) {
        *(uint4*)&Ksp[kr][kcp]     = kreg0;
        *(uint4*)&Ksp[kr][kcp + 4] = kreg1;
        {
            uint4 oA, oB;
            oA.x = __byte_perm(vreg0.x, vreg1.x, 0x5410); oA.y = __byte_perm(vreg0.x, vreg1.x, 0x7632);
            oA.z = __byte_perm(vreg0.y, vreg1.y, 0x5410); oA.w = __byte_perm(vreg0.y, vreg1.y, 0x7632);
            oB.x = __byte_perm(vreg0.z, vreg1.z, 0x5410); oB.y = __byte_perm(vreg0.z, vreg1.z, 0x7632);
            oB.z = __byte_perm(vreg0.w, vreg1.w, 0x5410); oB.w = __byte_perm(vreg0.w, vreg1.w, 0x7632);
            *(uint4*)&Vp[vkp][vc]     = oA;
            *(uint4*)&Vp[vkp][vc + 4] = oB;
        }
        __syncthreads();

        if (kt + 64 < T_SEQ) {
            const bf16* kb = QKV + (tokbase + kt + 64 + kr) * QKVN + koff;
            kreg0 = *(const uint4*)(kb + kcp * 2);
            kreg1 = *(const uint4*)(kb + (kcp + 4) * 2);
            const bf16* vb = QKV + (tokbase + kt + 64 + 2 * vkp) * QKVN + voff + vc;
            vreg0 = *(const uint4*)vb;
            vreg1 = *(const uint4*)(vb + QKVN);
        }

        float s[8][4] = {};
        #pragma unroll
        for (int ks = 0; ks < 4; ks++) {
            int kp0 = ks * 8;
            unsigned a0 = Qsp[m0 + g][kp0 + tig];
            unsigned a1 = Qsp[m0 + g + 8][kp0 + tig];
            unsigned a2 = Qsp[m0 + g][kp0 + tig + 4];
            unsigned a3 = Qsp[m0 + g + 8][kp0 + tig + 4];
            #pragma unroll
            for (int nt = 0; nt < 8; nt++) {
                unsigned b0 = Ksp[nt * 8 + g][kp0 + tig];
                unsigned b1 = Ksp[nt * 8 + g][kp0 + tig + 4];
                mma_bf16(s[nt], a0, a1, a2, a3, b0, b1);
            }
        }

        // online softmax in exp2 domain: sc2 = 0.125 * log2(e)
        const float sc2 = 0.125f * 1.44269504f;
        float mx0 = -1e30f, mx1 = -1e30f;
        #pragma unroll
        for (int nt = 0; nt < 8; nt++) {
            s[nt][0] *= sc2; s[nt][1] *= sc2; s[nt][2] *= sc2; s[nt][3] *= sc2;
            mx0 = fmaxf(mx0, fmaxf(s[nt][0], s[nt][1]));
            mx1 = fmaxf(mx1, fmaxf(s[nt][2], s[nt][3]));
        }
        mx0 = fmaxf(mx0, __shfl_xor_sync(~0u, mx0, 1));
        mx0 = fmaxf(mx0, __shfl_xor_sync(~0u, mx0, 2));
        mx1 = fmaxf(mx1, __shfl_xor_sync(~0u, mx1, 1));
        mx1 = fmaxf(mx1, __shfl_xor_sync(~0u, mx1, 2));
        float mn0 = fmaxf(m_prev[0], mx0);
        float mn1 = fmaxf(m_prev[1], mx1);
        float rs0 = 0.f, rs1 = 0.f;
        #pragma unroll
        for (int nt = 0; nt < 8; nt++) {
            s[nt][0] = fex2(s[nt][0] - mn0);
            s[nt][1] = fex2(s[nt][1] - mn0);
            s[nt][2] = fex2(s[nt][2] - mn1);
            s[nt][3] = fex2(s[nt][3] - mn1);
            rs0 += s[nt][0] + s[nt][1];
            rs1 += s[nt][2] + s[nt][3];
        }
        rs0 += __shfl_xor_sync(~0u, rs0, 1);
        rs0 += __shfl_xor_sync(~0u, rs0, 2);
        rs1 += __shfl_xor_sync(~0u, rs1, 1);
        rs1 += __shfl_xor_sync(~0u, rs1, 2);
        float scl0 = fex2(m_prev[0] - mn0);
        float scl1 = fex2(m_prev[1] - mn1);
        l_run[0] = l_run[0] * scl0 + rs0;
        l_run[1] = l_run[1] * scl1 + rs1;
        m_prev[0] = mn0; m_prev[1] = mn1;
        #pragma unroll
        for (int nt = 0; nt < 8; nt++) {
            o_acc[nt][0] *= scl0; o_acc[nt][1] *= scl0;
            o_acc[nt][2] *= scl1; o_acc[nt][3] *= scl1;
        }

        #pragma unroll
        for (int ks = 0; ks < 4; ks++) {
            int kp0 = ks * 8;
            unsigned a0 = pack_bf16(s[2 * ks][0],     s[2 * ks][1]);
            unsigned a1 = pack_bf16(s[2 * ks][2],     s[2 * ks][3]);
            unsigned a2 = pack_bf16(s[2 * ks + 1][0], s[2 * ks + 1][1]);
            unsigned a3 = pack_bf16(s[2 * ks + 1][2], s[2 * ks + 1][3]);
            #pragma unroll
            for (int nt = 0; nt < 8; nt++) {
                unsigned b0 = Vp[kp0 + tig][nt * 8 + g];
                unsigned b1 = Vp[kp0 + tig + 4][nt * 8 + g];
                mma_bf16(o_acc[nt], a0, a1, a2, a3, b0, b1);
            }
        }
        __syncthreads();
    }

    float inv0 = 1.f / l_run[0];
    float inv1 = 1.f / l_run[1];
    size_t obase = tokbase * D + h * HD;
    int q0 = qt * 128 + m0 + g;
    #pragma unroll
    for (int nt = 0; nt < 8; nt++) {
        int col = nt * 8 + tig * 2;
        *(unsigned*)(O + obase + (size_t)q0 * D + col) =
            pack_bf16(o_acc[nt][0] * inv0, o_acc[nt][1] * inv0);
        *(unsigned*)(O + obase + (size_t)(q0 + 8) * D + col) =
            pack_bf16(o_acc[nt][2] * inv1, o_acc[nt][3] * inv1);
    }
}

// =================================================================================
extern "C" void kernel_launch(void* const* d_in, const int* in_sizes, int n_in,
                              void* d_out, int out_size)
{
    const float* x        = (const float*)d_in[0];
    const float* norm_w   = (const float*)d_in[1];
    const float* phi_pre  = (const float*)d_in[2];
    const float* phi_post = (const float*)d_in[3];
    const float* phi_res  = (const float*)d_in[4];
    const float* b_pre    = (const float*)d_in[5];
    const float* b_post   = (const float*)d_in[6];
    const float* b_res    = (const float*)d_in[7];
    const float* a_pre    = (const float*)d_in[8];
    const float* a_post   = (const float*)d_in[9];
    const float* a_res    = (const float*)d_in[10];
    const float* ln1_w    = (const float*)d_in[11];
    const float* ln1_b    = (const float*)d_in[12];
    const float* Wq       = (const float*)d_in[13];
    const float* Wk       = (const float*)d_in[14];
    const float* Wv       = (const float*)d_in[15];
    const float* Wo       = (const float*)d_in[16];
    const float* ln2_w    = (const float*)d_in[17];
    const float* ln2_b    = (const float*)d_in[18];
    const float* W1       = (const float*)d_in[19];
    const float* W2       = (const float*)d_in[20];
    float* out = (float*)d_out;

    void *p;
    cudaGetSymbolAddress(&p, g_xin);     float* xin       = (float*)p;
    cudaGetSymbolAddress(&p, g_x2);      float* x2        = (float*)p;
    cudaGetSymbolAddress(&p, g_hpost);   float* hpost     = (float*)p;
    cudaGetSymbolAddress(&p, g_tilde);   float* tilde     = (float*)p;
    cudaGetSymbolAddress(&p, g_streams); bf16* streams    = (bf16*)p;
    cudaGetSymbolAddress(&p, g_h);       bf16* h          = (bf16*)p;
    cudaGetSymbolAddress(&p, g_qkv);     bf16* qkv        = (bf16*)p;
    cudaGetSymbolAddress(&p, g_o);       bf16* o          = (bf16*)p;
    cudaGetSymbolAddress(&p, g_g);       bf16* gbuf       = (bf16*)p;
    cudaGetSymbolAddress(&p, g_wqkv_p);  unsigned* wqkv   = (unsigned*)p;
    cudaGetSymbolAddress(&p, g_wo_p);    unsigned* wo     = (unsigned*)p;
    cudaGetSymbolAddress(&p, g_w1_p);    unsigned* w1     = (unsigned*)p;
    cudaGetSymbolAddress(&p, g_w2_p);    unsigned* w2     = (unsigned*)p;
    cudaGetSymbolAddress(&p, g_phiC_p);  unsigned* phiC   = (unsigned*)p;

    // 0) weight conversion (k-pair interleaved)
    convert_kernel<<<288, 256>>>(Wq, Wk, Wv, Wo, W1, W2, phi_pre, phi_post, phi_res,
                                 b_pre, b_post, b_res, a_pre, a_post, a_res);
    // 1) rmsnorm -> streams bf16
    rms_kernel<<<BT, 192>>>(x, norm_w);
    // 2) projections -> tilde (+bias)
    gemm_bf<4><<<dim3(1, BT / 128), 256>>>(streams, phiC, nullptr, nullptr, nullptr, tilde, 64, ND);
    // 3a) sigmoid + sinkhorn (two tokens per thread) -> gates, hpost
    gates_kernel<<<BT / 256, 128>>>(hpost);
    // 3b) mix + LN1 -> xin, h
    sinkmix_kernel<<<BT / 8, 256>>>(x, ln1_w, ln1_b, xin);
    // 4) fused QKV
    dim3 g192(D / 64, BT / 128), g576(QKVN / 64, BT / 128), g768(MLP / 64, BT / 128);
    gemm_bf<0><<<g576, 256>>>(h, wqkv, nullptr, nullptr, nullptr, qkv, QKVN, D);
    // 5) attention
    flash_bf<<<dim3(T_SEQ / 128, NH, NB), 256>>>(qkv, o);
    // 6) Wo + residual -> x2 (f32)
    gemm_bf<1><<<g192, 256>>>(o, wo, xin, nullptr, nullptr, x2, D, D);
    // 7) LN2 -> h bf16
    ln2_kernel<<<BT, 192>>>(x2, ln2_w, ln2_b);
    // 8) MLP up + GELU -> g bf16
    gemm_bf<2><<<g768, 256>>>(h, w1, nullptr, nullptr, nullptr, gbuf, MLP, D);
    // 9) MLP down + x2 residual + x_res (from x,gates) + gated scatter -> out (pure write)
    gemm_bf<3><<<g192, 256>>>(gbuf, w2, x2, hpost, x, out, D, MLP);
}

// round 12
// speedup vs baseline: 7.0697x; 1.0334x over previous
#include <cuda_runtime.h>
#include <cuda_bf16.h>
#include <math.h>

#define BT 32768
#define NSTREAM 4
#define D 192
#define ND 768
#define MLP 768
#define T_SEQ 1024
#define NB 32
#define NH 3
#define HD 64
#define QKVN 576

typedef __nv_bfloat16 bf16;

// ---------------- scratch (device globals; no allocation allowed) ----------------
__device__ float g_xin[BT * D];
__device__ float g_x2[BT * D];
__device__ float g_hpost[BT * NSTREAM];
__device__ float g_gates[BT * 20];       // 16 hres + 4 hpre per token
__device__ float g_bias24[24];
__device__ bf16  g_streams[BT * ND];
__device__ bf16  g_h[BT * D];
__device__ bf16  g_qkv[BT * QKVN];
__device__ bf16  g_o[BT * D];
__device__ bf16  g_g[BT * MLP];
// k-pair-interleaved weights: W_p[kp][n] = pack(W[2kp][n], W[2kp+1][n])
__device__ unsigned g_wqkv_p[(D / 2) * QKVN];
__device__ unsigned g_wo_p[(D / 2) * D];
__device__ unsigned g_w1_p[(D / 2) * MLP];
__device__ unsigned g_w2_p[(MLP / 2) * D];
__device__ unsigned g_phiC_p[(ND / 2) * 64];

// ---------------- helpers ----------------
__device__ __forceinline__ unsigned pack_bf16(float lo, float hi) {
    unsigned r;
    asm("cvt.rn.bf16x2.f32 %0, %1, %2;" : "=r"(r) : "f"(hi), "f"(lo));
    return r;
}

__device__ __forceinline__ void mma_bf16(float c[4],
    unsigned a0, unsigned a1, unsigned a2, unsigned a3,
    unsigned b0, unsigned b1)
{
    asm volatile(
        "mma.sync.aligned.m16n8k16.row.col.f32.bf16.bf16.f32 "
        "{%0,%1,%2,%3}, {%4,%5,%6,%7}, {%8,%9}, {%0,%1,%2,%3};\n"
        : "+f"(c[0]), "+f"(c[1]), "+f"(c[2]), "+f"(c[3])
        : "r"(a0), "r"(a1), "r"(a2), "r"(a3), "r"(b0), "r"(b1));
}

__device__ __forceinline__ void cp16(void* smem, const void* g) {
    unsigned saddr = (unsigned)__cvta_generic_to_shared(smem);
    asm volatile("cp.async.cg.shared.global [%0], [%1], 16;\n" :: "r"(saddr), "l"(g));
}
#define CP_COMMIT() asm volatile("cp.async.commit_group;\n" ::: "memory")

__device__ __forceinline__ float frcp(float x) {
    float r;
    asm("rcp.approx.f32 %0, %1;" : "=f"(r) : "f"(x));
    return r;
}

__device__ __forceinline__ float fex2(float x) {
    float r;
    asm("ex2.approx.f32 %0, %1;" : "=f"(r) : "f"(x));
    return r;
}

__device__ __forceinline__ float tanh_ap(float x) {
    float r;
    asm("tanh.approx.f32 %0, %1;" : "=f"(r) : "f"(x));
    return r;
}

__device__ __forceinline__ float gelu_f(float x) {
    float x3 = x * x * x;
    float t = tanh_ap(0.7978845608028654f * (x + 0.044715f * x3));
    return 0.5f * x * (1.f + t);
}

// =================================================================================
// Kernel 0: weight conversion fp32 -> bf16 k-pair-interleaved (+ phi combine, bias24)
// =================================================================================
__global__ void convert_kernel(
    const float* __restrict__ Wq, const float* __restrict__ Wk,
    const float* __restrict__ Wv, const float* __restrict__ Wo,
    const float* __restrict__ W1, const float* __restrict__ W2,
    const float* __restrict__ phi_pre, const float* __restrict__ phi_post,
    const float* __restrict__ phi_res,
    const float* __restrict__ b_pre, const float* __restrict__ b_post,
    const float* __restrict__ b_res,
    const float* __restrict__ a_pre, const float* __restrict__ a_post,
    const float* __restrict__ a_res)
{
    int idx = blockIdx.x * blockDim.x + threadIdx.x;
    if (idx < (D / 2) * QKVN) {
        int kp = idx / QKVN, c = idx % QKVN;
        const float* W; int cc;
        if (c < D)          { W = Wq; cc = c; }
        else if (c < 2 * D) { W = Wk; cc = c - D; }
        else                { W = Wv; cc = c - 2 * D; }
        g_wqkv_p[idx] = pack_bf16(W[(2 * kp) * D + cc], W[(2 * kp + 1) * D + cc]);
    }
    if (idx < (D / 2) * D) {
        int kp = idx / D, c = idx % D;
        g_wo_p[idx] = pack_bf16(Wo[(2 * kp) * D + c], Wo[(2 * kp + 1) * D + c]);
    }
    if (idx < (D / 2) * MLP) {
        int kp = idx / MLP, c = idx % MLP;
        g_w1_p[idx] = pack_bf16(W1[(2 * kp) * MLP + c], W1[(2 * kp + 1) * MLP + c]);
    }
    if (idx < (MLP / 2) * D) {
        int kp = idx / D, c = idx % D;
        g_w2_p[idx] = pack_bf16(W2[(2 * kp) * D + c], W2[(2 * kp + 1) * D + c]);
    }
    if (idx < (ND / 2) * 64) {
        int kp = idx >> 6, c = idx & 63;
        float v[2];
        #pragma unroll
        for (int u = 0; u < 2; u++) {
            int d = 2 * kp + u;
            float t = 0.f;
            if (c < 4)       t = a_pre[0]  * phi_pre[d * 4 + c];
            else if (c < 8)  t = a_post[0] * phi_post[d * 4 + (c - 4)];
            else if (c < 24) t = a_res[0]  * phi_res[d * 16 + (c - 8)];
            v[u] = t;
        }
        g_phiC_p[idx] = pack_bf16(v[0], v[1]);
    }
    if (idx < 24) {
        float v;
        if (idx < 4)      v = b_pre[idx];
        else if (idx < 8) v = b_post[idx - 4];
        else              v = b_res[idx - 8];
        g_bias24[idx] = v;
    }
}

// =================================================================================
// Kernel 1: rmsnorm -> streams (bf16). One block (192 threads, float4 each) / token.
// =================================================================================
__global__ __launch_bounds__(192) void rms_kernel(
    const float* __restrict__ x, const float* __restrict__ norm_w)
{
    int tok = blockIdx.x, tid = threadIdx.x;
    int lane = tid & 31, wid = tid >> 5;
    __shared__ float red[6];
    __shared__ float s_inv;

    float4 xv = *(const float4*)(x + (size_t)tok * ND + tid * 4);
    float sq = xv.x * xv.x + xv.y * xv.y + xv.z * xv.z + xv.w * xv.w;
    #pragma unroll
    for (int o = 16; o; o >>= 1) sq += __shfl_xor_sync(~0u, sq, o);
    if (lane == 0) red[wid] = sq;
    __syncthreads();
    if (tid == 0) {
        float s = red[0] + red[1] + red[2] + red[3] + red[4] + red[5];
        s_inv = rsqrtf(s / (float)ND + 1e-8f);
    }
    __syncthreads();
    float inv = s_inv;
    float4 wv = *(const float4*)(norm_w + tid * 4);
    unsigned p0 = pack_bf16(xv.x * inv * wv.x, xv.y * inv * wv.y);
    unsigned p1 = pack_bf16(xv.z * inv * wv.z, xv.w * inv * wv.w);
    *(uint2*)((unsigned*)g_streams + (size_t)tok * (ND / 2) + tid * 2) = make_uint2(p0, p1);
}

// =================================================================================
// Kernel 2: bf16 tensor-core GEMM, cp.async 2-stage pipeline.
// BM=128 BN=64 BK=32, 256 threads, 8 warps. B passed pre-interleaved (k-pairs).
// EPI: 0 plain->bf16, 1 +Res->f32, 2 gelu->bf16,
//      3 final: out = x_res(from Xorig+gates) + (acc+Res)*hpost  [pure write]
//      4 fused gates: tilde -> sigmoids + sinkhorn -> g_gates, hpost (no Cv write)
// =================================================================================
template <int EPI>
__global__ __launch_bounds__(256) void gemm_bf(
    const bf16* __restrict__ A, const unsigned* __restrict__ Bp,
    const float* __restrict__ Res, float* __restrict__ hpost,
    const float* __restrict__ Xorig,
    void* __restrict__ Cv, int N, int K)
{
    __shared__ __align__(16) unsigned Asp[2][128][20];  // [m][kpair], (20g+tig) CF
    __shared__ __align__(16) unsigned Bsp[2][16][72];   // [kpair][n], (8tig+g) CF

    int tid = threadIdx.x;
    int wid = tid >> 5, lane = tid & 31;
    int g = lane >> 2, tig = lane & 3;
    int wm = wid & 3, wn = wid >> 2;     // 4 x 2 warp grid
    int bm = blockIdx.y, bn = blockIdx.x;

    float acc[2][4][4] = {};

    int ar = tid >> 1, acp = (tid & 1) * 8;   // A: row, pair-col base
    int bkp = tid >> 4, bc = (tid & 15) * 4;  // B: pair-row, col base

    const bf16* Abase = A + (size_t)(bm * 128 + ar) * K + acp * 2;
    const unsigned* Bbase = Bp + (size_t)bkp * N + bn * 64 + bc;

    // prefetch stage 0
    cp16(&Asp[0][ar][acp],     Abase);
    cp16(&Asp[0][ar][acp + 4], Abase + 8);
    cp16(&Bsp[0][bkp][bc],     Bbase);
    CP_COMMIT();

    int nk = K >> 5;
    for (int it = 0; it < nk; it++) {
        if (it + 1 < nk) {
            int st = (it + 1) & 1;
            cp16(&Asp[st][ar][acp],     Abase + (it + 1) * 32);
            cp16(&Asp[st][ar][acp + 4], Abase + (it + 1) * 32 + 8);
            cp16(&Bsp[st][bkp][bc],     Bbase + (size_t)16 * (it + 1) * N);
            CP_COMMIT();
            asm volatile("cp.async.wait_group 1;\n" ::: "memory");
        } else {
            asm volatile("cp.async.wait_group 0;\n" ::: "memory");
        }
        __syncthreads();

        const unsigned (*As)[20] = Asp[it & 1];
        const unsigned (*Bs)[72] = Bsp[it & 1];
        #pragma unroll
        for (int ks = 0; ks < 2; ks++) {
            int kp0 = ks * 8;
            unsigned a[2][4], b[4][2];
            #pragma unroll
            for (int mt = 0; mt < 2; mt++) {
                int m0 = wm * 32 + mt * 16;
                a[mt][0] = As[m0 + g][kp0 + tig];
                a[mt][1] = As[m0 + g + 8][kp0 + tig];
                a[mt][2] = As[m0 + g][kp0 + tig + 4];
                a[mt][3] = As[m0 + g + 8][kp0 + tig + 4];
            }
            #pragma unroll
            for (int nt = 0; nt < 4; nt++) {
                int n0 = wn * 32 + nt * 8;
                b[nt][0] = Bs[kp0 + tig][n0 + g];
                b[nt][1] = Bs[kp0 + tig + 4][n0 + g];
            }
            #pragma unroll
            for (int mt = 0; mt < 2; mt++)
                #pragma unroll
                for (int nt = 0; nt < 4; nt++)
                    mma_bf16(acc[mt][nt], a[mt][0], a[mt][1], a[mt][2], a[mt][3],
                             b[nt][0], b[nt][1]);
        }
        __syncthreads();
    }

    if (EPI == 4) {
        // ---- fused gates: stage tilde in smem, then per-thread sinkhorn ----
        __shared__ float tl[128][25];
        #pragma unroll
        for (int mt = 0; mt < 2; mt++) {
            #pragma unroll
            for (int half = 0; half < 2; half++) {
                if (wn == 0) {
                    int rl = wm * 32 + mt * 16 + half * 8 + g;
                    #pragma unroll
                    for (int nt = 0; nt < 3; nt++) {
                        int col = nt * 8 + tig * 2;
                        tl[rl][col]     = acc[mt][nt][half * 2 + 0] + g_bias24[col];
                        tl[rl][col + 1] = acc[mt][nt][half * 2 + 1] + g_bias24[col + 1];
                    }
                }
            }
        }
        __syncthreads();
        if (tid < 128) {
            size_t tok = (size_t)bm * 128 + tid;
            const float* t = tl[tid];

            float hp[4];
            #pragma unroll
            for (int j = 0; j < 4; j++) hp[j] = frcp(1.f + fex2(-1.44269504f * t[j]));
            float4 h4;
            h4.x = 2.f * frcp(1.f + fex2(-1.44269504f * t[4]));
            h4.y = 2.f * frcp(1.f + fex2(-1.44269504f * t[5]));
            h4.z = 2.f * frcp(1.f + fex2(-1.44269504f * t[6]));
            h4.w = 2.f * frcp(1.f + fex2(-1.44269504f * t[7]));
            *(float4*)(hpost + tok * 4) = h4;

            float m[16];
            float mx = t[8];
            #pragma unroll
            for (int j = 1; j < 16; j++) mx = fmaxf(mx, t[8 + j]);
            #pragma unroll
            for (int j = 0; j < 16; j++) m[j] = fex2(1.44269504f * (t[8 + j] - mx));

            #pragma unroll 1
            for (int it2 = 0; it2 < 20; it2++) {
                #pragma unroll
                for (int i = 0; i < 4; i++) {
                    float rs = m[4 * i] + m[4 * i + 1] + m[4 * i + 2] + m[4 * i + 3];
                    float inv = frcp(rs + 1e-8f);
                    m[4 * i] *= inv; m[4 * i + 1] *= inv; m[4 * i + 2] *= inv; m[4 * i + 3] *= inv;
                }
                #pragma unroll
                for (int j = 0; j < 4; j++) {
                    float cs = m[j] + m[4 + j] + m[8 + j] + m[12 + j];
                    float inv = frcp(cs + 1e-8f);
                    m[j] *= inv; m[4 + j] *= inv; m[8 + j] *= inv; m[12 + j] *= inv;
                }
            }

            float* gp = g_gates + tok * 20;
            *(float4*)(gp + 0)  = make_float4(m[0], m[1], m[2], m[3]);
            *(float4*)(gp + 4)  = make_float4(m[4], m[5], m[6], m[7]);
            *(float4*)(gp + 8)  = make_float4(m[8], m[9], m[10], m[11]);
            *(float4*)(gp + 12) = make_float4(m[12], m[13], m[14], m[15]);
            *(float4*)(gp + 16) = make_float4(hp[0], hp[1], hp[2], hp[3]);
        }
        return;
    }

    #pragma unroll
    for (int mt = 0; mt < 2; mt++) {
        #pragma unroll
        for (int half = 0; half < 2; half++) {
            int row = bm * 128 + wm * 32 + mt * 16 + g + half * 8;

            float4 hr0, hr1, hr2, hr3, hps;
            if (EPI == 3) {
                const float4* gp4 = (const float4*)(g_gates + (size_t)row * 20);
                hr0 = gp4[0]; hr1 = gp4[1]; hr2 = gp4[2]; hr3 = gp4[3];
                hps = *(const float4*)(hpost + (size_t)row * 4);
            }

            #pragma unroll
            for (int nt = 0; nt < 4; nt++) {
                int col = bn * 64 + wn * 32 + nt * 8 + tig * 2;
                float v0 = acc[mt][nt][half * 2 + 0];
                float v1 = acc[mt][nt][half * 2 + 1];
                if (EPI == 0) {
                    bf16* C = (bf16*)Cv;
                    *(unsigned*)(C + (size_t)row * N + col) = pack_bf16(v0, v1);
                } else if (EPI == 1) {
                    float* C = (float*)Cv;
                    float2 r = *(const float2*)(Res + (size_t)row * N + col);
                    *(float2*)(C + (size_t)row * N + col) = make_float2(v0 + r.x, v1 + r.y);
                } else if (EPI == 2) {
                    bf16* C = (bf16*)Cv;
                    *(unsigned*)(C + (size_t)row * N + col) = pack_bf16(gelu_f(v0), gelu_f(v1));
                } else if (EPI == 3) {
                    float* C = (float*)Cv;
                    float2 r = *(const float2*)(Res + (size_t)row * N + col);
                    float vx = v0 + r.x, vy = v1 + r.y;
                    const float* xr = Xorig + (size_t)row * ND + col;
                    float2 xj0 = *(const float2*)(xr);
                    float2 xj1 = *(const float2*)(xr + D);
                    float2 xj2 = *(const float2*)(xr + 2 * D);
                    float2 xj3 = *(const float2*)(xr + 3 * D);
                    float* op = C + (size_t)row * ND + col;
                    float ox, oy;
                    ox = hr0.x * xj0.x + hr0.y * xj1.x + hr0.z * xj2.x + hr0.w * xj3.x + vx * hps.x;
                    oy = hr0.x * xj0.y + hr0.y * xj1.y + hr0.z * xj2.y + hr0.w * xj3.y + vy * hps.x;
                    *(float2*)(op) = make_float2(ox, oy);
                    ox = hr1.x * xj0.x + hr1.y * xj1.x + hr1.z * xj2.x + hr1.w * xj3.x + vx * hps.y;
                    oy = hr1.x * xj0.y + hr1.y * xj1.y + hr1.z * xj2.y + hr1.w * xj3.y + vy * hps.y;
                    *(float2*)(op + D) = make_float2(ox, oy);
                    ox = hr2.x * xj0.x + hr2.y * xj1.x + hr2.z * xj2.x + hr2.w * xj3.x + vx * hps.z;
                    oy = hr2.x * xj0.y + hr2.y * xj1.y + hr2.z * xj2.y + hr2.w * xj3.y + vy * hps.z;
                    *(float2*)(op + 2 * D) = make_float2(ox, oy);
                    ox = hr3.x * xj0.x + hr3.y * xj1.x + hr3.z * xj2.x + hr3.w * xj3.x + vx * hps.w;
                    oy = hr3.x * xj0.y + hr3.y * xj1.y + hr3.z * xj2.y + hr3.w * xj3.y + vy * hps.w;
                    *(float2*)(op + 3 * D) = make_float2(ox, oy);
                }
            }
        }
    }
}

// =================================================================================
// Kernel 3: stream mixing + fused LN1. 1 warp/token, 8 tok/block.
// =================================================================================
__global__ __launch_bounds__(256) void sinkmix_kernel(
    const float* __restrict__ x,
    const float* __restrict__ ln1_w, const float* __restrict__ ln1_b,
    float* __restrict__ xin)
{
    int wid = threadIdx.x >> 5, lane = threadIdx.x & 31;
    int tok = blockIdx.x * 8 + wid;

    float gv = (lane < 4) ? g_gates[(size_t)tok * 20 + 16 + lane] : 0.f;
    float hp[4];
    #pragma unroll
    for (int i = 0; i < 4; i++) hp[i] = __shfl_sync(~0u, gv, i);

    const float* xrow = x + (size_t)tok * ND;
    float xi_c[6];
    float sum = 0.f, sumsq = 0.f;
    #pragma unroll
    for (int c = 0; c < 6; c++) {
        int dd = c * 32 + lane;
        float x0 = xrow[dd], x1 = xrow[D + dd], x2v = xrow[2 * D + dd], x3 = xrow[3 * D + dd];
        float xi = hp[0] * x0 + hp[1] * x1 + hp[2] * x2v + hp[3] * x3;
        xin[(size_t)tok * D + dd] = xi;
        xi_c[c] = xi;
        sum += xi; sumsq += xi * xi;
    }
    #pragma unroll
    for (int o = 16; o; o >>= 1) {
        sum += __shfl_xor_sync(~0u, sum, o);
        sumsq += __shfl_xor_sync(~0u, sumsq, o);
    }
    float mean = sum / (float)D;
    float var = sumsq / (float)D - mean * mean;
    float invstd = rsqrtf(var + 1e-5f);
    #pragma unroll
    for (int c = 0; c < 6; c++) {
        int dd = c * 32 + lane;
        float hv = (xi_c[c] - mean) * invstd * ln1_w[dd] + ln1_b[dd];
        g_h[(size_t)tok * D + dd] = __float2bfloat16(hv);
    }
}

// =================================================================================
// Kernel 4: LayerNorm (x2 f32 -> h bf16). One block (192 threads) per token.
// =================================================================================
__global__ __launch_bounds__(192) void ln2_kernel(
    const float* __restrict__ in, const float* __restrict__ w,
    const float* __restrict__ b)
{
    int tok = blockIdx.x, tid = threadIdx.x;
    int lane = tid & 31, wid = tid >> 5;
    __shared__ float red[6];
    __shared__ float s_mean, s_invstd;

    float v = in[(size_t)tok * D + tid];
    float sm = v;
    #pragma unroll
    for (int o = 16; o; o >>= 1) sm += __shfl_xor_sync(~0u, sm, o);
    if (lane == 0) red[wid] = sm;
    __syncthreads();
    if (tid == 0) {
        float s = red[0] + red[1] + red[2] + red[3] + red[4] + red[5];
        s_mean = s / (float)D;
    }
    __syncthreads();
    float dv = v - s_mean;
    float sq = dv * dv;
    #pragma unroll
    for (int o = 16; o; o >>= 1) sq += __shfl_xor_sync(~0u, sq, o);
    __syncthreads();
    if (lane == 0) red[wid] = sq;
    __syncthreads();
    if (tid == 0) {
        float s = red[0] + red[1] + red[2] + red[3] + red[4] + red[5];
        s_invstd = rsqrtf(s / (float)D + 1e-5f);
    }
    __syncthreads();
    g_h[(size_t)tok * D + tid] = __float2bfloat16(dv * s_invstd * w[tid] + b[tid]);
}

// =================================================================================
// Kernel 5: bf16 flash attention. BQ=128, BKEY=64, HD=64, 128 threads (4 warps).
// Warp owns 32 q-rows (2 m-tiles); K/V b-frags loaded ONCE per warp, fed to both.
// Q held entirely in registers (direct gmem frag load). Register K/V prefetch.
// =================================================================================
__global__ __launch_bounds__(128) void flash_bf(
    const bf16* __restrict__ QKV, bf16* __restrict__ O)
{
    __shared__ __align__(16) unsigned Ksp[64][36];   // [key][dpair] (4g+tig) CF
    __shared__ __align__(16) unsigned Vp[32][72];    // [keypair][d] (8tig+g) CF

    int tid = threadIdx.x, wid = tid >> 5, lane = tid & 31;
    int g = lane >> 2, tig = lane & 3;
    int qt = blockIdx.x, h = blockIdx.y, b = blockIdx.z;
    size_t tokbase = (size_t)b * T_SEQ;
    int qoff = h * HD, koff = D + h * HD, voff = 2 * D + h * HD;
    int m0 = wid * 32;

    // Q A-frags directly from gmem into registers (pairs contiguous along d)
    unsigned aq[2][4][4];
    {
        const bf16* qb = QKV + (tokbase + qt * 128) * QKVN + qoff;
        #pragma unroll
        for (int mt = 0; mt < 2; mt++) {
            int r0 = m0 + mt * 16 + g;
            #pragma unroll
            for (int ks = 0; ks < 4; ks++) {
                aq[mt][ks][0] = *(const unsigned*)(qb + (size_t)r0 * QKVN + (ks * 8 + tig) * 2);
                aq[mt][ks][1] = *(const unsigned*)(qb + (size_t)(r0 + 8) * QKVN + (ks * 8 + tig) * 2);
                aq[mt][ks][2] = *(const unsigned*)(qb + (size_t)r0 * QKVN + (ks * 8 + tig + 4) * 2);
                aq[mt][ks][3] = *(const unsigned*)(qb + (size_t)(r0 + 8) * QKVN + (ks * 8 + tig + 4) * 2);
            }
        }
    }

    // per-thread K/V load coords (128 threads)
    int kr = tid >> 1, kcp = (tid & 1) * 16;   // K: row (64), 16 pairs
    int vkp = tid >> 2, vc = (tid & 3) * 16;   // V: pair-row (32), 16 cols

    float m_prev[2][2] = {{-1e30f, -1e30f}, {-1e30f, -1e30f}};
    float l_run[2][2] = {};
    float o_acc[2][8][4] = {};

    // prefetch tile 0
    uint4 kreg[4], vr0a, vr0b, vr1a, vr1b;
    {
        const bf16* kb = QKV + (tokbase + kr) * QKVN + koff;
        #pragma unroll
        for (int u = 0; u < 4; u++) kreg[u] = *(const uint4*)(kb + (kcp + 4 * u) * 2);
        const bf16* vb = QKV + (tokbase + 2 * vkp) * QKVN + voff + vc;
        vr0a = *(const uint4*)vb;         vr0b = *(const uint4*)(vb + 8);
        vr1a = *(const uint4*)(vb + QKVN); vr1b = *(const uint4*)(vb + QKVN + 8);
    }

    for (int kt = 0; kt < T_SEQ; kt += 64) {
        // commit prefetched tile to smem
        #pragma unroll
        for (int u = 0; u < 4; u++) *(uint4*)&Ksp[kr][kcp + 4 * u] = kreg[u];
        {
            uint4 oA, oB;
            oA.x = __byte_perm(vr0a.x, vr1a.x, 0x5410); oA.y = __byte_perm(vr0a.x, vr1a.x, 0x7632);
            oA.z = __byte_perm(vr0a.y, vr1a.y, 0x5410); oA.w = __byte_perm(vr0a.y, vr1a.y, 0x7632);
            oB.x = __byte_perm(vr0a.z, vr1a.z, 0x5410); oB.y = __byte_perm(vr0a.z, vr1a.z, 0x7632);
            oB.z = __byte_perm(vr0a.w, vr1a.w, 0x5410); oB.w = __byte_perm(vr0a.w, vr1a.w, 0x7632);
            *(uint4*)&Vp[vkp][vc]     = oA;
            *(uint4*)&Vp[vkp][vc + 4] = oB;
            oA.x = __byte_perm(vr0b.x, vr1b.x, 0x5410); oA.y = __byte_perm(vr0b.x, vr1b.x, 0x7632);
            oA.z = __byte_perm(vr0b.y, vr1b.y, 0x5410); oA.w = __byte_perm(vr0b.y, vr1b.y, 0x7632);
            oB.x = __byte_perm(vr0b.z, vr1b.z, 0x5410); oB.y = __byte_perm(vr0b.z, vr1b.z, 0x7632);
            oB.z = __byte_perm(vr0b.w, vr1b.w, 0x5410); oB.w = __byte_perm(vr0b.w, vr1b.w, 0x7632);
            *(uint4*)&Vp[vkp][vc + 8]  = oA;
            *(uint4*)&Vp[vkp][vc + 12] = oB;
        }
        __syncthreads();

        // prefetch next tile
        if (kt + 64 < T_SEQ) {
            const bf16* kb = QKV + (tokbase + kt + 64 + kr) * QKVN + koff;
            #pragma unroll
            for (int u = 0; u < 4; u++) kreg[u] = *(const uint4*)(kb + (kcp + 4 * u) * 2);
            const bf16* vb = QKV + (tokbase + kt + 64 + 2 * vkp) * QKVN + voff + vc;
            vr0a = *(const uint4*)vb;         vr0b = *(const uint4*)(vb + 8);
            vr1a = *(const uint4*)(vb + QKVN); vr1b = *(const uint4*)(vb + QKVN + 8);
        }

        // S = Q K^T : b-frags loaded once, used by BOTH m-tiles
        float s[2][8][4] = {};
        #pragma unroll
        for (int ks = 0; ks < 4; ks++) {
            int kp0 = ks * 8;
            #pragma unroll
            for (int nt = 0; nt < 8; nt++) {
                unsigned b0 = Ksp[nt * 8 + g][kp0 + tig];
                unsigned b1 = Ksp[nt * 8 + g][kp0 + tig + 4];
                mma_bf16(s[0][nt], aq[0][ks][0], aq[0][ks][1], aq[0][ks][2], aq[0][ks][3], b0, b1);
                mma_bf16(s[1][nt], aq[1][ks][0], aq[1][ks][1], aq[1][ks][2], aq[1][ks][3], b0, b1);
            }
        }

        // online softmax in exp2 domain
        const float sc2 = 0.125f * 1.44269504f;
        #pragma unroll
        for (int mt = 0; mt < 2; mt++) {
            float mx0 = -1e30f, mx1 = -1e30f;
            #pragma unroll
            for (int nt = 0; nt < 8; nt++) {
                s[mt][nt][0] *= sc2; s[mt][nt][1] *= sc2; s[mt][nt][2] *= sc2; s[mt][nt][3] *= sc2;
                mx0 = fmaxf(mx0, fmaxf(s[mt][nt][0], s[mt][nt][1]));
                mx1 = fmaxf(mx1, fmaxf(s[mt][nt][2], s[mt][nt][3]));
            }
            mx0 = fmaxf(mx0, __shfl_xor_sync(~0u, mx0, 1));
            mx0 = fmaxf(mx0, __shfl_xor_sync(~0u, mx0, 2));
            mx1 = fmaxf(mx1, __shfl_xor_sync(~0u, mx1, 1));
            mx1 = fmaxf(mx1, __shfl_xor_sync(~0u, mx1, 2));
            float mn0 = fmaxf(m_prev[mt][0], mx0);
            float mn1 = fmaxf(m_prev[mt][1], mx1);
            float rs0 = 0.f, rs1 = 0.f;
            #pragma unroll
            for (int nt = 0; nt < 8; nt++) {
                s[mt][nt][0] = fex2(s[mt][nt][0] - mn0);
                s[mt][nt][1] = fex2(s[mt][nt][1] - mn0);
                s[mt][nt][2] = fex2(s[mt][nt][2] - mn1);
                s[mt][nt][3] = fex2(s[mt][nt][3] - mn1);
                rs0 += s[mt][nt][0] + s[mt][nt][1];
                rs1 += s[mt][nt][2] + s[mt][nt][3];
            }
            rs0 += __shfl_xor_sync(~0u, rs0, 1);
            rs0 += __shfl_xor_sync(~0u, rs0, 2);
            rs1 += __shfl_xor_sync(~0u, rs1, 1);
            rs1 += __shfl_xor_sync(~0u, rs1, 2);
            float scl0 = fex2(m_prev[mt][0] - mn0);
            float scl1 = fex2(m_prev[mt][1] - mn1);
            l_run[mt][0] = l_run[mt][0] * scl0 + rs0;
            l_run[mt][1] = l_run[mt][1] * scl1 + rs1;
            m_prev[mt][0] = mn0; m_prev[mt][1] = mn1;
            #pragma unroll
            for (int nt = 0; nt < 8; nt++) {
                o_acc[mt][nt][0] *= scl0; o_acc[mt][nt][1] *= scl0;
                o_acc[mt][nt][2] *= scl1; o_acc[mt][nt][3] *= scl1;
            }
        }

        // O += P V : P in registers; V b-frags loaded once, used by both m-tiles
        #pragma unroll
        for (int ks = 0; ks < 4; ks++) {
            int kp0 = ks * 8;
            unsigned pa[2][4];
            #pragma unroll
            for (int mt = 0; mt < 2; mt++) {
                pa[mt][0] = pack_bf16(s[mt][2 * ks][0],     s[mt][2 * ks][1]);
                pa[mt][1] = pack_bf16(s[mt][2 * ks][2],     s[mt][2 * ks][3]);
                pa[mt][2] = pack_bf16(s[mt][2 * ks + 1][0], s[mt][2 * ks + 1][1]);
                pa[mt][3] = pack_bf16(s[mt][2 * ks + 1][2], s[mt][2 * ks + 1][3]);
            }
            #pragma unroll
            for (int nt = 0; nt < 8; nt++) {
                unsigned b0 = Vp[kp0 + tig][nt * 8 + g];
                unsigned b1 = Vp[kp0 + tig + 4][nt * 8 + g];
                mma_bf16(o_acc[0][nt], pa[0][0], pa[0][1], pa[0][2], pa[0][3], b0, b1);
                mma_bf16(o_acc[1][nt], pa[1][0], pa[1][1], pa[1][2], pa[1][3], b0, b1);
            }
        }
        __syncthreads();
    }

    size_t obase = tokbase * D + h * HD;
    #pragma unroll
    for (int mt = 0; mt < 2; mt++) {
        float inv0 = 1.f / l_run[mt][0];
        float inv1 = 1.f / l_run[mt][1];
        int q0 = qt * 128 + m0 + mt * 16 + g;
        #pragma unroll
        for (int nt = 0; nt < 8; nt++) {
            int col = nt * 8 + tig * 2;
            *(unsigned*)(O + obase + (size_t)q0 * D + col) =
                pack_bf16(o_acc[mt][nt][0] * inv0, o_acc[mt][nt][1] * inv0);
            *(unsigned*)(O + obase + (size_t)(q0 + 8) * D + col) =
                pack_bf16(o_acc[mt][nt][2] * inv1, o_acc[mt][nt][3] * inv1);
        }
    }
}

// =================================================================================
extern "C" void kernel_launch(void* const* d_in, const int* in_sizes, int n_in,
                              void* d_out, int out_size)
{
    const float* x        = (const float*)d_in[0];
    const float* norm_w   = (const float*)d_in[1];
    const float* phi_pre  = (const float*)d_in[2];
    const float* phi_post = (const float*)d_in[3];
    const float* phi_res  = (const float*)d_in[4];
    const float* b_pre    = (const float*)d_in[5];
    const float* b_post   = (const float*)d_in[6];
    const float* b_res    = (const float*)d_in[7];
    const float* a_pre    = (const float*)d_in[8];
    const float* a_post   = (const float*)d_in[9];
    const float* a_res    = (const float*)d_in[10];
    const float* ln1_w    = (const float*)d_in[11];
    const float* ln1_b    = (const float*)d_in[12];
    const float* Wq       = (const float*)d_in[13];
    const float* Wk       = (const float*)d_in[14];
    const float* Wv       = (const float*)d_in[15];
    const float* Wo       = (const float*)d_in[16];
    const float* ln2_w    = (const float*)d_in[17];
    const float* ln2_b    = (const float*)d_in[18];
    const float* W1       = (const float*)d_in[19];
    const float* W2       = (const float*)d_in[20];
    float* out = (float*)d_out;

    void *p;
    cudaGetSymbolAddress(&p, g_xin);     float* xin       = (float*)p;
    cudaGetSymbolAddress(&p, g_x2);      float* x2        = (float*)p;
    cudaGetSymbolAddress(&p, g_hpost);   float* hpost     = (float*)p;
    cudaGetSymbolAddress(&p, g_streams); bf16* streams    = (bf16*)p;
    cudaGetSymbolAddress(&p, g_h);       bf16* h          = (bf16*)p;
    cudaGetSymbolAddress(&p, g_qkv);     bf16* qkv        = (bf16*)p;
    cudaGetSymbolAddress(&p, g_o);       bf16* o          = (bf16*)p;
    cudaGetSymbolAddress(&p, g_g);       bf16* gbuf       = (bf16*)p;
    cudaGetSymbolAddress(&p, g_wqkv_p);  unsigned* wqkv   = (unsigned*)p;
    cudaGetSymbolAddress(&p, g_wo_p);    unsigned* wo     = (unsigned*)p;
    cudaGetSymbolAddress(&p, g_w1_p);    unsigned* w1     = (unsigned*)p;
    cudaGetSymbolAddress(&p, g_w2_p);    unsigned* w2     = (unsigned*)p;
    cudaGetSymbolAddress(&p, g_phiC_p);  unsigned* phiC   = (unsigned*)p;

    // 0) weight conversion (k-pair interleaved)
    convert_kernel<<<288, 256>>>(Wq, Wk, Wv, Wo, W1, W2, phi_pre, phi_post, phi_res,
                                 b_pre, b_post, b_res, a_pre, a_post, a_res);
    // 1) rmsnorm -> streams bf16
    rms_kernel<<<BT, 192>>>(x, norm_w);
    // 2) projections + FUSED sigmoid/sinkhorn epilogue -> g_gates, hpost
    gemm_bf<4><<<dim3(1, BT / 128), 256>>>(streams, phiC, nullptr, hpost, nullptr, nullptr, 64, ND);
    // 3) mix + LN1 -> xin, h
    sinkmix_kernel<<<BT / 8, 256>>>(x, ln1_w, ln1_b, xin);
    // 4) fused QKV
    dim3 g192(D / 64, BT / 128), g576(QKVN / 64, BT / 128), g768(MLP / 64, BT / 128);
    gemm_bf<0><<<g576, 256>>>(h, wqkv, nullptr, nullptr, nullptr, qkv, QKVN, D);
    // 5) attention (4 warps, 32 q-rows/warp, Q in regs)
    flash_bf<<<dim3(T_SEQ / 128, NH, NB), 128>>>(qkv, o);
    // 6) Wo + residual -> x2 (f32)
    gemm_bf<1><<<g192, 256>>>(o, wo, xin, nullptr, nullptr, x2, D, D);
    // 7) LN2 -> h bf16
    ln2_kernel<<<BT, 192>>>(x2, ln2_w, ln2_b);
    // 8) MLP up + GELU -> g bf16
    gemm_bf<2><<<g768, 256>>>(h, w1, nullptr, nullptr, nullptr, gbuf, MLP, D);
    // 9) MLP down + x2 residual + x_res (from x,gates) + gated scatter -> out (pure write)
    gemm_bf<3><<<g192, 256>>>(gbuf, w2, x2, hpost, x, out, D, MLP);
}

// round 15
// speedup vs baseline: 7.2819x; 1.0300x over previous
#include <cuda_runtime.h>
#include <cuda_bf16.h>
#include <math.h>

#define BT 32768
#define NSTREAM 4
#define D 192
#define ND 768
#define MLP 768
#define T_SEQ 1024
#define NB 32
#define NH 3
#define HD 64
#define QKVN 576

typedef __nv_bfloat16 bf16;

// ---------------- scratch (device globals; no allocation allowed) ----------------
__device__ float g_xin[BT * D];
__device__ float g_x2[BT * D];
__device__ float g_hpost[BT * NSTREAM];
__device__ float g_gates[BT * 20];       // 16 hres + 4 hpre per token
__device__ float g_bias24[24];
__device__ bf16  g_h[BT * D];
__device__ bf16  g_qkv[BT * QKVN];
__device__ bf16  g_o[BT * D];
__device__ bf16  g_g[BT * MLP];
// k-pair-interleaved weights: W_p[kp][n] = pack(W[2kp][n], W[2kp+1][n])
__device__ unsigned g_wqkv_p[(D / 2) * QKVN];
__device__ unsigned g_wo_p[(D / 2) * D];
__device__ unsigned g_w1_p[(D / 2) * MLP];
__device__ unsigned g_w2_p[(MLP / 2) * D];
__device__ unsigned g_phiC_p[(ND / 2) * 64];

// ---------------- helpers ----------------
__device__ __forceinline__ unsigned pack_bf16(float lo, float hi) {
    unsigned r;
    asm("cvt.rn.bf16x2.f32 %0, %1, %2;" : "=r"(r) : "f"(hi), "f"(lo));
    return r;
}

__device__ __forceinline__ void mma_bf16(float c[4],
    unsigned a0, unsigned a1, unsigned a2, unsigned a3,
    unsigned b0, unsigned b1)
{
    asm volatile(
        "mma.sync.aligned.m16n8k16.row.col.f32.bf16.bf16.f32 "
        "{%0,%1,%2,%3}, {%4,%5,%6,%7}, {%8,%9}, {%0,%1,%2,%3};\n"
        : "+f"(c[0]), "+f"(c[1]), "+f"(c[2]), "+f"(c[3])
        : "r"(a0), "r"(a1), "r"(a2), "r"(a3), "r"(b0), "r"(b1));
}

__device__ __forceinline__ void cp16(void* smem, const void* g) {
    unsigned saddr = (unsigned)__cvta_generic_to_shared(smem);
    asm volatile("cp.async.cg.shared.global [%0], [%1], 16;\n" :: "r"(saddr), "l"(g));
}
#define CP_COMMIT() asm volatile("cp.async.commit_group;\n" ::: "memory")

__device__ __forceinline__ float frcp(float x) {
    float r;
    asm("rcp.approx.f32 %0, %1;" : "=f"(r) : "f"(x));
    return r;
}

__device__ __forceinline__ float fex2(float x) {
    float r;
    asm("ex2.approx.f32 %0, %1;" : "=f"(r) : "f"(x));
    return r;
}

__device__ __forceinline__ float tanh_ap(float x) {
    float r;
    asm("tanh.approx.f32 %0, %1;" : "=f"(r) : "f"(x));
    return r;
}

__device__ __forceinline__ float gelu_f(float x) {
    float x3 = x * x * x;
    float t = tanh_ap(0.7978845608028654f * (x + 0.044715f * x3));
    return 0.5f * x * (1.f + t);
}

// =================================================================================
// Kernel 0: weight conversion fp32 -> bf16 k-pair-interleaved (+ phi combine, bias24)
// =================================================================================
__global__ void convert_kernel(
    const float* __restrict__ Wq, const float* __restrict__ Wk,
    const float* __restrict__ Wv, const float* __restrict__ Wo,
    const float* __restrict__ W1, const float* __restrict__ W2,
    const float* __restrict__ phi_pre, const float* __restrict__ phi_post,
    const float* __restrict__ phi_res,
    const float* __restrict__ b_pre, const float* __restrict__ b_post,
    const float* __restrict__ b_res,
    const float* __restrict__ a_pre, const float* __restrict__ a_post,
    const float* __restrict__ a_res)
{
    int idx = blockIdx.x * blockDim.x + threadIdx.x;
    if (idx < (D / 2) * QKVN) {
        int kp = idx / QKVN, c = idx % QKVN;
        const float* W; int cc;
        if (c < D)          { W = Wq; cc = c; }
        else if (c < 2 * D) { W = Wk; cc = c - D; }
        else                { W = Wv; cc = c - 2 * D; }
        g_wqkv_p[idx] = pack_bf16(W[(2 * kp) * D + cc], W[(2 * kp + 1) * D + cc]);
    }
    if (idx < (D / 2) * D) {
        int kp = idx / D, c = idx % D;
        g_wo_p[idx] = pack_bf16(Wo[(2 * kp) * D + c], Wo[(2 * kp + 1) * D + c]);
    }
    if (idx < (D / 2) * MLP) {
        int kp = idx / MLP, c = idx % MLP;
        g_w1_p[idx] = pack_bf16(W1[(2 * kp) * MLP + c], W1[(2 * kp + 1) * MLP + c]);
    }
    if (idx < (MLP / 2) * D) {
        int kp = idx / D, c = idx % D;
        g_w2_p[idx] = pack_bf16(W2[(2 * kp) * D + c], W2[(2 * kp + 1) * D + c]);
    }
    if (idx < (ND / 2) * 64) {
        int kp = idx >> 6, c = idx & 63;
        float v[2];
        #pragma unroll
        for (int u = 0; u < 2; u++) {
            int d = 2 * kp + u;
            float t = 0.f;
            if (c < 4)       t = a_pre[0]  * phi_pre[d * 4 + c];
            else if (c < 8)  t = a_post[0] * phi_post[d * 4 + (c - 4)];
            else if (c < 24) t = a_res[0]  * phi_res[d * 16 + (c - 8)];
            v[u] = t;
        }
        g_phiC_p[idx] = pack_bf16(v[0], v[1]);
    }
    if (idx < 24) {
        float v;
        if (idx < 4)      v = b_pre[idx];
        else if (idx < 8) v = b_post[idx - 4];
        else              v = b_res[idx - 8];
        g_bias24[idx] = v;
    }
}

// =================================================================================
// Kernel 1: FUSED rmsnorm + tilde GEMM + sigmoid/sinkhorn gates.
// BM=128 (block owns 128 tokens), N=64, K=768. RMS stats in prologue; A normalized
// on the fly during fill; per-thread register sinkhorn in the epilogue.
// =================================================================================
__global__ __launch_bounds__(256) void gemm_gates(
    const float* __restrict__ x, const unsigned* __restrict__ Bp,
    const float* __restrict__ norm_w, float* __restrict__ hpost)
{
    __shared__ __align__(16) unsigned Asp[2][128][20];
    __shared__ __align__(16) unsigned Bsp[2][16][72];
    __shared__ float tl[128][25];
    __shared__ float sinv_s[128];
    __shared__ __align__(16) float wnorm_s[ND];

    const int N = 64;
    int tid = threadIdx.x;
    int wid = tid >> 5, lane = tid & 31;
    int g = lane >> 2, tig = lane & 3;
    int wm = wid & 3, wn = wid >> 2;
    int bm = blockIdx.y;

    int bkp = tid >> 4, bc = (tid & 15) * 4;
    const unsigned* Bbase = Bp + (size_t)bkp * N + bc;

    cp16(&Bsp[0][bkp][bc], Bbase);
    CP_COMMIT();

    // norm_w -> smem
    for (int i = tid; i < ND / 4; i += 256)
        *(float4*)&wnorm_s[i * 4] = *(const float4*)(norm_w + i * 4);

    // rms stats: 8 warps x 16 rows
    for (int r = 0; r < 16; r++) {
        int row = wid * 16 + r;
        const float* xr = x + ((size_t)bm * 128 + row) * ND;
        float sq = 0.f;
        #pragma unroll
        for (int i = 0; i < 6; i++) {
            float4 v = *(const float4*)(xr + (lane + i * 32) * 4);
            sq += v.x * v.x + v.y * v.y + v.z * v.z + v.w * v.w;
        }
        #pragma unroll
        for (int o = 16; o; o >>= 1) sq += __shfl_xor_sync(~0u, sq, o);
        if (lane == 0) sinv_s[row] = rsqrtf(sq / (float)ND + 1e-8f);
    }
    __syncthreads();

    int ar = tid >> 1, ac0 = (tid & 1) * 16, acp = (tid & 1) * 8;
    const float* Abase = x + ((size_t)bm * 128 + ar) * ND + ac0;

    float4 ax[4];
    #pragma unroll
    for (int j = 0; j < 4; j++) ax[j] = *(const float4*)(Abase + j * 4);

    // convert+store helper (lambda)
    auto convert_store = [&](int stage, int kb) {
        float s = sinv_s[ar];
        unsigned u[8];
        #pragma unroll
        for (int j = 0; j < 4; j++) {
            float4 wv = *(const float4*)(wnorm_s + kb + ac0 + j * 4);
            u[2 * j]     = pack_bf16(ax[j].x * s * wv.x, ax[j].y * s * wv.y);
            u[2 * j + 1] = pack_bf16(ax[j].z * s * wv.z, ax[j].w * s * wv.w);
        }
        *(uint4*)&Asp[stage][ar][acp]     = *(uint4*)&u[0];
        *(uint4*)&Asp[stage][ar][acp + 4] = *(uint4*)&u[4];
    };
    convert_store(0, 0);

    float acc[2][4][4] = {};
    const int nk = ND / 32;  // 24
    for (int it = 0; it < nk; it++) {
        int cur = it & 1;
        if (it + 1 < nk) {
            cp16(&Bsp[cur ^ 1][bkp][bc], Bbase + (size_t)16 * (it + 1) * N);
            CP_COMMIT();
            #pragma unroll
            for (int j = 0; j < 4; j++)
                ax[j] = *(const float4*)(Abase + (it + 1) * 32 + j * 4);
            asm volatile("cp.async.wait_group 1;\n" ::: "memory");
        } else {
            asm volatile("cp.async.wait_group 0;\n" ::: "memory");
        }
        __syncthreads();

        const unsigned (*As)[20] = Asp[cur];
        const unsigned (*Bs)[72] = Bsp[cur];
        #pragma unroll
        for (int ks = 0; ks < 2; ks++) {
            int kp0 = ks * 8;
            unsigned a[2][4], b[4][2];
            #pragma unroll
            for (int mt = 0; mt < 2; mt++) {
                int m0 = wm * 32 + mt * 16;
                a[mt][0] = As[m0 + g][kp0 + tig];
                a[mt][1] = As[m0 + g + 8][kp0 + tig];
                a[mt][2] = As[m0 + g][kp0 + tig + 4];
                a[mt][3] = As[m0 + g + 8][kp0 + tig + 4];
            }
            #pragma unroll
            for (int nt = 0; nt < 4; nt++) {
                int n0 = wn * 32 + nt * 8;
                b[nt][0] = Bs[kp0 + tig][n0 + g];
                b[nt][1] = Bs[kp0 + tig + 4][n0 + g];
            }
            #pragma unroll
            for (int mt = 0; mt < 2; mt++)
                #pragma unroll
                for (int nt = 0; nt < 4; nt++)
                    mma_bf16(acc[mt][nt], a[mt][0], a[mt][1], a[mt][2], a[mt][3],
                             b[nt][0], b[nt][1]);
        }
        if (it + 1 < nk) convert_store(cur ^ 1, (it + 1) * 32);
        __syncthreads();
    }

    // ---- fused gates epilogue: stage tilde in smem, per-thread sinkhorn ----
    #pragma unroll
    for (int mt = 0; mt < 2; mt++) {
        #pragma unroll
        for (int half = 0; half < 2; half++) {
            if (wn == 0) {
                int rl = wm * 32 + mt * 16 + half * 8 + g;
                #pragma unroll
                for (int nt = 0; nt < 3; nt++) {
                    int col = nt * 8 + tig * 2;
                    tl[rl][col]     = acc[mt][nt][half * 2 + 0] + g_bias24[col];
                    tl[rl][col + 1] = acc[mt][nt][half * 2 + 1] + g_bias24[col + 1];
                }
            }
        }
    }
    __syncthreads();
    if (tid < 128) {
        size_t tok = (size_t)bm * 128 + tid;
        const float* t = tl[tid];

        float hp[4];
        #pragma unroll
        for (int j = 0; j < 4; j++) hp[j] = frcp(1.f + fex2(-1.44269504f * t[j]));
        float4 h4;
        h4.x = 2.f * frcp(1.f + fex2(-1.44269504f * t[4]));
        h4.y = 2.f * frcp(1.f + fex2(-1.44269504f * t[5]));
        h4.z = 2.f * frcp(1.f + fex2(-1.44269504f * t[6]));
        h4.w = 2.f * frcp(1.f + fex2(-1.44269504f * t[7]));
        *(float4*)(hpost + tok * 4) = h4;

        float m[16];
        float mx = t[8];
        #pragma unroll
        for (int j = 1; j < 16; j++) mx = fmaxf(mx, t[8 + j]);
        #pragma unroll
        for (int j = 0; j < 16; j++) m[j] = fex2(1.44269504f * (t[8 + j] - mx));

        #pragma unroll 1
        for (int it2 = 0; it2 < 20; it2++) {
            #pragma unroll
            for (int i = 0; i < 4; i++) {
                float rs = m[4 * i] + m[4 * i + 1] + m[4 * i + 2] + m[4 * i + 3];
                float inv = frcp(rs + 1e-8f);
                m[4 * i] *= inv; m[4 * i + 1] *= inv; m[4 * i + 2] *= inv; m[4 * i + 3] *= inv;
            }
            #pragma unroll
            for (int j = 0; j < 4; j++) {
                float cs = m[j] + m[4 + j] + m[8 + j] + m[12 + j];
                float inv = frcp(cs + 1e-8f);
                m[j] *= inv; m[4 + j] *= inv; m[8 + j] *= inv; m[12 + j] *= inv;
            }
        }

        float* gp = g_gates + tok * 20;
        *(float4*)(gp + 0)  = make_float4(m[0], m[1], m[2], m[3]);
        *(float4*)(gp + 4)  = make_float4(m[4], m[5], m[6], m[7]);
        *(float4*)(gp + 8)  = make_float4(m[8], m[9], m[10], m[11]);
        *(float4*)(gp + 12) = make_float4(m[12], m[13], m[14], m[15]);
        *(float4*)(gp + 16) = make_float4(hp[0], hp[1], hp[2], hp[3]);
    }
}

// =================================================================================
// Kernel 2: bf16 tensor-core GEMM, cp.async 2-stage pipeline.
// EPI: 0 plain->bf16, 1 +Res->f32, 2 gelu->bf16,
//      3 final: out = x_res(from Xorig+gates) + (acc+Res)*hpost  [pure write]
// =================================================================================
template <int EPI>
__global__ __launch_bounds__(256) void gemm_bf(
    const bf16* __restrict__ A, const unsigned* __restrict__ Bp,
    const float* __restrict__ Res, const float* __restrict__ hpost,
    const float* __restrict__ Xorig,
    void* __restrict__ Cv, int N, int K)
{
    __shared__ __align__(16) unsigned Asp[2][128][20];
    __shared__ __align__(16) unsigned Bsp[2][16][72];

    int tid = threadIdx.x;
    int wid = tid >> 5, lane = tid & 31;
    int g = lane >> 2, tig = lane & 3;
    int wm = wid & 3, wn = wid >> 2;
    int bm = blockIdx.y, bn = blockIdx.x;

    float acc[2][4][4] = {};

    int ar = tid >> 1, acp = (tid & 1) * 8;
    int bkp = tid >> 4, bc = (tid & 15) * 4;

    const bf16* Abase = A + (size_t)(bm * 128 + ar) * K + acp * 2;
    const unsigned* Bbase = Bp + (size_t)bkp * N + bn * 64 + bc;

    cp16(&Asp[0][ar][acp],     Abase);
    cp16(&Asp[0][ar][acp + 4], Abase + 8);
    cp16(&Bsp[0][bkp][bc],     Bbase);
    CP_COMMIT();

    int nk = K >> 5;
    for (int it = 0; it < nk; it++) {
        if (it + 1 < nk) {
            int st = (it + 1) & 1;
            cp16(&Asp[st][ar][acp],     Abase + (it + 1) * 32);
            cp16(&Asp[st][ar][acp + 4], Abase + (it + 1) * 32 + 8);
            cp16(&Bsp[st][bkp][bc],     Bbase + (size_t)16 * (it + 1) * N);
            CP_COMMIT();
            asm volatile("cp.async.wait_group 1;\n" ::: "memory");
        } else {
            asm volatile("cp.async.wait_group 0;\n" ::: "memory");
        }
        __syncthreads();

        const unsigned (*As)[20] = Asp[it & 1];
        const unsigned (*Bs)[72] = Bsp[it & 1];
        #pragma unroll
        for (int ks = 0; ks < 2; ks++) {
            int kp0 = ks * 8;
            unsigned a[2][4], b[4][2];
            #pragma unroll
            for (int mt = 0; mt < 2; mt++) {
                int m0 = wm * 32 + mt * 16;
                a[mt][0] = As[m0 + g][kp0 + tig];
                a[mt][1] = As[m0 + g + 8][kp0 + tig];
                a[mt][2] = As[m0 + g][kp0 + tig + 4];
                a[mt][3] = As[m0 + g + 8][kp0 + tig + 4];
            }
            #pragma unroll
            for (int nt = 0; nt < 4; nt++) {
                int n0 = wn * 32 + nt * 8;
                b[nt][0] = Bs[kp0 + tig][n0 + g];
                b[nt][1] = Bs[kp0 + tig + 4][n0 + g];
            }
            #pragma unroll
            for (int mt = 0; mt < 2; mt++)
                #pragma unroll
                for (int nt = 0; nt < 4; nt++)
                    mma_bf16(acc[mt][nt], a[mt][0], a[mt][1], a[mt][2], a[mt][3],
                             b[nt][0], b[nt][1]);
        }
        __syncthreads();
    }

    #pragma unroll
    for (int mt = 0; mt < 2; mt++) {
        #pragma unroll
        for (int half = 0; half < 2; half++) {
            int row = bm * 128 + wm * 32 + mt * 16 + g + half * 8;

            float4 hr0, hr1, hr2, hr3, hps;
            if (EPI == 3) {
                const float4* gp4 = (const float4*)(g_gates + (size_t)row * 20);
                hr0 = gp4[0]; hr1 = gp4[1]; hr2 = gp4[2]; hr3 = gp4[3];
                hps = *(const float4*)(hpost + (size_t)row * 4);
            }

            #pragma unroll
            for (int nt = 0; nt < 4; nt++) {
                int col = bn * 64 + wn * 32 + nt * 8 + tig * 2;
                float v0 = acc[mt][nt][half * 2 + 0];
                float v1 = acc[mt][nt][half * 2 + 1];
                if (EPI == 0) {
                    bf16* C = (bf16*)Cv;
                    *(unsigned*)(C + (size_t)row * N + col) = pack_bf16(v0, v1);
                } else if (EPI == 1) {
                    float* C = (float*)Cv;
                    float2 r = *(const float2*)(Res + (size_t)row * N + col);
                    *(float2*)(C + (size_t)row * N + col) = make_float2(v0 + r.x, v1 + r.y);
                } else if (EPI == 2) {
                    bf16* C = (bf16*)Cv;
                    *(unsigned*)(C + (size_t)row * N + col) = pack_bf16(gelu_f(v0), gelu_f(v1));
                } else if (EPI == 3) {
                    float* C = (float*)Cv;
                    float2 r = *(const float2*)(Res + (size_t)row * N + col);
                    float vx = v0 + r.x, vy = v1 + r.y;
                    const float* xr = Xorig + (size_t)row * ND + col;
                    float2 xj0 = *(const float2*)(xr);
                    float2 xj1 = *(const float2*)(xr + D);
                    float2 xj2 = *(const float2*)(xr + 2 * D);
                    float2 xj3 = *(const float2*)(xr + 3 * D);
                    float* op = C + (size_t)row * ND + col;
                    float ox, oy;
                    ox = hr0.x * xj0.x + hr0.y * xj1.x + hr0.z * xj2.x + hr0.w * xj3.x + vx * hps.x;
                    oy = hr0.x * xj0.y + hr0.y * xj1.y + hr0.z * xj2.y + hr0.w * xj3.y + vy * hps.x;
                    *(float2*)(op) = make_float2(ox, oy);
                    ox = hr1.x * xj0.x + hr1.y * xj1.x + hr1.z * xj2.x + hr1.w * xj3.x + vx * hps.y;
                    oy = hr1.x * xj0.y + hr1.y * xj1.y + hr1.z * xj2.y + hr1.w * xj3.y + vy * hps.y;
                    *(float2*)(op + D) = make_float2(ox, oy);
                    ox = hr2.x * xj0.x + hr2.y * xj1.x + hr2.z * xj2.x + hr2.w * xj3.x + vx * hps.z;
                    oy = hr2.x * xj0.y + hr2.y * xj1.y + hr2.z * xj2.y + hr2.w * xj3.y + vy * hps.z;
                    *(float2*)(op + 2 * D) = make_float2(ox, oy);
                    ox = hr3.x * xj0.x + hr3.y * xj1.x + hr3.z * xj2.x + hr3.w * xj3.x + vx * hps.w;
                    oy = hr3.x * xj0.y + hr3.y * xj1.y + hr3.z * xj2.y + hr3.w * xj3.y + vy * hps.w;
                    *(float2*)(op + 3 * D) = make_float2(ox, oy);
                }
            }
        }
    }
}

// =================================================================================
// Kernel 3: stream mixing + fused LN1. 1 warp/token, 8 tok/block.
// =================================================================================
__global__ __launch_bounds__(256) void sinkmix_kernel(
    const float* __restrict__ x,
    const float* __restrict__ ln1_w, const float* __restrict__ ln1_b,
    float* __restrict__ xin)
{
    int wid = threadIdx.x >> 5, lane = threadIdx.x & 31;
    int tok = blockIdx.x * 8 + wid;

    float gv = (lane < 4) ? g_gates[(size_t)tok * 20 + 16 + lane] : 0.f;
    float hp[4];
    #pragma unroll
    for (int i = 0; i < 4; i++) hp[i] = __shfl_sync(~0u, gv, i);

    const float* xrow = x + (size_t)tok * ND;
    float xi_c[6];
    float sum = 0.f, sumsq = 0.f;
    #pragma unroll
    for (int c = 0; c < 6; c++) {
        int dd = c * 32 + lane;
        float x0 = xrow[dd], x1 = xrow[D + dd], x2v = xrow[2 * D + dd], x3 = xrow[3 * D + dd];
        float xi = hp[0] * x0 + hp[1] * x1 + hp[2] * x2v + hp[3] * x3;
        xin[(size_t)tok * D + dd] = xi;
        xi_c[c] = xi;
        sum += xi; sumsq += xi * xi;
    }
    #pragma unroll
    for (int o = 16; o; o >>= 1) {
        sum += __shfl_xor_sync(~0u, sum, o);
        sumsq += __shfl_xor_sync(~0u, sumsq, o);
    }
    float mean = sum / (float)D;
    float var = sumsq / (float)D - mean * mean;
    float invstd = rsqrtf(var + 1e-5f);
    #pragma unroll
    for (int c = 0; c < 6; c++) {
        int dd = c * 32 + lane;
        float hv = (xi_c[c] - mean) * invstd * ln1_w[dd] + ln1_b[dd];
        g_h[(size_t)tok * D + dd] = __float2bfloat16(hv);
    }
}

// =================================================================================
// Kernel 4: LayerNorm (x2 f32 -> h bf16). 1 warp/token, 8 tok/block, shuffle-only.
// =================================================================================
__global__ __launch_bounds__(256) void ln2_kernel(
    const float* __restrict__ in, const float* __restrict__ w,
    const float* __restrict__ b)
{
    int wid = threadIdx.x >> 5, lane = threadIdx.x & 31;
    int tok = blockIdx.x * 8 + wid;
    const float* row = in + (size_t)tok * D;

    float v[6];
    float sum = 0.f, sumsq = 0.f;
    #pragma unroll
    for (int c = 0; c < 6; c++) {
        v[c] = row[c * 32 + lane];
        sum += v[c]; sumsq += v[c] * v[c];
    }
    #pragma unroll
    for (int o = 16; o; o >>= 1) {
        sum += __shfl_xor_sync(~0u, sum, o);
        sumsq += __shfl_xor_sync(~0u, sumsq, o);
    }
    float mean = sum / (float)D;
    float var = sumsq / (float)D - mean * mean;
    float invstd = rsqrtf(var + 1e-5f);
    #pragma unroll
    for (int c = 0; c < 6; c++) {
        int dd = c * 32 + lane;
        g_h[(size_t)tok * D + dd] = __float2bfloat16((v[c] - mean) * invstd * w[dd] + b[dd]);
    }
}

// =================================================================================
// Kernel 5: bf16 flash attention. BQ=128, BKEY=64, HD=64, 128 threads (4 warps).
// Double-buffered K/V smem -> ONE barrier per key-tile. Q in registers. P in regs.
// =================================================================================
__global__ __launch_bounds__(128) void flash_bf(
    const bf16* __restrict__ QKV, bf16* __restrict__ O)
{
    __shared__ __align__(16) unsigned Ksp[2][64][36];   // [key][dpair] (4g+tig) CF
    __shared__ __align__(16) unsigned Vp[2][32][72];    // [keypair][d] (8tig+g) CF

    int tid = threadIdx.x, wid = tid >> 5, lane = tid & 31;
    int g = lane >> 2, tig = lane & 3;
    int qt = blockIdx.x, h = blockIdx.y, b = blockIdx.z;
    size_t tokbase = (size_t)b * T_SEQ;
    int qoff = h * HD, koff = D + h * HD, voff = 2 * D + h * HD;
    int m0 = wid * 32;

    // Q A-frags directly from gmem into registers
    unsigned aq[2][4][4];
    {
        const bf16* qb = QKV + (tokbase + qt * 128) * QKVN + qoff;
        #pragma unroll
        for (int mt = 0; mt < 2; mt++) {
            int r0 = m0 + mt * 16 + g;
            #pragma unroll
            for (int ks = 0; ks < 4; ks++) {
                aq[mt][ks][0] = *(const unsigned*)(qb + (size_t)r0 * QKVN + (ks * 8 + tig) * 2);
                aq[mt][ks][1] = *(const unsigned*)(qb + (size_t)(r0 + 8) * QKVN + (ks * 8 + tig) * 2);
                aq[mt][ks][2] = *(const unsigned*)(qb + (size_t)r0 * QKVN + (ks * 8 + tig + 4) * 2);
                aq[mt][ks][3] = *(const unsigned*)(qb + (size_t)(r0 + 8) * QKVN + (ks * 8 + tig + 4) * 2);
            }
        }
    }

    int kr = tid >> 1, kcp = (tid & 1) * 16;   // K: row (64), 16 pairs
    int vkp = tid >> 2, vc = (tid & 3) * 16;   // V: pair-row (32), 16 cols

    float m_prev[2][2] = {{-1e30f, -1e30f}, {-1e30f, -1e30f}};
    float l_run[2][2] = {};
    float o_acc[2][8][4] = {};

    uint4 kreg[4], vr0a, vr0b, vr1a, vr1b;
    // load tile 0 regs + commit to stage 0
    {
        const bf16* kb = QKV + (tokbase + kr) * QKVN + koff;
        #pragma unroll
        for (int u = 0; u < 4; u++) kreg[u] = *(const uint4*)(kb + (kcp + 4 * u) * 2);
        const bf16* vb = QKV + (tokbase + 2 * vkp) * QKVN + voff + vc;
        vr0a = *(const uint4*)vb;          vr0b = *(const uint4*)(vb + 8);
        vr1a = *(const uint4*)(vb + QKVN); vr1b = *(const uint4*)(vb + QKVN + 8);

        #pragma unroll
        for (int u = 0; u < 4; u++) *(uint4*)&Ksp[0][kr][kcp + 4 * u] = kreg[u];
        uint4 oA, oB;
        oA.x = __byte_perm(vr0a.x, vr1a.x, 0x5410); oA.y = __byte_perm(vr0a.x, vr1a.x, 0x7632);
        oA.z = __byte_perm(vr0a.y, vr1a.y, 0x5410); oA.w = __byte_perm(vr0a.y, vr1a.y, 0x7632);
        oB.x = __byte_perm(vr0a.z, vr1a.z, 0x5410); oB.y = __byte_perm(vr0a.z, vr1a.z, 0x7632);
        oB.z = __byte_perm(vr0a.w, vr1a.w, 0x5410); oB.w = __byte_perm(vr0a.w, vr1a.w, 0x7632);
        *(uint4*)&Vp[0][vkp][vc]     = oA;
        *(uint4*)&Vp[0][vkp][vc + 4] = oB;
        oA.x = __byte_perm(vr0b.x, vr1b.x, 0x5410); oA.y = __byte_perm(vr0b.x, vr1b.x, 0x7632);
        oA.z = __byte_perm(vr0b.y, vr1b.y, 0x5410); oA.w = __byte_perm(vr0b.y, vr1b.y, 0x7632);
        oB.x = __byte_perm(vr0b.z, vr1b.z, 0x5410); oB.y = __byte_perm(vr0b.z, vr1b.z, 0x7632);
        oB.z = __byte_perm(vr0b.w, vr1b.w, 0x5410); oB.w = __byte_perm(vr0b.w, vr1b.w, 0x7632);
        *(uint4*)&Vp[0][vkp][vc + 8]  = oA;
        *(uint4*)&Vp[0][vkp][vc + 12] = oB;
    }
    __syncthreads();

    const int NIT = T_SEQ / 64;
    #pragma unroll 1
    for (int it = 0; it < NIT; it++) {
        int cur = it & 1;

        // prefetch next tile into regs (consumed at commit below)
        if (it + 1 < NIT) {
            const bf16* kb = QKV + (tokbase + (it + 1) * 64 + kr) * QKVN + koff;
            #pragma unroll
            for (int u = 0; u < 4; u++) kreg[u] = *(const uint4*)(kb + (kcp + 4 * u) * 2);
            const bf16* vb = QKV + (tokbase + (it + 1) * 64 + 2 * vkp) * QKVN + voff + vc;
            vr0a = *(const uint4*)vb;          vr0b = *(const uint4*)(vb + 8);
            vr1a = *(const uint4*)(vb + QKVN); vr1b = *(const uint4*)(vb + QKVN + 8);
        }

        // S = Q K^T
        float s[2][8][4] = {};
        #pragma unroll
        for (int ks = 0; ks < 4; ks++) {
            int kp0 = ks * 8;
            #pragma unroll
            for (int nt = 0; nt < 8; nt++) {
                unsigned b0 = Ksp[cur][nt * 8 + g][kp0 + tig];
                unsigned b1 = Ksp[cur][nt * 8 + g][kp0 + tig + 4];
                mma_bf16(s[0][nt], aq[0][ks][0], aq[0][ks][1], aq[0][ks][2], aq[0][ks][3], b0, b1);
                mma_bf16(s[1][nt], aq[1][ks][0], aq[1][ks][1], aq[1][ks][2], aq[1][ks][3], b0, b1);
            }
        }

        // online softmax in exp2 domain
        const float sc2 = 0.125f * 1.44269504f;
        #pragma unroll
        for (int mt = 0; mt < 2; mt++) {
            float mx0 = -1e30f, mx1 = -1e30f;
            #pragma unroll
            for (int nt = 0; nt < 8; nt++) {
                s[mt][nt][0] *= sc2; s[mt][nt][1] *= sc2; s[mt][nt][2] *= sc2; s[mt][nt][3] *= sc2;
                mx0 = fmaxf(mx0, fmaxf(s[mt][nt][0], s[mt][nt][1]));
                mx1 = fmaxf(mx1, fmaxf(s[mt][nt][2], s[mt][nt][3]));
            }
            mx0 = fmaxf(mx0, __shfl_xor_sync(~0u, mx0, 1));
            mx0 = fmaxf(mx0, __shfl_xor_sync(~0u, mx0, 2));
            mx1 = fmaxf(mx1, __shfl_xor_sync(~0u, mx1, 1));
            mx1 = fmaxf(mx1, __shfl_xor_sync(~0u, mx1, 2));
            float mn0 = fmaxf(m_prev[mt][0], mx0);
            float mn1 = fmaxf(m_prev[mt][1], mx1);
            float rs0 = 0.f, rs1 = 0.f;
            #pragma unroll
            for (int nt = 0; nt < 8; nt++) {
                s[mt][nt][0] = fex2(s[mt][nt][0] - mn0);
                s[mt][nt][1] = fex2(s[mt][nt][1] - mn0);
                s[mt][nt][2] = fex2(s[mt][nt][2] - mn1);
                s[mt][nt][3] = fex2(s[mt][nt][3] - mn1);
                rs0 += s[mt][nt][0] + s[mt][nt][1];
                rs1 += s[mt][nt][2] + s[mt][nt][3];
            }
            rs0 += __shfl_xor_sync(~0u, rs0, 1);
            rs0 += __shfl_xor_sync(~0u, rs0, 2);
            rs1 += __shfl_xor_sync(~0u, rs1, 1);
            rs1 += __shfl_xor_sync(~0u, rs1, 2);
            float scl0 = fex2(m_prev[mt][0] - mn0);
            float scl1 = fex2(m_prev[mt][1] - mn1);
            l_run[mt][0] = l_run[mt][0] * scl0 + rs0;
            l_run[mt][1] = l_run[mt][1] * scl1 + rs1;
            m_prev[mt][0] = mn0; m_prev[mt][1] = mn1;
            #pragma unroll
            for (int nt = 0; nt < 8; nt++) {
                o_acc[mt][nt][0] *= scl0; o_acc[mt][nt][1] *= scl0;
                o_acc[mt][nt][2] *= scl1; o_acc[mt][nt][3] *= scl1;
            }
        }

        // O += P V (P in regs)
        #pragma unroll
        for (int ks = 0; ks < 4; ks++) {
            int kp0 = ks * 8;
            unsigned pa[2][4];
            #pragma unroll
            for (int mt = 0; mt < 2; mt++) {
                pa[mt][0] = pack_bf16(s[mt][2 * ks][0],     s[mt][2 * ks][1]);
                pa[mt][1] = pack_bf16(s[mt][2 * ks][2],     s[mt][2 * ks][3]);
                pa[mt][2] = pack_bf16(s[mt][2 * ks + 1][0], s[mt][2 * ks + 1][1]);
                pa[mt][3] = pack_bf16(s[mt][2 * ks + 1][2], s[mt][2 * ks + 1][3]);
            }
            #pragma unroll
            for (int nt = 0; nt < 8; nt++) {
                unsigned b0 = Vp[cur][kp0 + tig][nt * 8 + g];
                unsigned b1 = Vp[cur][kp0 + tig + 4][nt * 8 + g];
                mma_bf16(o_acc[0][nt], pa[0][0], pa[0][1], pa[0][2], pa[0][3], b0, b1);
                mma_bf16(o_acc[1][nt], pa[1][0], pa[1][1], pa[1][2], pa[1][3], b0, b1);
            }
        }

        // commit prefetched tile into OTHER stage (safe: its readers finished at
        // the barrier ending iter it-1), then single barrier.
        if (it + 1 < NIT) {
            int nx = cur ^ 1;
            #pragma unroll
            for (int u = 0; u < 4; u++) *(uint4*)&Ksp[nx][kr][kcp + 4 * u] = kreg[u];
            uint4 oA, oB;
            oA.x = __byte_perm(vr0a.x, vr1a.x, 0x5410); oA.y = __byte_perm(vr0a.x, vr1a.x, 0x7632);
            oA.z = __byte_perm(vr0a.y, vr1a.y, 0x5410); oA.w = __byte_perm(vr0a.y, vr1a.y, 0x7632);
            oB.x = __byte_perm(vr0a.z, vr1a.z, 0x5410); oB.y = __byte_perm(vr0a.z, vr1a.z, 0x7632);
            oB.z = __byte_perm(vr0a.w, vr1a.w, 0x5410); oB.w = __byte_perm(vr0a.w, vr1a.w, 0x7632);
            *(uint4*)&Vp[nx][vkp][vc]     = oA;
            *(uint4*)&Vp[nx][vkp][vc + 4] = oB;
            oA.x = __byte_perm(vr0b.x, vr1b.x, 0x5410); oA.y = __byte_perm(vr0b.x, vr1b.x, 0x7632);
            oA.z = __byte_perm(vr0b.y, vr1b.y, 0x5410); oA.w = __byte_perm(vr0b.y, vr1b.y, 0x7632);
            oB.x = __byte_perm(vr0b.z, vr1b.z, 0x5410); oB.y = __byte_perm(vr0b.z, vr1b.z, 0x7632);
            oB.z = __byte_perm(vr0b.w, vr1b.w, 0x5410); oB.w = __byte_perm(vr0b.w, vr1b.w, 0x7632);
            *(uint4*)&Vp[nx][vkp][vc + 8]  = oA;
            *(uint4*)&Vp[nx][vkp][vc + 12] = oB;
        }
        __syncthreads();
    }

    size_t obase = tokbase * D + h * HD;
    #pragma unroll
    for (int mt = 0; mt < 2; mt++) {
        float inv0 = 1.f / l_run[mt][0];
        float inv1 = 1.f / l_run[mt][1];
        int q0 = qt * 128 + m0 + mt * 16 + g;
        #pragma unroll
        for (int nt = 0; nt < 8; nt++) {
            int col = nt * 8 + tig * 2;
            *(unsigned*)(O + obase + (size_t)q0 * D + col) =
                pack_bf16(o_acc[mt][nt][0] * inv0, o_acc[mt][nt][1] * inv0);
            *(unsigned*)(O + obase + (size_t)(q0 + 8) * D + col) =
                pack_bf16(o_acc[mt][nt][2] * inv1, o_acc[mt][nt][3] * inv1);
        }
    }
}

// =================================================================================
extern "C" void kernel_launch(void* const* d_in, const int* in_sizes, int n_in,
                              void* d_out, int out_size)
{
    const float* x        = (const float*)d_in[0];
    const float* norm_w   = (const float*)d_in[1];
    const float* phi_pre  = (const float*)d_in[2];
    const float* phi_post = (const float*)d_in[3];
    const float* phi_res  = (const float*)d_in[4];
    const float* b_pre    = (const float*)d_in[5];
    const float* b_post   = (const float*)d_in[6];
    const float* b_res    = (const float*)d_in[7];
    const float* a_pre    = (const float*)d_in[8];
    const float* a_post   = (const float*)d_in[9];
    const float* a_res    = (const float*)d_in[10];
    const float* ln1_w    = (const float*)d_in[11];
    const float* ln1_b    = (const float*)d_in[12];
    const float* Wq       = (const float*)d_in[13];
    const float* Wk       = (const float*)d_in[14];
    const float* Wv       = (const float*)d_in[15];
    const float* Wo       = (const float*)d_in[16];
    const float* ln2_w    = (const float*)d_in[17];
    const float* ln2_b    = (const float*)d_in[18];
    const float* W1       = (const float*)d_in[19];
    const float* W2       = (const float*)d_in[20];
    float* out = (float*)d_out;

    void *p;
    cudaGetSymbolAddress(&p, g_xin);     float* xin       = (float*)p;
    cudaGetSymbolAddress(&p, g_x2);      float* x2        = (float*)p;
    cudaGetSymbolAddress(&p, g_hpost);   float* hpost     = (float*)p;
    cudaGetSymbolAddress(&p, g_h);       bf16* h          = (bf16*)p;
    cudaGetSymbolAddress(&p, g_qkv);     bf16* qkv        = (bf16*)p;
    cudaGetSymbolAddress(&p, g_o);       bf16* o          = (bf16*)p;
    cudaGetSymbolAddress(&p, g_g);       bf16* gbuf       = (bf16*)p;
    cudaGetSymbolAddress(&p, g_wqkv_p);  unsigned* wqkv   = (unsigned*)p;
    cudaGetSymbolAddress(&p, g_wo_p);    unsigned* wo     = (unsigned*)p;
    cudaGetSymbolAddress(&p, g_w1_p);    unsigned* w1     = (unsigned*)p;
    cudaGetSymbolAddress(&p, g_w2_p);    unsigned* w2     = (unsigned*)p;
    cudaGetSymbolAddress(&p, g_phiC_p);  unsigned* phiC   = (unsigned*)p;

    // 0) weight conversion (k-pair interleaved)
    convert_kernel<<<288, 256>>>(Wq, Wk, Wv, Wo, W1, W2, phi_pre, phi_post, phi_res,
                                 b_pre, b_post, b_res, a_pre, a_post, a_res);
    // 1) FUSED rmsnorm + projections + sigmoid/sinkhorn -> g_gates, hpost
    gemm_gates<<<dim3(1, BT / 128), 256>>>(x, phiC, norm_w, hpost);
    // 2) mix + LN1 -> xin, h
    sinkmix_kernel<<<BT / 8, 256>>>(x, ln1_w, ln1_b, xin);
    // 3) fused QKV
    dim3 g192(D / 64, BT / 128), g576(QKVN / 64, BT / 128), g768(MLP / 64, BT / 128);
    gemm_bf<0><<<g576, 256>>>(h, wqkv, nullptr, nullptr, nullptr, qkv, QKVN, D);
    // 4) attention (double-buffered smem, 1 barrier/tile)
    flash_bf<<<dim3(T_SEQ / 128, NH, NB), 128>>>(qkv, o);
    // 5) Wo + residual -> x2 (f32)
    gemm_bf<1><<<g192, 256>>>(o, wo, xin, nullptr, nullptr, x2, D, D);
    // 6) LN2 -> h bf16 (warp-per-token)
    ln2_kernel<<<BT / 8, 256>>>(x2, ln2_w, ln2_b);
    // 7) MLP up + GELU -> g bf16
    gemm_bf<2><<<g768, 256>>>(h, w1, nullptr, nullptr, nullptr, gbuf, MLP, D);
    // 8) MLP down + x2 residual + x_res (from x,gates) + gated scatter -> out (pure write)
    gemm_bf<3><<<g192, 256>>>(gbuf, w2, x2, hpost, x, out, D, MLP);
}

// round 17
// speedup vs baseline: 7.4297x; 1.0203x over previous
#include <cuda_runtime.h>
#include <cuda_bf16.h>
#include <math.h>

#define BT 32768
#define NSTREAM 4
#define D 192
#define ND 768
#define MLP 768
#define T_SEQ 1024
#define NB 32
#define NH 3
#define HD 64
#define QKVN 576

typedef __nv_bfloat16 bf16;

// ---------------- scratch (device globals; no allocation allowed) ----------------
__device__ float g_xin[BT * D];
__device__ float g_x2[BT * D];
__device__ float g_hpost[BT * NSTREAM];
__device__ float g_gates[BT * 20];       // 16 hres + 4 hpre per token
__device__ float g_bias24[24];
__device__ bf16  g_h[BT * D];
__device__ bf16  g_qkv[BT * QKVN];
__device__ bf16  g_o[BT * D];
__device__ bf16  g_g[BT * MLP];
// k-pair-interleaved weights: W_p[kp][n] = pack(W[2kp][n], W[2kp+1][n])
__device__ unsigned g_wqkv_p[(D / 2) * QKVN];
__device__ unsigned g_wo_p[(D / 2) * D];
__device__ unsigned g_w1_p[(D / 2) * MLP];
__device__ unsigned g_w2_p[(MLP / 2) * D];
__device__ unsigned g_phiC_p[(ND / 2) * 64];

// ---------------- helpers ----------------
__device__ __forceinline__ unsigned pack_bf16(float lo, float hi) {
    unsigned r;
    asm("cvt.rn.bf16x2.f32 %0, %1, %2;" : "=r"(r) : "f"(hi), "f"(lo));
    return r;
}

__device__ __forceinline__ void mma_bf16(float c[4],
    unsigned a0, unsigned a1, unsigned a2, unsigned a3,
    unsigned b0, unsigned b1)
{
    asm volatile(
        "mma.sync.aligned.m16n8k16.row.col.f32.bf16.bf16.f32 "
        "{%0,%1,%2,%3}, {%4,%5,%6,%7}, {%8,%9}, {%0,%1,%2,%3};\n"
        : "+f"(c[0]), "+f"(c[1]), "+f"(c[2]), "+f"(c[3])
        : "r"(a0), "r"(a1), "r"(a2), "r"(a3), "r"(b0), "r"(b1));
}

__device__ __forceinline__ void cp16(void* smem, const void* g) {
    unsigned saddr = (unsigned)__cvta_generic_to_shared(smem);
    asm volatile("cp.async.cg.shared.global [%0], [%1], 16;\n" :: "r"(saddr), "l"(g));
}
#define CP_COMMIT() asm volatile("cp.async.commit_group;\n" ::: "memory")

__device__ __forceinline__ float frcp(float x) {
    float r;
    asm("rcp.approx.f32 %0, %1;" : "=f"(r) : "f"(x));
    return r;
}

__device__ __forceinline__ float fex2(float x) {
    float r;
    asm("ex2.approx.f32 %0, %1;" : "=f"(r) : "f"(x));
    return r;
}

__device__ __forceinline__ float tanh_ap(float x) {
    float r;
    asm("tanh.approx.f32 %0, %1;" : "=f"(r) : "f"(x));
    return r;
}

__device__ __forceinline__ float gelu_f(float x) {
    float x3 = x * x * x;
    float t = tanh_ap(0.7978845608028654f * (x + 0.044715f * x3));
    return 0.5f * x * (1.f + t);
}

// =================================================================================
// Kernel 0: weight conversion fp32 -> bf16 k-pair-interleaved (+ phi combine, bias24)
// =================================================================================
__global__ void convert_kernel(
    const float* __restrict__ Wq, const float* __restrict__ Wk,
    const float* __restrict__ Wv, const float* __restrict__ Wo,
    const float* __restrict__ W1, const float* __restrict__ W2,
    const float* __restrict__ phi_pre, const float* __restrict__ phi_post,
    const float* __restrict__ phi_res,
    const float* __restrict__ b_pre, const float* __restrict__ b_post,
    const float* __restrict__ b_res,
    const float* __restrict__ a_pre, const float* __restrict__ a_post,
    const float* __restrict__ a_res)
{
    int idx = blockIdx.x * blockDim.x + threadIdx.x;
    if (idx < (D / 2) * QKVN) {
        int kp = idx / QKVN, c = idx % QKVN;
        const float* W; int cc;
        if (c < D)          { W = Wq; cc = c; }
        else if (c < 2 * D) { W = Wk; cc = c - D; }
        else                { W = Wv; cc = c - 2 * D; }
        g_wqkv_p[idx] = pack_bf16(W[(2 * kp) * D + cc], W[(2 * kp + 1) * D + cc]);
    }
    if (idx < (D / 2) * D) {
        int kp = idx / D, c = idx % D;
        g_wo_p[idx] = pack_bf16(Wo[(2 * kp) * D + c], Wo[(2 * kp + 1) * D + c]);
    }
    if (idx < (D / 2) * MLP) {
        int kp = idx / MLP, c = idx % MLP;
        g_w1_p[idx] = pack_bf16(W1[(2 * kp) * MLP + c], W1[(2 * kp + 1) * MLP + c]);
    }
    if (idx < (MLP / 2) * D) {
        int kp = idx / D, c = idx % D;
        g_w2_p[idx] = pack_bf16(W2[(2 * kp) * D + c], W2[(2 * kp + 1) * D + c]);
    }
    if (idx < (ND / 2) * 64) {
        int kp = idx >> 6, c = idx & 63;
        float v[2];
        #pragma unroll
        for (int u = 0; u < 2; u++) {
            int d = 2 * kp + u;
            float t = 0.f;
            if (c < 4)       t = a_pre[0]  * phi_pre[d * 4 + c];
            else if (c < 8)  t = a_post[0] * phi_post[d * 4 + (c - 4)];
            else if (c < 24) t = a_res[0]  * phi_res[d * 16 + (c - 8)];
            v[u] = t;
        }
        g_phiC_p[idx] = pack_bf16(v[0], v[1]);
    }
    if (idx < 24) {
        float v;
        if (idx < 4)      v = b_pre[idx];
        else if (idx < 8) v = b_post[idx - 4];
        else              v = b_res[idx - 8];
        g_bias24[idx] = v;
    }
}

// =================================================================================
// Kernel 1: FUSED rmsnorm + tilde GEMM + sigmoid/sinkhorn gates.
// Single barrier per k-iter: fill for it+1 issued after iter-it barrier.
// =================================================================================
__global__ __launch_bounds__(256) void gemm_gates(
    const float* __restrict__ x, const unsigned* __restrict__ Bp,
    const float* __restrict__ norm_w, float* __restrict__ hpost)
{
    __shared__ __align__(16) unsigned Asp[2][128][20];
    __shared__ __align__(16) unsigned Bsp[2][16][72];
    __shared__ float tl[128][25];
    __shared__ float sinv_s[128];
    __shared__ __align__(16) float wnorm_s[ND];

    const int N = 64;
    int tid = threadIdx.x;
    int wid = tid >> 5, lane = tid & 31;
    int g = lane >> 2, tig = lane & 3;
    int wm = wid & 3, wn = wid >> 2;
    int bm = blockIdx.y;

    int bkp = tid >> 4, bc = (tid & 15) * 4;
    const unsigned* Bbase = Bp + (size_t)bkp * N + bc;

    cp16(&Bsp[0][bkp][bc], Bbase);
    CP_COMMIT();

    for (int i = tid; i < ND / 4; i += 256)
        *(float4*)&wnorm_s[i * 4] = *(const float4*)(norm_w + i * 4);

    // rms stats: 8 warps x 16 rows
    for (int r = 0; r < 16; r++) {
        int row = wid * 16 + r;
        const float* xr = x + ((size_t)bm * 128 + row) * ND;
        float sq = 0.f;
        #pragma unroll
        for (int i = 0; i < 6; i++) {
            float4 v = *(const float4*)(xr + (lane + i * 32) * 4);
            sq += v.x * v.x + v.y * v.y + v.z * v.z + v.w * v.w;
        }
        #pragma unroll
        for (int o = 16; o; o >>= 1) sq += __shfl_xor_sync(~0u, sq, o);
        if (lane == 0) sinv_s[row] = rsqrtf(sq / (float)ND + 1e-8f);
    }
    __syncthreads();

    int ar = tid >> 1, ac0 = (tid & 1) * 16, acp = (tid & 1) * 8;
    const float* Abase = x + ((size_t)bm * 128 + ar) * ND + ac0;

    float4 ax[4];
    #pragma unroll
    for (int j = 0; j < 4; j++) ax[j] = *(const float4*)(Abase + j * 4);

    auto convert_store = [&](int stage, int kb) {
        float s = sinv_s[ar];
        unsigned u[8];
        #pragma unroll
        for (int j = 0; j < 4; j++) {
            float4 wv = *(const float4*)(wnorm_s + kb + ac0 + j * 4);
            u[2 * j]     = pack_bf16(ax[j].x * s * wv.x, ax[j].y * s * wv.y);
            u[2 * j + 1] = pack_bf16(ax[j].z * s * wv.z, ax[j].w * s * wv.w);
        }
        *(uint4*)&Asp[stage][ar][acp]     = *(uint4*)&u[0];
        *(uint4*)&Asp[stage][ar][acp + 4] = *(uint4*)&u[4];
    };
    convert_store(0, 0);
    // preload ax for tile 1
    #pragma unroll
    for (int j = 0; j < 4; j++) ax[j] = *(const float4*)(Abase + 32 + j * 4);
    asm volatile("cp.async.wait_group 0;\n" ::: "memory");
    __syncthreads();   // A0 stores + B0 visible

    float acc[2][4][4] = {};
    const int nk = ND / 32;  // 24
    for (int it = 0; it < nk; it++) {
        int cur = it & 1;
        if (it + 1 < nk) {
            // fill stage cur^1 (its readers finished before the barrier that
            // opened this iteration)
            cp16(&Bsp[cur ^ 1][bkp][bc], Bbase + (size_t)16 * (it + 1) * N);
            CP_COMMIT();
            convert_store(cur ^ 1, (it + 1) * 32);
            if (it + 2 < nk) {
                #pragma unroll
                for (int j = 0; j < 4; j++)
                    ax[j] = *(const float4*)(Abase + (it + 2) * 32 + j * 4);
            }
        }

        const unsigned (*As)[20] = Asp[cur];
        const unsigned (*Bs)[72] = Bsp[cur];
        #pragma unroll
        for (int ks = 0; ks < 2; ks++) {
            int kp0 = ks * 8;
            unsigned a[2][4], b[4][2];
            #pragma unroll
            for (int mt = 0; mt < 2; mt++) {
                int m0 = wm * 32 + mt * 16;
                a[mt][0] = As[m0 + g][kp0 + tig];
                a[mt][1] = As[m0 + g + 8][kp0 + tig];
                a[mt][2] = As[m0 + g][kp0 + tig + 4];
                a[mt][3] = As[m0 + g + 8][kp0 + tig + 4];
            }
            #pragma unroll
            for (int nt = 0; nt < 4; nt++) {
                int n0 = wn * 32 + nt * 8;
                b[nt][0] = Bs[kp0 + tig][n0 + g];
                b[nt][1] = Bs[kp0 + tig + 4][n0 + g];
            }
            #pragma unroll
            for (int mt = 0; mt < 2; mt++)
                #pragma unroll
                for (int nt = 0; nt < 4; nt++)
                    mma_bf16(acc[mt][nt], a[mt][0], a[mt][1], a[mt][2], a[mt][3],
                             b[nt][0], b[nt][1]);
        }
        if (it + 1 < nk)
            asm volatile("cp.async.wait_group 0;\n" ::: "memory");
        __syncthreads();
    }

    // ---- fused gates epilogue ----
    #pragma unroll
    for (int mt = 0; mt < 2; mt++) {
        #pragma unroll
        for (int half = 0; half < 2; half++) {
            if (wn == 0) {
                int rl = wm * 32 + mt * 16 + half * 8 + g;
                #pragma unroll
                for (int nt = 0; nt < 3; nt++) {
                    int col = nt * 8 + tig * 2;
                    tl[rl][col]     = acc[mt][nt][half * 2 + 0] + g_bias24[col];
                    tl[rl][col + 1] = acc[mt][nt][half * 2 + 1] + g_bias24[col + 1];
                }
            }
        }
    }
    __syncthreads();
    if (tid < 128) {
        size_t tok = (size_t)bm * 128 + tid;
        const float* t = tl[tid];

        float hp[4];
        #pragma unroll
        for (int j = 0; j < 4; j++) hp[j] = frcp(1.f + fex2(-1.44269504f * t[j]));
        float4 h4;
        h4.x = 2.f * frcp(1.f + fex2(-1.44269504f * t[4]));
        h4.y = 2.f * frcp(1.f + fex2(-1.44269504f * t[5]));
        h4.z = 2.f * frcp(1.f + fex2(-1.44269504f * t[6]));
        h4.w = 2.f * frcp(1.f + fex2(-1.44269504f * t[7]));
        *(float4*)(hpost + tok * 4) = h4;

        float m[16];
        float mx = t[8];
        #pragma unroll
        for (int j = 1; j < 16; j++) mx = fmaxf(mx, t[8 + j]);
        #pragma unroll
        for (int j = 0; j < 16; j++) m[j] = fex2(1.44269504f * (t[8 + j] - mx));

        #pragma unroll 1
        for (int it2 = 0; it2 < 20; it2++) {
            #pragma unroll
            for (int i = 0; i < 4; i++) {
                float rs = m[4 * i] + m[4 * i + 1] + m[4 * i + 2] + m[4 * i + 3];
                float inv = frcp(rs + 1e-8f);
                m[4 * i] *= inv; m[4 * i + 1] *= inv; m[4 * i + 2] *= inv; m[4 * i + 3] *= inv;
            }
            #pragma unroll
            for (int j = 0; j < 4; j++) {
                float cs = m[j] + m[4 + j] + m[8 + j] + m[12 + j];
                float inv = frcp(cs + 1e-8f);
                m[j] *= inv; m[4 + j] *= inv; m[8 + j] *= inv; m[12 + j] *= inv;
            }
        }

        float* gp = g_gates + tok * 20;
        *(float4*)(gp + 0)  = make_float4(m[0], m[1], m[2], m[3]);
        *(float4*)(gp + 4)  = make_float4(m[4], m[5], m[6], m[7]);
        *(float4*)(gp + 8)  = make_float4(m[8], m[9], m[10], m[11]);
        *(float4*)(gp + 12) = make_float4(m[12], m[13], m[14], m[15]);
        *(float4*)(gp + 16) = make_float4(hp[0], hp[1], hp[2], hp[3]);
    }
}

// =================================================================================
// Kernel 2: bf16 tensor-core GEMM, 3-stage cp.async ring, ONE barrier per k-iter.
// EPI: 0 plain->bf16, 1 +Res->f32, 2 gelu->bf16,
//      3 final: out = x_res(from Xorig+gates) + (acc+Res)*hpost  [pure write]
// =================================================================================
template <int EPI>
__global__ __launch_bounds__(256) void gemm_bf(
    const bf16* __restrict__ A, const unsigned* __restrict__ Bp,
    const float* __restrict__ Res, const float* __restrict__ hpost,
    const float* __restrict__ Xorig,
    void* __restrict__ Cv, int N, int K)
{
    __shared__ __align__(16) unsigned Asp[3][128][20];
    __shared__ __align__(16) unsigned Bsp[3][16][72];

    int tid = threadIdx.x;
    int wid = tid >> 5, lane = tid & 31;
    int g = lane >> 2, tig = lane & 3;
    int wm = wid & 3, wn = wid >> 2;
    int bm = blockIdx.y, bn = blockIdx.x;

    float acc[2][4][4] = {};

    int ar = tid >> 1, acp = (tid & 1) * 8;
    int bkp = tid >> 4, bc = (tid & 15) * 4;

    const bf16* Abase = A + (size_t)(bm * 128 + ar) * K + acp * 2;
    const unsigned* Bbase = Bp + (size_t)bkp * N + bn * 64 + bc;

    // prologue: stages 0 and 1 (nk >= 6 for all uses)
    cp16(&Asp[0][ar][acp],     Abase);
    cp16(&Asp[0][ar][acp + 4], Abase + 8);
    cp16(&Bsp[0][bkp][bc],     Bbase);
    CP_COMMIT();
    cp16(&Asp[1][ar][acp],     Abase + 32);
    cp16(&Asp[1][ar][acp + 4], Abase + 40);
    cp16(&Bsp[1][bkp][bc],     Bbase + (size_t)16 * N);
    CP_COMMIT();

    int nk = K >> 5;
    int cur = 0, nxt = 2;
    for (int it = 0; it < nk; it++) {
        if (it + 1 < nk) {
            asm volatile("cp.async.wait_group 1;\n" ::: "memory");
        } else {
            asm volatile("cp.async.wait_group 0;\n" ::: "memory");
        }
        __syncthreads();
        // fill stage nxt = (it+2)%3 == (it-1)%3: its readers finished before the
        // barrier above, so no trailing barrier is needed.
        if (it + 2 < nk) {
            cp16(&Asp[nxt][ar][acp],     Abase + (it + 2) * 32);
            cp16(&Asp[nxt][ar][acp + 4], Abase + (it + 2) * 32 + 8);
            cp16(&Bsp[nxt][bkp][bc],     Bbase + (size_t)16 * (it + 2) * N);
            CP_COMMIT();
        }

        const unsigned (*As)[20] = Asp[cur];
        const unsigned (*Bs)[72] = Bsp[cur];
        #pragma unroll
        for (int ks = 0; ks < 2; ks++) {
            int kp0 = ks * 8;
            unsigned a[2][4], b[4][2];
            #pragma unroll
            for (int mt = 0; mt < 2; mt++) {
                int m0 = wm * 32 + mt * 16;
                a[mt][0] = As[m0 + g][kp0 + tig];
                a[mt][1] = As[m0 + g + 8][kp0 + tig];
                a[mt][2] = As[m0 + g][kp0 + tig + 4];
                a[mt][3] = As[m0 + g + 8][kp0 + tig + 4];
            }
            #pragma unroll
            for (int nt = 0; nt < 4; nt++) {
                int n0 = wn * 32 + nt * 8;
                b[nt][0] = Bs[kp0 + tig][n0 + g];
                b[nt][1] = Bs[kp0 + tig + 4][n0 + g];
            }
            #pragma unroll
            for (int mt = 0; mt < 2; mt++)
                #pragma unroll
                for (int nt = 0; nt < 4; nt++)
                    mma_bf16(acc[mt][nt], a[mt][0], a[mt][1], a[mt][2], a[mt][3],
                             b[nt][0], b[nt][1]);
        }
        cur = (cur == 2) ? 0 : cur + 1;
        nxt = (nxt == 2) ? 0 : nxt + 1;
    }

    #pragma unroll
    for (int mt = 0; mt < 2; mt++) {
        #pragma unroll
        for (int half = 0; half < 2; half++) {
            int row = bm * 128 + wm * 32 + mt * 16 + g + half * 8;

            float4 hr0, hr1, hr2, hr3, hps;
            if (EPI == 3) {
                const float4* gp4 = (const float4*)(g_gates + (size_t)row * 20);
                hr0 = gp4[0]; hr1 = gp4[1]; hr2 = gp4[2]; hr3 = gp4[3];
                hps = *(const float4*)(hpost + (size_t)row * 4);
            }

            #pragma unroll
            for (int nt = 0; nt < 4; nt++) {
                int col = bn * 64 + wn * 32 + nt * 8 + tig * 2;
                float v0 = acc[mt][nt][half * 2 + 0];
                float v1 = acc[mt][nt][half * 2 + 1];
                if (EPI == 0) {
                    bf16* C = (bf16*)Cv;
                    *(unsigned*)(C + (size_t)row * N + col) = pack_bf16(v0, v1);
                } else if (EPI == 1) {
                    float* C = (float*)Cv;
                    float2 r = *(const float2*)(Res + (size_t)row * N + col);
                    *(float2*)(C + (size_t)row * N + col) = make_float2(v0 + r.x, v1 + r.y);
                } else if (EPI == 2) {
                    bf16* C = (bf16*)Cv;
                    *(unsigned*)(C + (size_t)row * N + col) = pack_bf16(gelu_f(v0), gelu_f(v1));
                } else if (EPI == 3) {
                    float* C = (float*)Cv;
                    float2 r = *(const float2*)(Res + (size_t)row * N + col);
                    float vx = v0 + r.x, vy = v1 + r.y;
                    const float* xr = Xorig + (size_t)row * ND + col;
                    float2 xj0 = *(const float2*)(xr);
                    float2 xj1 = *(const float2*)(xr + D);
                    float2 xj2 = *(const float2*)(xr + 2 * D);
                    float2 xj3 = *(const float2*)(xr + 3 * D);
                    float* op = C + (size_t)row * ND + col;
                    float ox, oy;
                    ox = hr0.x * xj0.x + hr0.y * xj1.x + hr0.z * xj2.x + hr0.w * xj3.x + vx * hps.x;
                    oy = hr0.x * xj0.y + hr0.y * xj1.y + hr0.z * xj2.y + hr0.w * xj3.y + vy * hps.x;
                    *(float2*)(op) = make_float2(ox, oy);
                    ox = hr1.x * xj0.x + hr1.y * xj1.x + hr1.z * xj2.x + hr1.w * xj3.x + vx * hps.y;
                    oy = hr1.x * xj0.y + hr1.y * xj1.y + hr1.z * xj2.y + hr1.w * xj3.y + vy * hps.y;
                    *(float2*)(op + D) = make_float2(ox, oy);
                    ox = hr2.x * xj0.x + hr2.y * xj1.x + hr2.z * xj2.x + hr2.w * xj3.x + vx * hps.z;
                    oy = hr2.x * xj0.y + hr2.y * xj1.y + hr2.z * xj2.y + hr2.w * xj3.y + vy * hps.z;
                    *(float2*)(op + 2 * D) = make_float2(ox, oy);
                    ox = hr3.x * xj0.x + hr3.y * xj1.x + hr3.z * xj2.x + hr3.w * xj3.x + vx * hps.w;
                    oy = hr3.x * xj0.y + hr3.y * xj1.y + hr3.z * xj2.y + hr3.w * xj3.y + vy * hps.w;
                    *(float2*)(op + 3 * D) = make_float2(ox, oy);
                }
            }
        }
    }
}

// =================================================================================
// Kernel 3: stream mixing + fused LN1. 1 warp/token, 8 tok/block.
// =================================================================================
__global__ __launch_bounds__(256) void sinkmix_kernel(
    const float* __restrict__ x,
    const float* __restrict__ ln1_w, const float* __restrict__ ln1_b,
    float* __restrict__ xin)
{
    int wid = threadIdx.x >> 5, lane = threadIdx.x & 31;
    int tok = blockIdx.x * 8 + wid;

    float gv = (lane < 4) ? g_gates[(size_t)tok * 20 + 16 + lane] : 0.f;
    float hp[4];
    #pragma unroll
    for (int i = 0; i < 4; i++) hp[i] = __shfl_sync(~0u, gv, i);

    const float* xrow = x + (size_t)tok * ND;
    float xi_c[6];
    float sum = 0.f, sumsq = 0.f;
    #pragma unroll
    for (int c = 0; c < 6; c++) {
        int dd = c * 32 + lane;
        float x0 = xrow[dd], x1 = xrow[D + dd], x2v = xrow[2 * D + dd], x3 = xrow[3 * D + dd];
        float xi = hp[0] * x0 + hp[1] * x1 + hp[2] * x2v + hp[3] * x3;
        xin[(size_t)tok * D + dd] = xi;
        xi_c[c] = xi;
        sum += xi; sumsq += xi * xi;
    }
    #pragma unroll
    for (int o = 16; o; o >>= 1) {
        sum += __shfl_xor_sync(~0u, sum, o);
        sumsq += __shfl_xor_sync(~0u, sumsq, o);
    }
    float mean = sum / (float)D;
    float var = sumsq / (float)D - mean * mean;
    float invstd = rsqrtf(var + 1e-5f);
    #pragma unroll
    for (int c = 0; c < 6; c++) {
        int dd = c * 32 + lane;
        float hv = (xi_c[c] - mean) * invstd * ln1_w[dd] + ln1_b[dd];
        g_h[(size_t)tok * D + dd] = __float2bfloat16(hv);
    }
}

// =================================================================================
// Kernel 4: LayerNorm (x2 f32 -> h bf16). 1 warp/token, 8 tok/block, shuffle-only.
// =================================================================================
__global__ __launch_bounds__(256) void ln2_kernel(
    const float* __restrict__ in, const float* __restrict__ w,
    const float* __restrict__ b)
{
    int wid = threadIdx.x >> 5, lane = threadIdx.x & 31;
    int tok = blockIdx.x * 8 + wid;
    const float* row = in + (size_t)tok * D;

    float v[6];
    float sum = 0.f, sumsq = 0.f;
    #pragma unroll
    for (int c = 0; c < 6; c++) {
        v[c] = row[c * 32 + lane];
        sum += v[c]; sumsq += v[c] * v[c];
    }
    #pragma unroll
    for (int o = 16; o; o >>= 1) {
        sum += __shfl_xor_sync(~0u, sum, o);
        sumsq += __shfl_xor_sync(~0u, sumsq, o);
    }
    float mean = sum / (float)D;
    float var = sumsq / (float)D - mean * mean;
    float invstd = rsqrtf(var + 1e-5f);
    #pragma unroll
    for (int c = 0; c < 6; c++) {
        int dd = c * 32 + lane;
        g_h[(size_t)tok * D + dd] = __float2bfloat16((v[c] - mean) * invstd * w[dd] + b[dd]);
    }
}

// =================================================================================
// Kernel 5: bf16 flash attention. BQ=128, BKEY=64, HD=64, 128 threads (4 warps).
// Double-buffered K/V smem -> ONE barrier per key-tile. Q in registers. P in regs.
// =================================================================================
__global__ __launch_bounds__(128) void flash_bf(
    const bf16* __restrict__ QKV, bf16* __restrict__ O)
{
    __shared__ __align__(16) unsigned Ksp[2][64][36];   // [key][dpair] (4g+tig) CF
    __shared__ __align__(16) unsigned Vp[2][32][72];    // [keypair][d] (8tig+g) CF

    int tid = threadIdx.x, wid = tid >> 5, lane = tid & 31;
    int g = lane >> 2, tig = lane & 3;
    int qt = blockIdx.x, h = blockIdx.y, b = blockIdx.z;
    size_t tokbase = (size_t)b * T_SEQ;
    int qoff = h * HD, koff = D + h * HD, voff = 2 * D + h * HD;
    int m0 = wid * 32;

    // Q A-frags directly from gmem into registers
    unsigned aq[2][4][4];
    {
        const bf16* qb = QKV + (tokbase + qt * 128) * QKVN + qoff;
        #pragma unroll
        for (int mt = 0; mt < 2; mt++) {
            int r0 = m0 + mt * 16 + g;
            #pragma unroll
            for (int ks = 0; ks < 4; ks++) {
                aq[mt][ks][0] = *(const unsigned*)(qb + (size_t)r0 * QKVN + (ks * 8 + tig) * 2);
                aq[mt][ks][1] = *(const unsigned*)(qb + (size_t)(r0 + 8) * QKVN + (ks * 8 + tig) * 2);
                aq[mt][ks][2] = *(const unsigned*)(qb + (size_t)r0 * QKVN + (ks * 8 + tig + 4) * 2);
                aq[mt][ks][3] = *(const unsigned*)(qb + (size_t)(r0 + 8) * QKVN + (ks * 8 + tig + 4) * 2);
            }
        }
    }

    int kr = tid >> 1, kcp = (tid & 1) * 16;   // K: row (64), 16 pairs
    int vkp = tid >> 2, vc = (tid & 3) * 16;   // V: pair-row (32), 16 cols

    float m_prev[2][2] = {{-1e30f, -1e30f}, {-1e30f, -1e30f}};
    float l_run[2][2] = {};
    float o_acc[2][8][4] = {};

    uint4 kreg[4], vr0a, vr0b, vr1a, vr1b;
    // load tile 0 regs + commit to stage 0
    {
        const bf16* kb = QKV + (tokbase + kr) * QKVN + koff;
        #pragma unroll
        for (int u = 0; u < 4; u++) kreg[u] = *(const uint4*)(kb + (kcp + 4 * u) * 2);
        const bf16* vb = QKV + (tokbase + 2 * vkp) * QKVN + voff + vc;
        vr0a = *(const uint4*)vb;          vr0b = *(const uint4*)(vb + 8);
        vr1a = *(const uint4*)(vb + QKVN); vr1b = *(const uint4*)(vb + QKVN + 8);

        #pragma unroll
        for (int u = 0; u < 4; u++) *(uint4*)&Ksp[0][kr][kcp + 4 * u] = kreg[u];
        uint4 oA, oB;
        oA.x = __byte_perm(vr0a.x, vr1a.x, 0x5410); oA.y = __byte_perm(vr0a.x, vr1a.x, 0x7632);
        oA.z = __byte_perm(vr0a.y, vr1a.y, 0x5410); oA.w = __byte_perm(vr0a.y, vr1a.y, 0x7632);
        oB.x = __byte_perm(vr0a.z, vr1a.z, 0x5410); oB.y = __byte_perm(vr0a.z, vr1a.z, 0x7632);
        oB.z = __byte_perm(vr0a.w, vr1a.w, 0x5410); oB.w = __byte_perm(vr0a.w, vr1a.w, 0x7632);
        *(uint4*)&Vp[0][vkp][vc]     = oA;
        *(uint4*)&Vp[0][vkp][vc + 4] = oB;
        oA.x = __byte_perm(vr0b.x, vr1b.x, 0x5410); oA.y = __byte_perm(vr0b.x, vr1b.x, 0x7632);
        oA.z = __byte_perm(vr0b.y, vr1b.y, 0x5410); oA.w = __byte_perm(vr0b.y, vr1b.y, 0x7632);
        oB.x = __byte_perm(vr0b.z, vr1b.z, 0x5410); oB.y = __byte_perm(vr0b.z, vr1b.z, 0x7632);
        oB.z = __byte_perm(vr0b.w, vr1b.w, 0x5410); oB.w = __byte_perm(vr0b.w, vr1b.w, 0x7632);
        *(uint4*)&Vp[0][vkp][vc + 8]  = oA;
        *(uint4*)&Vp[0][vkp][vc + 12] = oB;
    }
    __syncthreads();

    const int NIT = T_SEQ / 64;
    #pragma unroll 1
    for (int it = 0; it < NIT; it++) {
        int cur = it & 1;

        // prefetch next tile into regs (consumed at commit below)
        if (it + 1 < NIT) {
            const bf16* kb = QKV + (tokbase + (it + 1) * 64 + kr) * QKVN + koff;
            #pragma unroll
            for (int u = 0; u < 4; u++) kreg[u] = *(const uint4*)(kb + (kcp + 4 * u) * 2);
            const bf16* vb = QKV + (tokbase + (it + 1) * 64 + 2 * vkp) * QKVN + voff + vc;
            vr0a = *(const uint4*)vb;          vr0b = *(const uint4*)(vb + 8);
            vr1a = *(const uint4*)(vb + QKVN); vr1b = *(const uint4*)(vb + QKVN + 8);
        }

        // S = Q K^T
        float s[2][8][4] = {};
        #pragma unroll
        for (int ks = 0; ks < 4; ks++) {
            int kp0 = ks * 8;
            #pragma unroll
            for (int nt = 0; nt < 8; nt++) {
                unsigned b0 = Ksp[cur][nt * 8 + g][kp0 + tig];
                unsigned b1 = Ksp[cur][nt * 8 + g][kp0 + tig + 4];
                mma_bf16(s[0][nt], aq[0][ks][0], aq[0][ks][1], aq[0][ks][2], aq[0][ks][3], b0, b1);
                mma_bf16(s[1][nt], aq[1][ks][0], aq[1][ks][1], aq[1][ks][2], aq[1][ks][3], b0, b1);
            }
        }

        // online softmax in exp2 domain
        const float sc2 = 0.125f * 1.44269504f;
        #pragma unroll
        for (int mt = 0; mt < 2; mt++) {
            float mx0 = -1e30f, mx1 = -1e30f;
            #pragma unroll
            for (int nt = 0; nt < 8; nt++) {
                s[mt][nt][0] *= sc2; s[mt][nt][1] *= sc2; s[mt][nt][2] *= sc2; s[mt][nt][3] *= sc2;
                mx0 = fmaxf(mx0, fmaxf(s[mt][nt][0], s[mt][nt][1]));
                mx1 = fmaxf(mx1, fmaxf(s[mt][nt][2], s[mt][nt][3]));
            }
            mx0 = fmaxf(mx0, __shfl_xor_sync(~0u, mx0, 1));
            mx0 = fmaxf(mx0, __shfl_xor_sync(~0u, mx0, 2));
            mx1 = fmaxf(mx1, __shfl_xor_sync(~0u, mx1, 1));
            mx1 = fmaxf(mx1, __shfl_xor_sync(~0u, mx1, 2));
            float mn0 = fmaxf(m_prev[mt][0], mx0);
            float mn1 = fmaxf(m_prev[mt][1], mx1);
            float rs0 = 0.f, rs1 = 0.f;
            #pragma unroll
            for (int nt = 0; nt < 8; nt++) {
                s[mt][nt][0] = fex2(s[mt][nt][0] - mn0);
                s[mt][nt][1] = fex2(s[mt][nt][1] - mn0);
                s[mt][nt][2] = fex2(s[mt][nt][2] - mn1);
                s[mt][nt][3] = fex2(s[mt][nt][3] - mn1);
                rs0 += s[mt][nt][0] + s[mt][nt][1];
                rs1 += s[mt][nt][2] + s[mt][nt][3];
            }
            rs0 += __shfl_xor_sync(~0u, rs0, 1);
            rs0 += __shfl_xor_sync(~0u, rs0, 2);
            rs1 += __shfl_xor_sync(~0u, rs1, 1);
            rs1 += __shfl_xor_sync(~0u, rs1, 2);
            float scl0 = fex2(m_prev[mt][0] - mn0);
            float scl1 = fex2(m_prev[mt][1] - mn1);
            l_run[mt][0] = l_run[mt][0] * scl0 + rs0;
            l_run[mt][1] = l_run[mt][1] * scl1 + rs1;
            m_prev[mt][0] = mn0; m_prev[mt][1] = mn1;
            #pragma unroll
            for (int nt = 0; nt < 8; nt++) {
                o_acc[mt][nt][0] *= scl0; o_acc[mt][nt][1] *= scl0;
                o_acc[mt][nt][2] *= scl1; o_acc[mt][nt][3] *= scl1;
            }
        }

        // O += P V (P in regs)
        #pragma unroll
        for (int ks = 0; ks < 4; ks++) {
            int kp0 = ks * 8;
            unsigned pa[2][4];
            #pragma unroll
            for (int mt = 0; mt < 2; mt++) {
                pa[mt][0] = pack_bf16(s[mt][2 * ks][0],     s[mt][2 * ks][1]);
                pa[mt][1] = pack_bf16(s[mt][2 * ks][2],     s[mt][2 * ks][3]);
                pa[mt][2] = pack_bf16(s[mt][2 * ks + 1][0], s[mt][2 * ks + 1][1]);
                pa[mt][3] = pack_bf16(s[mt][2 * ks + 1][2], s[mt][2 * ks + 1][3]);
            }
            #pragma unroll
            for (int nt = 0; nt < 8; nt++) {
                unsigned b0 = Vp[cur][kp0 + tig][nt * 8 + g];
                unsigned b1 = Vp[cur][kp0 + tig + 4][nt * 8 + g];
                mma_bf16(o_acc[0][nt], pa[0][0], pa[0][1], pa[0][2], pa[0][3], b0, b1);
                mma_bf16(o_acc[1][nt], pa[1][0], pa[1][1], pa[1][2], pa[1][3], b0, b1);
            }
        }

        // commit prefetched tile into OTHER stage, then single barrier.
        if (it + 1 < NIT) {
            int nx = cur ^ 1;
            #pragma unroll
            for (int u = 0; u < 4; u++) *(uint4*)&Ksp[nx][kr][kcp + 4 * u] = kreg[u];
            uint4 oA, oB;
            oA.x = __byte_perm(vr0a.x, vr1a.x, 0x5410); oA.y = __byte_perm(vr0a.x, vr1a.x, 0x7632);
            oA.z = __byte_perm(vr0a.y, vr1a.y, 0x5410); oA.w = __byte_perm(vr0a.y, vr1a.y, 0x7632);
            oB.x = __byte_perm(vr0a.z, vr1a.z, 0x5410); oB.y = __byte_perm(vr0a.z, vr1a.z, 0x7632);
            oB.z = __byte_perm(vr0a.w, vr1a.w, 0x5410); oB.w = __byte_perm(vr0a.w, vr1a.w, 0x7632);
            *(uint4*)&Vp[nx][vkp][vc]     = oA;
            *(uint4*)&Vp[nx][vkp][vc + 4] = oB;
            oA.x = __byte_perm(vr0b.x, vr1b.x, 0x5410); oA.y = __byte_perm(vr0b.x, vr1b.x, 0x7632);
            oA.z = __byte_perm(vr0b.y, vr1b.y, 0x5410); oA.w = __byte_perm(vr0b.y, vr1b.y, 0x7632);
            oB.x = __byte_perm(vr0b.z, vr1b.z, 0x5410); oB.y = __byte_perm(vr0b.z, vr1b.z, 0x7632);
            oB.z = __byte_perm(vr0b.w, vr1b.w, 0x5410); oB.w = __byte_perm(vr0b.w, vr1b.w, 0x7632);
            *(uint4*)&Vp[nx][vkp][vc + 8]  = oA;
            *(uint4*)&Vp[nx][vkp][vc + 12] = oB;
        }
        __syncthreads();
    }

    size_t obase = tokbase * D + h * HD;
    #pragma unroll
    for (int mt = 0; mt < 2; mt++) {
        float inv0 = 1.f / l_run[mt][0];
        float inv1 = 1.f / l_run[mt][1];
        int q0 = qt * 128 + m0 + mt * 16 + g;
        #pragma unroll
        for (int nt = 0; nt < 8; nt++) {
            int col = nt * 8 + tig * 2;
            *(unsigned*)(O + obase + (size_t)q0 * D + col) =
                pack_bf16(o_acc[mt][nt][0] * inv0, o_acc[mt][nt][1] * inv0);
            *(unsigned*)(O + obase + (size_t)(q0 + 8) * D + col) =
                pack_bf16(o_acc[mt][nt][2] * inv1, o_acc[mt][nt][3] * inv1);
        }
    }
}

// =================================================================================
extern "C" void kernel_launch(void* const* d_in, const int* in_sizes, int n_in,
                              void* d_out, int out_size)
{
    const float* x        = (const float*)d_in[0];
    const float* norm_w   = (const float*)d_in[1];
    const float* phi_pre  = (const float*)d_in[2];
    const float* phi_post = (const float*)d_in[3];
    const float* phi_res  = (const float*)d_in[4];
    const float* b_pre    = (const float*)d_in[5];
    const float* b_post   = (const float*)d_in[6];
    const float* b_res    = (const float*)d_in[7];
    const float* a_pre    = (const float*)d_in[8];
    const float* a_post   = (const float*)d_in[9];
    const float* a_res    = (const float*)d_in[10];
    const float* ln1_w    = (const float*)d_in[11];
    const float* ln1_b    = (const float*)d_in[12];
    const float* Wq       = (const float*)d_in[13];
    const float* Wk       = (const float*)d_in[14];
    const float* Wv       = (const float*)d_in[15];
    const float* Wo       = (const float*)d_in[16];
    const float* ln2_w    = (const float*)d_in[17];
    const float* ln2_b    = (const float*)d_in[18];
    const float* W1       = (const float*)d_in[19];
    const float* W2       = (const float*)d_in[20];
    float* out = (float*)d_out;

    void *p;
    cudaGetSymbolAddress(&p, g_xin);     float* xin       = (float*)p;
    cudaGetSymbolAddress(&p, g_x2);      float* x2        = (float*)p;
    cudaGetSymbolAddress(&p, g_hpost);   float* hpost     = (float*)p;
    cudaGetSymbolAddress(&p, g_h);       bf16* h          = (bf16*)p;
    cudaGetSymbolAddress(&p, g_qkv);     bf16* qkv        = (bf16*)p;
    cudaGetSymbolAddress(&p, g_o);       bf16* o          = (bf16*)p;
    cudaGetSymbolAddress(&p, g_g);       bf16* gbuf       = (bf16*)p;
    cudaGetSymbolAddress(&p, g_wqkv_p);  unsigned* wqkv   = (unsigned*)p;
    cudaGetSymbolAddress(&p, g_wo_p);    unsigned* wo     = (unsigned*)p;
    cudaGetSymbolAddress(&p, g_w1_p);    unsigned* w1     = (unsigned*)p;
    cudaGetSymbolAddress(&p, g_w2_p);    unsigned* w2     = (unsigned*)p;
    cudaGetSymbolAddress(&p, g_phiC_p);  unsigned* phiC   = (unsigned*)p;

    // 0) weight conversion (k-pair interleaved)
    convert_kernel<<<288, 256>>>(Wq, Wk, Wv, Wo, W1, W2, phi_pre, phi_post, phi_res,
                                 b_pre, b_post, b_res, a_pre, a_post, a_res);
    // 1) FUSED rmsnorm + projections + sigmoid/sinkhorn -> g_gates, hpost
    gemm_gates<<<dim3(1, BT / 128), 256>>>(x, phiC, norm_w, hpost);
    // 2) mix + LN1 -> xin, h
    sinkmix_kernel<<<BT / 8, 256>>>(x, ln1_w, ln1_b, xin);
    // 3) fused QKV
    dim3 g192(D / 64, BT / 128), g576(QKVN / 64, BT / 128), g768(MLP / 64, BT / 128);
    gemm_bf<0><<<g576, 256>>>(h, wqkv, nullptr, nullptr, nullptr, qkv, QKVN, D);
    // 4) attention (double-buffered smem, 1 barrier/tile)
    flash_bf<<<dim3(T_SEQ / 128, NH, NB), 128>>>(qkv, o);
    // 5) Wo + residual -> x2 (f32)
    gemm_bf<1><<<g192, 256>>>(o, wo, xin, nullptr, nullptr, x2, D, D);
    // 6) LN2 -> h bf16 (warp-per-token)
    ln2_kernel<<<BT / 8, 256>>>(x2, ln2_w, ln2_b);
    // 7) MLP up + GELU -> g bf16
    gemm_bf<2><<<g768, 256>>>(h, w1, nullptr, nullptr, nullptr, gbuf, MLP, D);
    // 8) MLP down + x2 residual + x_res (from x,gates) + gated scatter -> out (pure write)
    gemm_bf<3><<<g192, 256>>>(gbuf, w2, x2, hpost, x, out, D, MLP);
}